// round 1
// baseline (speedup 1.0000x reference)
#include <cuda_runtime.h>
#include <math.h>

// ---- problem constants ----
#define Bb   2
#define Ll   512
#define Qq   512
#define Ee   1024
#define Ww   1024
#define Dd   8
#define Hn   32      // H_NLM
#define NHh  16
#define HDd  64
#define SAa  512
#define SOo  1024
#define Vv   8192
#define Tt   6
#define SHh  2048    // SYN_H
#define BQ   (Bb*Qq)   // 1024
#define BL   (Bb*Ll)   // 1024

// ---- scratch (device globals; no allocation allowed) ----
__device__ float g_embx[BL*Ee];
__device__ float g_kv  [BL*Ee];
__device__ float g_tmp [BQ*Ee];               // q/k/v projection staging (BL==BQ)
__device__ float g_qh  [Bb*NHh*Qq*HDd];
__device__ float g_kh  [Bb*NHh*Ll*HDd];
__device__ float g_vh  [Bb*NHh*Ll*HDd];
__device__ float g_ctx [BQ*Ee];
__device__ float g_attn[BQ*Ee];
__device__ float g_cat [BQ*(Ee+Ww)];
__device__ float g_h1  [BQ*SHh];
__device__ float g_z   [BQ*Ww];
__device__ float g_pah [BQ*Ww*Dd];            // ring buffer over last dim
__device__ float g_Na  [BQ*SAa];
__device__ float g_No  [BQ*SOo];
__device__ float g_sa  [BQ*SAa];
__device__ float g_so  [BQ*SOo];
__device__ float g_q   [BQ*Ee];

__device__ __forceinline__ float gelu_f(float x) {
    float x3 = x*x*x;
    return 0.5f*x*(1.0f + tanhf(0.7978845608028654f*(x + 0.044715f*x3)));
}

// ---- embedding gather: emb_input[bl, e] = emb[x[bl], e] ----
__global__ void k_gather(const int* __restrict__ x, const float* __restrict__ emb,
                         float* __restrict__ out) {
    int i = blockIdx.x*blockDim.x + threadIdx.x;
    if (i >= BL*Ee) return;
    int e = i % Ee, bl = i / Ee;
    out[i] = emb[(long)x[bl]*Ee + e];
}

// ---- state init: broadcast z_init/pah_init, zero sync numerators ----
__global__ void k_init(const float* __restrict__ z0, const float* __restrict__ p0,
                       float* __restrict__ z, float* __restrict__ pah,
                       float* __restrict__ Na, float* __restrict__ No) {
    int i = blockIdx.x*blockDim.x + threadIdx.x;
    if (i < BQ*Ww*Dd) pah[i] = p0[i % (Ww*Dd)];
    if (i < BQ*Ww)    z[i]   = z0[i % Ww];
    if (i < BQ*SAa)   Na[i]  = 0.f;
    if (i < BQ*SOo)   No[i]  = 0.f;
}

// ---- register-tiled SGEMM: C[m*ldcm + n*ldcn] = epi(A(MxK) @ B(KxN) [+bias]) ----
// BM=BN=128, BK=8, 256 threads, 8x8 per thread. All dims divisible (M%128==0 etc).
template<int EPI>  // 0=none, 1=+bias, 2=gelu(+bias)
__global__ void sgemm128(const float* __restrict__ A, const float* __restrict__ Bm,
                         const float* __restrict__ bias, float* __restrict__ C,
                         int M, int N, int K, long ldcm, long ldcn) {
    __shared__ float As[8][128];
    __shared__ float Bs[8][128];
    const int tid = threadIdx.x;
    const int bm = blockIdx.y*128, bn = blockIdx.x*128;
    const int arow = tid >> 1, acol = (tid & 1)*4;
    const int brow = tid >> 5, bcol = (tid & 31)*4;
    const int tm = (tid >> 4)*8, tn = (tid & 15)*8;

    const float* Ag = A + (long)(bm + arow)*K + acol;
    const float* Bg = Bm + (long)brow*N + bn + bcol;

    float acc[8][8];
    #pragma unroll
    for (int i = 0; i < 8; i++)
        #pragma unroll
        for (int j = 0; j < 8; j++) acc[i][j] = 0.f;

    for (int k0 = 0; k0 < K; k0 += 8) {
        float4 av = *(const float4*)Ag;  Ag += 8;
        float4 bv = *(const float4*)Bg;  Bg += (long)8*N;
        As[acol+0][arow] = av.x; As[acol+1][arow] = av.y;
        As[acol+2][arow] = av.z; As[acol+3][arow] = av.w;
        *(float4*)&Bs[brow][bcol] = bv;
        __syncthreads();
        #pragma unroll
        for (int kk = 0; kk < 8; kk++) {
            float ar[8], br[8];
            #pragma unroll
            for (int i = 0; i < 8; i++) ar[i] = As[kk][tm+i];
            #pragma unroll
            for (int j = 0; j < 8; j++) br[j] = Bs[kk][tn+j];
            #pragma unroll
            for (int i = 0; i < 8; i++)
                #pragma unroll
                for (int j = 0; j < 8; j++) acc[i][j] += ar[i]*br[j];
        }
        __syncthreads();
    }
    #pragma unroll
    for (int i = 0; i < 8; i++) {
        long m = bm + tm + i;
        #pragma unroll
        for (int j = 0; j < 8; j++) {
            long n = bn + tn + j;
            float v = acc[i][j];
            if (EPI >= 1) v += bias[n];
            if (EPI == 2) v = gelu_f(v);
            C[m*ldcm + n*ldcn] = v;
        }
    }
}

// ---- split heads (+optional RoPE): in (B,S,E) -> out (B,NH,S,HD) ----
__global__ void k_rope_split(const float* __restrict__ in, float* __restrict__ out,
                             int S, int do_rope) {
    int i = blockIdx.x*blockDim.x + threadIdx.x;
    if (i >= Bb*S*Ee) return;
    int d = i % HDd;
    int h = (i / HDd) % NHh;
    int s = (i / Ee) % S;
    int b = i / (Ee*S);
    const float* row = in + ((long)(b*S + s))*Ee + h*HDd;
    float v;
    if (do_rope) {
        const int half = HDd/2;
        int j = d % half;
        float inv = expf(-(float)j * (9.210340371976184f / (float)half)); // 10000^{-j/half}
        float ang = (float)s * inv;
        float c = cosf(ang), sn = sinf(ang);
        float x1 = row[j], x2 = row[j + half];
        v = (d < half) ? (x1*c - x2*sn) : (x2*c + x1*sn);
    } else {
        v = row[d];
    }
    out[(((long)(b*NHh + h))*S + s)*HDd + d] = v;
}

// ---- causal attention, one block per (q,h,b), 64 threads ----
__global__ void k_attn(const float* __restrict__ qh, const float* __restrict__ kh,
                       const float* __restrict__ vh, float* __restrict__ ctx) {
    int qi = blockIdx.x, h = blockIdx.y, b = blockIdx.z;
    int tid = threadIdx.x;                       // 64
    __shared__ float qs[HDd];
    __shared__ float sc[Ll];
    __shared__ float red[64];

    qs[tid] = qh[(((long)(b*NHh + h))*Qq + qi)*HDd + tid];
    __syncthreads();

    const float* kb = kh + ((long)(b*NHh + h))*Ll*HDd;
    const float scale = 0.125f;                  // 1/sqrt(64)
    for (int k = tid; k < Ll; k += 64) {
        float s = -1e30f;
        if (k <= qi) {
            const float* kr = kb + (long)k*HDd;
            s = 0.f;
            #pragma unroll
            for (int d = 0; d < HDd; d += 4) {
                float4 kq = *(const float4*)(kr + d);
                float4 qv = *(const float4*)(qs + d);
                s += kq.x*qv.x + kq.y*qv.y + kq.z*qv.z + kq.w*qv.w;
            }
            s *= scale;
        }
        sc[k] = s;
    }
    __syncthreads();

    float m = -1e30f;
    for (int k = tid; k <= qi; k += 64) m = fmaxf(m, sc[k]);
    red[tid] = m; __syncthreads();
    for (int o = 32; o > 0; o >>= 1) { if (tid < o) red[tid] = fmaxf(red[tid], red[tid+o]); __syncthreads(); }
    m = red[0];
    __syncthreads();

    float ssum = 0.f;
    for (int k = tid; k <= qi; k += 64) { float e = expf(sc[k] - m); sc[k] = e; ssum += e; }
    red[tid] = ssum; __syncthreads();
    for (int o = 32; o > 0; o >>= 1) { if (tid < o) red[tid] += red[tid+o]; __syncthreads(); }
    float inv = 1.f / red[0];
    __syncthreads();

    const float* vb = vh + ((long)(b*NHh + h))*Ll*HDd;
    float acc = 0.f;
    for (int k = 0; k <= qi; k++) acc += sc[k]*vb[(long)k*HDd + tid];
    ctx[((long)(b*Qq + qi))*Ee + h*HDd + tid] = acc*inv;
}

// ---- concat [attn_out, z] -> (BQ, E+W) ----
__global__ void k_concat(const float* __restrict__ a, const float* __restrict__ z,
                         float* __restrict__ out) {
    int i = blockIdx.x*blockDim.x + threadIdx.x;
    if (i >= BQ*(Ee+Ww)) return;
    int c = i % (Ee+Ww), r = i / (Ee+Ww);
    out[i] = (c < Ee) ? a[(long)r*Ee + c] : z[(long)r*Ww + (c - Ee)];
}

// ---- per-neuron MLP: pah(ring) -> gelu(8->32) -> 32->1 -> z ----
__global__ void k_nlm(const float* __restrict__ pah, const float* __restrict__ w1,
                      const float* __restrict__ b1, const float* __restrict__ w2,
                      const float* __restrict__ b2, float* __restrict__ z, int start) {
    int w  = blockIdx.x;
    int bq = blockIdx.y*blockDim.x + threadIdx.x;
    __shared__ float w1s[Dd*Hn];
    __shared__ float b1s[Hn];
    __shared__ float w2s[Hn];
    if (threadIdx.x < Dd*Hn) w1s[threadIdx.x] = w1[(long)w*Dd*Hn + threadIdx.x];
    if (threadIdx.x < Hn) {
        b1s[threadIdx.x] = b1[(long)w*Hn + threadIdx.x];
        w2s[threadIdx.x] = w2[(long)w*Hn + threadIdx.x];
    }
    __syncthreads();
    float pv[Dd];
    const float* pr = pah + ((long)bq*Ww + w)*Dd;
    #pragma unroll
    for (int d = 0; d < Dd; d++) pv[d] = pr[(start + d) & 7];
    float zacc = b2[w];
    #pragma unroll
    for (int hh = 0; hh < Hn; hh++) {
        float a = b1s[hh];
        #pragma unroll
        for (int d = 0; d < Dd; d++) a += pv[d]*w1s[d*Hn + hh];
        zacc += gelu_f(a)*w2s[hh];
    }
    z[(long)bq*Ww + w] = zacc;
}

// ---- incremental sync: N <- N*e^{-d} + z[l]*z[r]; sync = N / sqrt(sum_k e^{-kd}) ----
__global__ void k_sync(const float* __restrict__ z, float* __restrict__ Nbuf,
                       float* __restrict__ syn, const int* __restrict__ il,
                       const int* __restrict__ ir, const float* __restrict__ dec,
                       int S, int Tn) {
    int i = blockIdx.x*blockDim.x + threadIdx.x;
    if (i >= BQ*S) return;
    int s = i % S, bq = i / S;
    float d  = dec[s];
    float ed = expf(-d);
    const float* zr = z + (long)bq*Ww;
    float p  = zr[il[s]]*zr[ir[s]];
    float Nn = Nbuf[i]*ed + p;
    Nbuf[i] = Nn;
    float den = 0.f, wgt = 1.f;
    for (int k = 0; k < Tn; k++) { den += wgt; wgt *= ed; }
    syn[i] = Nn / sqrtf(den);
}

// ---- host side ----
static float* sym(const void* s) {
    void* p = nullptr;
    cudaGetSymbolAddress(&p, s);
    return (float*)p;
}

static void gemm(int epi, const float* A, const float* B, const float* bias, float* C,
                 int M, int N, int K, long ldcm, long ldcn) {
    dim3 grid(N/128, M/128), block(256);
    if (epi == 0)      sgemm128<0><<<grid, block>>>(A, B, bias, C, M, N, K, ldcm, ldcn);
    else if (epi == 1) sgemm128<1><<<grid, block>>>(A, B, bias, C, M, N, K, ldcm, ldcn);
    else               sgemm128<2><<<grid, block>>>(A, B, bias, C, M, N, K, ldcm, ldcn);
}

extern "C" void kernel_launch(void* const* d_in, const int* in_sizes, int n_in,
                              void* d_out, int out_size) {
    (void)in_sizes; (void)n_in; (void)out_size;
    const int*   x       = (const int*)  d_in[0];
    // d_in[1] = num_output_q (unused; Q fixed)
    const float* emb     = (const float*)d_in[2];
    const float* w_kv    = (const float*)d_in[3];
    const float* w_qs    = (const float*)d_in[4];
    const float* wq      = (const float*)d_in[5];
    const float* wk      = (const float*)d_in[6];
    const float* wv      = (const float*)d_in[7];
    const float* wo      = (const float*)d_in[8];
    const float* ws1     = (const float*)d_in[9];
    const float* bs1     = (const float*)d_in[10];
    const float* ws2     = (const float*)d_in[11];
    const float* bs2     = (const float*)d_in[12];
    const float* nw1     = (const float*)d_in[13];
    const float* nb1     = (const float*)d_in[14];
    const float* nw2     = (const float*)d_in[15];
    const float* nb2     = (const float*)d_in[16];
    const float* out_w   = (const float*)d_in[17];
    const float* out_b   = (const float*)d_in[18];
    const float* z_init  = (const float*)d_in[19];
    const float* p_init  = (const float*)d_in[20];
    const float* dec_a   = (const float*)d_in[21];
    const float* dec_o   = (const float*)d_in[22];
    const int*   idx_la  = (const int*)  d_in[23];
    const int*   idx_ra  = (const int*)  d_in[24];
    const int*   idx_lo  = (const int*)  d_in[25];
    const int*   idx_ro  = (const int*)  d_in[26];
    float* out = (float*)d_out;

    float *embx = sym(g_embx), *kv = sym(g_kv), *tmp = sym(g_tmp);
    float *qh = sym(g_qh), *kh = sym(g_kh), *vh = sym(g_vh);
    float *ctx = sym(g_ctx), *attn = sym(g_attn), *cat = sym(g_cat);
    float *h1 = sym(g_h1), *z = sym(g_z), *pah = sym(g_pah);
    float *Na = sym(g_Na), *No = sym(g_No), *sa = sym(g_sa), *so = sym(g_so);
    float *qbuf = sym(g_q);

    const int TPB = 256;

    // ---- loop-invariant prologue ----
    k_gather<<<(BL*Ee + TPB-1)/TPB, TPB>>>(x, emb, embx);
    gemm(0, embx, w_kv, nullptr, kv, BL, Ee, Ee, Ee, 1);
    gemm(0, kv, wk, nullptr, tmp, BL, Ee, Ee, Ee, 1);
    k_rope_split<<<(Bb*Ll*Ee + TPB-1)/TPB, TPB>>>(tmp, kh, Ll, 1);
    gemm(0, kv, wv, nullptr, tmp, BL, Ee, Ee, Ee, 1);
    k_rope_split<<<(Bb*Ll*Ee + TPB-1)/TPB, TPB>>>(tmp, vh, Ll, 0);

    k_init<<<(BQ*Ww*Dd + TPB-1)/TPB, TPB>>>(z_init, p_init, z, pah, Na, No);
    // seed sync numerators with hist=[z_init], Tn=1
    k_sync<<<(BQ*SAa + TPB-1)/TPB, TPB>>>(z, Na, sa, idx_la, idx_ra, dec_a, SAa, 1);
    k_sync<<<(BQ*SOo + TPB-1)/TPB, TPB>>>(z, No, so, idx_lo, idx_ro, dec_o, SOo, 1);

    // ---- T iterations ----
    for (int t = 0; t < Tt; t++) {
        gemm(0, sa, w_qs, nullptr, qbuf, BQ, Ee, SAa, Ee, 1);          // q = sync_a @ w_q_sync
        gemm(0, qbuf, wq, nullptr, tmp, BQ, Ee, Ee, Ee, 1);            // q proj
        k_rope_split<<<(Bb*Qq*Ee + TPB-1)/TPB, TPB>>>(tmp, qh, Qq, 1);
        k_attn<<<dim3(Qq, NHh, Bb), 64>>>(qh, kh, vh, ctx);
        gemm(0, ctx, wo, nullptr, attn, BQ, Ee, Ee, Ee, 1);            // out proj
        k_concat<<<(BQ*(Ee+Ww) + TPB-1)/TPB, TPB>>>(attn, z, cat);
        gemm(2, cat, ws1, bs1, h1, BQ, SHh, Ee+Ww, SHh, 1);            // gelu(cat@ws1+bs1)
        gemm(1, h1, ws2, bs2, pah + t, BQ, Ww, SHh, (long)Ww*Dd, Dd);  // pre -> pah ring slot t
        k_nlm<<<dim3(Ww, BQ/TPB), TPB>>>(pah, nw1, nb1, nw2, nb2, z, t + 1);
        k_sync<<<(BQ*SAa + TPB-1)/TPB, TPB>>>(z, Na, sa, idx_la, idx_ra, dec_a, SAa, t + 2);
        k_sync<<<(BQ*SOo + TPB-1)/TPB, TPB>>>(z, No, so, idx_lo, idx_ro, dec_o, SOo, t + 2);
        gemm(1, so, out_w, out_b, out + (long)t*BQ*Vv, BQ, Vv, SOo, Vv, 1); // logits
    }
}

// round 5
// speedup vs baseline: 2.2802x; 2.2802x over previous
#include <cuda_runtime.h>
#include <cuda_bf16.h>
#include <math.h>
#include <stdint.h>

// ---- problem constants ----
#define Bb   2
#define Ll   512
#define Qq   512
#define Ee   1024
#define Ww   1024
#define Dd   8
#define Hn   32
#define NHh  16
#define HDd  64
#define SAa  512
#define SOo  1024
#define Vv   8192
#define Tt   6
#define SHh  2048
#define BQ   (Bb*Qq)
#define BL   (Bb*Ll)

typedef __nv_bfloat16 bf;

// ---- fp32 scratch ----
__device__ float g_kv  [BL*Ee];
__device__ float g_tmp [BQ*Ee];
__device__ float g_qh  [Bb*NHh*Qq*HDd];
__device__ float g_kh  [Bb*NHh*Ll*HDd];
__device__ float g_vh  [Bb*NHh*Ll*HDd];
__device__ float g_ctx [BQ*Ee];
__device__ float g_attn[BQ*Ee];
__device__ float g_cat [BQ*(Ee+Ww)];
__device__ float g_h1  [BQ*SHh];
__device__ float g_z   [BQ*Ww];
__device__ float g_pah [BQ*Ww*Dd];
__device__ float g_Na  [BQ*SAa];
__device__ float g_No  [BQ*SOo];
__device__ float g_sa  [BQ*SAa];
__device__ float g_so  [BQ*SOo];
__device__ float g_q   [BQ*Ee];

// ---- bf16 hi/lo: transposed weights [N,K] + activations [M,K] ----
__device__ bf g_wkvT_h[Ee*Ee],       g_wkvT_l[Ee*Ee];
__device__ bf g_wqsT_h[Ee*SAa],      g_wqsT_l[Ee*SAa];
__device__ bf g_wqT_h [Ee*Ee],       g_wqT_l [Ee*Ee];
__device__ bf g_wkT_h [Ee*Ee],       g_wkT_l [Ee*Ee];
__device__ bf g_wvT_h [Ee*Ee],       g_wvT_l [Ee*Ee];
__device__ bf g_woT_h [Ee*Ee],       g_woT_l [Ee*Ee];
__device__ bf g_ws1T_h[SHh*(Ee+Ww)], g_ws1T_l[SHh*(Ee+Ww)];
__device__ bf g_ws2T_h[Ww*SHh],      g_ws2T_l[Ww*SHh];
__device__ bf g_owT_h [Vv*SOo],      g_owT_l [Vv*SOo];
__device__ bf g_act_h [BQ*(Ee+Ww)],  g_act_l [BQ*(Ee+Ww)];

__device__ __forceinline__ float gelu_f(float x) {
    float x3 = x*x*x;
    return 0.5f*x*(1.0f + tanhf(0.7978845608028654f*(x + 0.044715f*x3)));
}

// ====================== mma.sync GEMM primitives ======================
__device__ __forceinline__ void cpa16(uint32_t s, const void* g){
    asm volatile("cp.async.cg.shared.global [%0], [%1], 16;" :: "r"(s), "l"(g));
}
__device__ __forceinline__ void cpcommit(){ asm volatile("cp.async.commit_group;" ::: "memory"); }
template<int N> __device__ __forceinline__ void cpwait(){ asm volatile("cp.async.wait_group %0;" :: "n"(N) : "memory"); }

__device__ __forceinline__ void ldmx4(uint32_t* r, uint32_t a){
    asm volatile("ldmatrix.sync.aligned.m8n8.x4.shared.b16 {%0,%1,%2,%3}, [%4];"
        : "=r"(r[0]),"=r"(r[1]),"=r"(r[2]),"=r"(r[3]) : "r"(a));
}
__device__ __forceinline__ void mma16816(float* c, const uint32_t* a, uint32_t b0, uint32_t b1){
    asm volatile("mma.sync.aligned.m16n8k16.row.col.f32.bf16.bf16.f32 "
        "{%0,%1,%2,%3}, {%4,%5,%6,%7}, {%8,%9}, {%0,%1,%2,%3};"
        : "+f"(c[0]),"+f"(c[1]),"+f"(c[2]),"+f"(c[3])
        : "r"(a[0]),"r"(a[1]),"r"(a[2]),"r"(a[3]), "r"(b0),"r"(b1));
}

// C(M,N) = epi(A @ B^T [+bias]) with A,B as bf16 hi/lo, B stored [N,K].
// Tile 128x128x32, 256 thr, 8 warps (4x2), warp tile 32x64, cp.async 2-stage.
#define TILE_B  10240            // 128 rows * 40 elems * 2B
#define STAGE_B (4*TILE_B)       // Ah,Al,Bh,Bl
#define HG_SMEM (2*STAGE_B)      // 81920

template<int EPI>   // 0=none 1=+bias 2=gelu(+bias)
__global__ void __launch_bounds__(256, 1) hgemm(
    const bf* __restrict__ Ah, const bf* __restrict__ Al,
    const bf* __restrict__ Bh, const bf* __restrict__ Bl,
    const float* __restrict__ bias, float* __restrict__ C,
    int M, int N, int K, long ldcm, long ldcn)
{
    extern __shared__ __align__(16) char dyn[];
    const int tid  = threadIdx.x;
    const int wid  = tid >> 5, lane = tid & 31;
    const int bm = blockIdx.y*128, bn = blockIdx.x*128;
    const int wm = wid & 3, wn = wid >> 2;      // 4 x 2 warp grid

    uint32_t sbase = (uint32_t)__cvta_generic_to_shared(dyn);

    const bf* gAh = Ah + (long)bm*K;
    const bf* gAl = Al + (long)bm*K;
    const bf* gBh = Bh + (long)bn*K;
    const bf* gBl = Bl + (long)bn*K;

    auto load_stage = [&](int st, int k0){
        uint32_t s0 = sbase + st*STAGE_B;
        const bf* gp[4] = {gAh, gAl, gBh, gBl};
        #pragma unroll
        for (int t = 0; t < 4; ++t) {
            #pragma unroll
            for (int c = 0; c < 2; ++c) {
                int ch  = tid + c*256;            // 0..511
                int row = ch >> 2, seg = ch & 3;  // 128 rows x 4 x 16B
                cpa16(s0 + t*TILE_B + row*80 + seg*16,
                      gp[t] + (long)row*K + k0 + seg*8);
            }
        }
    };

    float acc[2][8][4];
    #pragma unroll
    for (int i = 0; i < 2; i++)
        #pragma unroll
        for (int j = 0; j < 8; j++)
            #pragma unroll
            for (int q = 0; q < 4; q++) acc[i][j][q] = 0.f;

    const int NC = K >> 5;
    load_stage(0, 0); cpcommit();

    const int l = lane & 7, sel = lane >> 3;
    const int rofs = l + ((sel & 1) << 3);
    const int cofs = (sel >> 1) << 3;

    for (int c = 0; c < NC; ++c) {
        if (c + 1 < NC) { load_stage((c+1)&1, (c+1)*32); cpcommit(); cpwait<1>(); }
        else            { cpwait<0>(); }
        __syncthreads();

        uint32_t s0  = sbase + (c&1)*STAGE_B;
        uint32_t sAh = s0, sAl = s0 + TILE_B, sBh = s0 + 2*TILE_B, sBl = s0 + 3*TILE_B;

        #pragma unroll
        for (int k16 = 0; k16 < 2; ++k16) {
            int colo = k16*16 + cofs;
            uint32_t ah[2][4], al[2][4];
            #pragma unroll
            for (int mi = 0; mi < 2; ++mi) {
                uint32_t off = (uint32_t)((wm*32 + mi*16 + rofs)*40 + colo)*2;
                ldmx4(ah[mi], sAh + off);
                ldmx4(al[mi], sAl + off);
            }
            uint32_t bh[4][4], bl[4][4];
            #pragma unroll
            for (int ni = 0; ni < 4; ++ni) {
                uint32_t off = (uint32_t)((wn*64 + ni*16 + rofs)*40 + colo)*2;
                ldmx4(bh[ni], sBh + off);
                ldmx4(bl[ni], sBl + off);
            }
            #pragma unroll
            for (int mi = 0; mi < 2; ++mi)
                #pragma unroll
                for (int nj = 0; nj < 8; ++nj) {
                    int g = nj >> 1, h8 = nj & 1;
                    mma16816(acc[mi][nj], ah[mi], bh[g][h8], bh[g][h8+2]);
                    mma16816(acc[mi][nj], al[mi], bh[g][h8], bh[g][h8+2]);
                    mma16816(acc[mi][nj], ah[mi], bl[g][h8], bl[g][h8+2]);
                }
        }
        __syncthreads();
    }

    // epilogue: fragment -> C
    const int tr = lane >> 2, tc = (lane & 3)*2;
    #pragma unroll
    for (int mi = 0; mi < 2; ++mi) {
        #pragma unroll
        for (int nj = 0; nj < 8; ++nj) {
            int m0 = bm + wm*32 + mi*16 + tr;
            int n0 = bn + wn*64 + nj*8 + tc;
            float v[4] = {acc[mi][nj][0], acc[mi][nj][1], acc[mi][nj][2], acc[mi][nj][3]};
            if (EPI >= 1) {
                float b0 = __ldg(bias + n0), b1 = __ldg(bias + n0 + 1);
                v[0] += b0; v[1] += b1; v[2] += b0; v[3] += b1;
            }
            if (EPI == 2) {
                v[0] = gelu_f(v[0]); v[1] = gelu_f(v[1]);
                v[2] = gelu_f(v[2]); v[3] = gelu_f(v[3]);
            }
            if (ldcn == 1) {
                *(float2*)(C + (long)m0*ldcm + n0)     = make_float2(v[0], v[1]);
                *(float2*)(C + (long)(m0+8)*ldcm + n0) = make_float2(v[2], v[3]);
            } else {
                C[(long)m0*ldcm     + (long)n0*ldcn]     = v[0];
                C[(long)m0*ldcm     + (long)(n0+1)*ldcn] = v[1];
                C[(long)(m0+8)*ldcm + (long)n0*ldcn]     = v[2];
                C[(long)(m0+8)*ldcm + (long)(n0+1)*ldcn] = v[3];
            }
        }
    }
}

// ======================= small kernels =======================
__global__ void k_wsplit(const float* __restrict__ w, bf* __restrict__ hi,
                         bf* __restrict__ lo, int K, int N) {
    __shared__ float t[32][33];
    int k0 = blockIdx.y*32, n0 = blockIdx.x*32;
    for (int r = threadIdx.y; r < 32; r += 8)
        t[r][threadIdx.x] = w[(long)(k0+r)*N + n0 + threadIdx.x];
    __syncthreads();
    for (int r = threadIdx.y; r < 32; r += 8) {
        float v = t[threadIdx.x][r];
        bf h = __float2bfloat16(v);
        long o = (long)(n0+r)*K + k0 + threadIdx.x;
        hi[o] = h;
        lo[o] = __float2bfloat16(v - __bfloat162float(h));
    }
}

__global__ void k_split(const float* __restrict__ in, bf* __restrict__ hi,
                        bf* __restrict__ lo, int n) {
    int i = blockIdx.x*blockDim.x + threadIdx.x;
    if (i >= n) return;
    float v = in[i];
    bf h = __float2bfloat16(v);
    hi[i] = h;
    lo[i] = __float2bfloat16(v - __bfloat162float(h));
}

__global__ void k_gather(const int* __restrict__ x, const float* __restrict__ emb,
                         bf* __restrict__ hi, bf* __restrict__ lo) {
    int i = blockIdx.x*blockDim.x + threadIdx.x;
    if (i >= BL*Ee) return;
    int e = i % Ee, bl = i / Ee;
    float v = emb[(long)x[bl]*Ee + e];
    bf h = __float2bfloat16(v);
    hi[i] = h;
    lo[i] = __float2bfloat16(v - __bfloat162float(h));
}

__global__ void k_init(const float* __restrict__ z0, const float* __restrict__ p0,
                       float* __restrict__ z, float* __restrict__ pah,
                       float* __restrict__ Na, float* __restrict__ No) {
    int i = blockIdx.x*blockDim.x + threadIdx.x;
    if (i < BQ*Ww*Dd) pah[i] = p0[i % (Ww*Dd)];
    if (i < BQ*Ww)    z[i]   = z0[i % Ww];
    if (i < BQ*SAa)   Na[i]  = 0.f;
    if (i < BQ*SOo)   No[i]  = 0.f;
}

__global__ void k_rope_split(const float* __restrict__ in, float* __restrict__ out,
                             int S, int do_rope) {
    int i = blockIdx.x*blockDim.x + threadIdx.x;
    if (i >= Bb*S*Ee) return;
    int d = i % HDd;
    int h = (i / HDd) % NHh;
    int s = (i / Ee) % S;
    int b = i / (Ee*S);
    const float* row = in + ((long)(b*S + s))*Ee + h*HDd;
    float v;
    if (do_rope) {
        const int half = HDd/2;
        int j = d % half;
        float inv = expf(-(float)j * (9.210340371976184f / (float)half));
        float ang = (float)s * inv;
        float c = cosf(ang), sn = sinf(ang);
        float x1 = row[j], x2 = row[j + half];
        v = (d < half) ? (x1*c - x2*sn) : (x2*c + x1*sn);
    } else {
        v = row[d];
    }
    out[(((long)(b*NHh + h))*S + s)*HDd + d] = v;
}

__global__ void k_attn(const float* __restrict__ qh, const float* __restrict__ kh,
                       const float* __restrict__ vh, float* __restrict__ ctx) {
    int qi = blockIdx.x, h = blockIdx.y, b = blockIdx.z;
    int tid = threadIdx.x;
    __shared__ float qs[HDd];
    __shared__ float sc[Ll];
    __shared__ float red[64];

    qs[tid] = qh[(((long)(b*NHh + h))*Qq + qi)*HDd + tid];
    __syncthreads();

    const float* kb = kh + ((long)(b*NHh + h))*Ll*HDd;
    const float scale = 0.125f;
    for (int k = tid; k < Ll; k += 64) {
        float s = -1e30f;
        if (k <= qi) {
            const float* kr = kb + (long)k*HDd;
            s = 0.f;
            #pragma unroll
            for (int d = 0; d < HDd; d += 4) {
                float4 kq = *(const float4*)(kr + d);
                float4 qv = *(const float4*)(qs + d);
                s += kq.x*qv.x + kq.y*qv.y + kq.z*qv.z + kq.w*qv.w;
            }
            s *= scale;
        }
        sc[k] = s;
    }
    __syncthreads();

    float m = -1e30f;
    for (int k = tid; k <= qi; k += 64) m = fmaxf(m, sc[k]);
    red[tid] = m; __syncthreads();
    for (int o = 32; o > 0; o >>= 1) { if (tid < o) red[tid] = fmaxf(red[tid], red[tid+o]); __syncthreads(); }
    m = red[0];
    __syncthreads();

    float ssum = 0.f;
    for (int k = tid; k <= qi; k += 64) { float e = expf(sc[k] - m); sc[k] = e; ssum += e; }
    red[tid] = ssum; __syncthreads();
    for (int o = 32; o > 0; o >>= 1) { if (tid < o) red[tid] += red[tid+o]; __syncthreads(); }
    float inv = 1.f / red[0];
    __syncthreads();

    const float* vb = vh + ((long)(b*NHh + h))*Ll*HDd;
    float acc = 0.f;
    for (int k = 0; k <= qi; k++) acc += sc[k]*vb[(long)k*HDd + tid];
    ctx[((long)(b*Qq + qi))*Ee + h*HDd + tid] = acc*inv;
}

__global__ void k_concat(const float* __restrict__ a, const float* __restrict__ z,
                         float* __restrict__ out) {
    int i = blockIdx.x*blockDim.x + threadIdx.x;
    if (i >= BQ*(Ee+Ww)) return;
    int c = i % (Ee+Ww), r = i / (Ee+Ww);
    out[i] = (c < Ee) ? a[(long)r*Ee + c] : z[(long)r*Ww + (c - Ee)];
}

__global__ void k_nlm(const float* __restrict__ pah, const float* __restrict__ w1,
                      const float* __restrict__ b1, const float* __restrict__ w2,
                      const float* __restrict__ b2, float* __restrict__ z, int start) {
    int w  = blockIdx.x;
    int bq = blockIdx.y*blockDim.x + threadIdx.x;
    __shared__ float w1s[Dd*Hn];
    __shared__ float b1s[Hn];
    __shared__ float w2s[Hn];
    if (threadIdx.x < Dd*Hn) w1s[threadIdx.x] = w1[(long)w*Dd*Hn + threadIdx.x];
    if (threadIdx.x < Hn) {
        b1s[threadIdx.x] = b1[(long)w*Hn + threadIdx.x];
        w2s[threadIdx.x] = w2[(long)w*Hn + threadIdx.x];
    }
    __syncthreads();
    float pv[Dd];
    const float* pr = pah + ((long)bq*Ww + w)*Dd;
    #pragma unroll
    for (int d = 0; d < Dd; d++) pv[d] = pr[(start + d) & 7];
    float zacc = b2[w];
    #pragma unroll
    for (int hh = 0; hh < Hn; hh++) {
        float a = b1s[hh];
        #pragma unroll
        for (int d = 0; d < Dd; d++) a += pv[d]*w1s[d*Hn + hh];
        zacc += gelu_f(a)*w2s[hh];
    }
    z[(long)bq*Ww + w] = zacc;
}

__global__ void k_sync(const float* __restrict__ z, float* __restrict__ Nbuf,
                       float* __restrict__ syn, const int* __restrict__ il,
                       const int* __restrict__ ir, const float* __restrict__ dec,
                       int S, int Tn) {
    int i = blockIdx.x*blockDim.x + threadIdx.x;
    if (i >= BQ*S) return;
    int s = i % S, bq = i / S;
    float d  = dec[s];
    float ed = expf(-d);
    const float* zr = z + (long)bq*Ww;
    float p  = zr[il[s]]*zr[ir[s]];
    float Nn = Nbuf[i]*ed + p;
    Nbuf[i] = Nn;
    float den = 0.f, wgt = 1.f;
    for (int k = 0; k < Tn; k++) { den += wgt; wgt *= ed; }
    syn[i] = Nn / sqrtf(den);
}

// ======================= host =======================
static void* symv(const void* s) { void* p = nullptr; cudaGetSymbolAddress(&p, s); return p; }

static void tg(int epi, const bf* Ah, const bf* Al, const bf* Bh, const bf* Bl,
               const float* bias, float* C, int M, int N, int K, long ldcm, long ldcn) {
    dim3 g(N/128, M/128);
    if (epi == 0) {
        cudaFuncSetAttribute(hgemm<0>, cudaFuncAttributeMaxDynamicSharedMemorySize, HG_SMEM);
        hgemm<0><<<g, 256, HG_SMEM>>>(Ah, Al, Bh, Bl, bias, C, M, N, K, ldcm, ldcn);
    } else if (epi == 1) {
        cudaFuncSetAttribute(hgemm<1>, cudaFuncAttributeMaxDynamicSharedMemorySize, HG_SMEM);
        hgemm<1><<<g, 256, HG_SMEM>>>(Ah, Al, Bh, Bl, bias, C, M, N, K, ldcm, ldcn);
    } else {
        cudaFuncSetAttribute(hgemm<2>, cudaFuncAttributeMaxDynamicSharedMemorySize, HG_SMEM);
        hgemm<2><<<g, 256, HG_SMEM>>>(Ah, Al, Bh, Bl, bias, C, M, N, K, ldcm, ldcn);
    }
}

extern "C" void kernel_launch(void* const* d_in, const int* in_sizes, int n_in,
                              void* d_out, int out_size) {
    (void)in_sizes; (void)n_in; (void)out_size;
    const int*   x      = (const int*)  d_in[0];
    const float* emb    = (const float*)d_in[2];
    const float* w_kv   = (const float*)d_in[3];
    const float* w_qs   = (const float*)d_in[4];
    const float* wq     = (const float*)d_in[5];
    const float* wk     = (const float*)d_in[6];
    const float* wv     = (const float*)d_in[7];
    const float* wo     = (const float*)d_in[8];
    const float* ws1    = (const float*)d_in[9];
    const float* bs1    = (const float*)d_in[10];
    const float* ws2    = (const float*)d_in[11];
    const float* bs2    = (const float*)d_in[12];
    const float* nw1    = (const float*)d_in[13];
    const float* nb1    = (const float*)d_in[14];
    const float* nw2    = (const float*)d_in[15];
    const float* nb2    = (const float*)d_in[16];
    const float* out_w  = (const float*)d_in[17];
    const float* out_b  = (const float*)d_in[18];
    const float* z_init = (const float*)d_in[19];
    const float* p_init = (const float*)d_in[20];
    const float* dec_a  = (const float*)d_in[21];
    const float* dec_o  = (const float*)d_in[22];
    const int*   idx_la = (const int*)  d_in[23];
    const int*   idx_ra = (const int*)  d_in[24];
    const int*   idx_lo = (const int*)  d_in[25];
    const int*   idx_ro = (const int*)  d_in[26];
    float* out = (float*)d_out;

    float *kv = (float*)symv(g_kv), *tmp = (float*)symv(g_tmp);
    float *qh = (float*)symv(g_qh), *kh = (float*)symv(g_kh), *vh = (float*)symv(g_vh);
    float *ctx = (float*)symv(g_ctx), *attn = (float*)symv(g_attn), *cat = (float*)symv(g_cat);
    float *h1 = (float*)symv(g_h1), *z = (float*)symv(g_z), *pah = (float*)symv(g_pah);
    float *Na = (float*)symv(g_Na), *No = (float*)symv(g_No);
    float *sa = (float*)symv(g_sa), *so = (float*)symv(g_so);
    float *qbuf = (float*)symv(g_q);

    bf *wkvTh=(bf*)symv(g_wkvT_h), *wkvTl=(bf*)symv(g_wkvT_l);
    bf *wqsTh=(bf*)symv(g_wqsT_h), *wqsTl=(bf*)symv(g_wqsT_l);
    bf *wqTh =(bf*)symv(g_wqT_h),  *wqTl =(bf*)symv(g_wqT_l);
    bf *wkTh =(bf*)symv(g_wkT_h),  *wkTl =(bf*)symv(g_wkT_l);
    bf *wvTh =(bf*)symv(g_wvT_h),  *wvTl =(bf*)symv(g_wvT_l);
    bf *woTh =(bf*)symv(g_woT_h),  *woTl =(bf*)symv(g_woT_l);
    bf *ws1Th=(bf*)symv(g_ws1T_h), *ws1Tl=(bf*)symv(g_ws1T_l);
    bf *ws2Th=(bf*)symv(g_ws2T_h), *ws2Tl=(bf*)symv(g_ws2T_l);
    bf *owTh =(bf*)symv(g_owT_h),  *owTl =(bf*)symv(g_owT_l);
    bf *acth =(bf*)symv(g_act_h),  *actl =(bf*)symv(g_act_l);

    const int TPB = 256;
    dim3 wb(32, 8);

    // ---- weight transpose + split (loop invariant) ----
    k_wsplit<<<dim3(Ee/32,   Ee/32),  wb>>>(w_kv,  wkvTh, wkvTl, Ee,  Ee);
    k_wsplit<<<dim3(Ee/32,   SAa/32), wb>>>(w_qs,  wqsTh, wqsTl, SAa, Ee);
    k_wsplit<<<dim3(Ee/32,   Ee/32),  wb>>>(wq,    wqTh,  wqTl,  Ee,  Ee);
    k_wsplit<<<dim3(Ee/32,   Ee/32),  wb>>>(wk,    wkTh,  wkTl,  Ee,  Ee);
    k_wsplit<<<dim3(Ee/32,   Ee/32),  wb>>>(wv,    wvTh,  wvTl,  Ee,  Ee);
    k_wsplit<<<dim3(Ee/32,   Ee/32),  wb>>>(wo,    woTh,  woTl,  Ee,  Ee);
    k_wsplit<<<dim3(SHh/32,  (Ee+Ww)/32), wb>>>(ws1, ws1Th, ws1Tl, Ee+Ww, SHh);
    k_wsplit<<<dim3(Ww/32,   SHh/32), wb>>>(ws2,   ws2Th, ws2Tl, SHh, Ww);
    k_wsplit<<<dim3(Vv/32,   SOo/32), wb>>>(out_w, owTh,  owTl,  SOo, Vv);

    // ---- prologue: kv, kh, vh ----
    k_gather<<<(BL*Ee + TPB-1)/TPB, TPB>>>(x, emb, acth, actl);
    tg(0, acth, actl, wkvTh, wkvTl, nullptr, kv, BL, Ee, Ee, Ee, 1);
    k_split<<<(BL*Ee + TPB-1)/TPB, TPB>>>(kv, acth, actl, BL*Ee);
    tg(0, acth, actl, wkTh, wkTl, nullptr, tmp, BL, Ee, Ee, Ee, 1);
    k_rope_split<<<(Bb*Ll*Ee + TPB-1)/TPB, TPB>>>(tmp, kh, Ll, 1);
    tg(0, acth, actl, wvTh, wvTl, nullptr, tmp, BL, Ee, Ee, Ee, 1);
    k_rope_split<<<(Bb*Ll*Ee + TPB-1)/TPB, TPB>>>(tmp, vh, Ll, 0);

    k_init<<<(BQ*Ww*Dd + TPB-1)/TPB, TPB>>>(z_init, p_init, z, pah, Na, No);
    k_sync<<<(BQ*SAa + TPB-1)/TPB, TPB>>>(z, Na, sa, idx_la, idx_ra, dec_a, SAa, 1);
    k_sync<<<(BQ*SOo + TPB-1)/TPB, TPB>>>(z, No, so, idx_lo, idx_ro, dec_o, SOo, 1);

    // ---- T iterations ----
    for (int t = 0; t < Tt; t++) {
        k_split<<<(BQ*SAa + TPB-1)/TPB, TPB>>>(sa, acth, actl, BQ*SAa);
        tg(0, acth, actl, wqsTh, wqsTl, nullptr, qbuf, BQ, Ee, SAa, Ee, 1);
        k_split<<<(BQ*Ee + TPB-1)/TPB, TPB>>>(qbuf, acth, actl, BQ*Ee);
        tg(0, acth, actl, wqTh, wqTl, nullptr, tmp, BQ, Ee, Ee, Ee, 1);
        k_rope_split<<<(Bb*Qq*Ee + TPB-1)/TPB, TPB>>>(tmp, qh, Qq, 1);
        k_attn<<<dim3(Qq, NHh, Bb), 64>>>(qh, kh, vh, ctx);
        k_split<<<(BQ*Ee + TPB-1)/TPB, TPB>>>(ctx, acth, actl, BQ*Ee);
        tg(0, acth, actl, woTh, woTl, nullptr, attn, BQ, Ee, Ee, Ee, 1);
        k_concat<<<(BQ*(Ee+Ww) + TPB-1)/TPB, TPB>>>(attn, z, cat);
        k_split<<<(BQ*(Ee+Ww) + TPB-1)/TPB, TPB>>>(cat, acth, actl, BQ*(Ee+Ww));
        tg(2, acth, actl, ws1Th, ws1Tl, bs1, h1, BQ, SHh, Ee+Ww, SHh, 1);
        k_split<<<(BQ*SHh + TPB-1)/TPB, TPB>>>(h1, acth, actl, BQ*SHh);
        tg(1, acth, actl, ws2Th, ws2Tl, bs2, pah + t, BQ, Ww, SHh, (long)Ww*Dd, Dd);
        k_nlm<<<dim3(Ww, BQ/TPB), TPB>>>(pah, nw1, nb1, nw2, nb2, z, t + 1);
        k_sync<<<(BQ*SAa + TPB-1)/TPB, TPB>>>(z, Na, sa, idx_la, idx_ra, dec_a, SAa, t + 2);
        k_sync<<<(BQ*SOo + TPB-1)/TPB, TPB>>>(z, No, so, idx_lo, idx_ro, dec_o, SOo, t + 2);
        k_split<<<(BQ*SOo + TPB-1)/TPB, TPB>>>(so, acth, actl, BQ*SOo);
        tg(1, acth, actl, owTh, owTl, out_b, out + (long)t*BQ*Vv, BQ, Vv, SOo, Vv, 1);
    }
}

// round 8
// speedup vs baseline: 3.0772x; 1.3495x over previous
#include <cuda_runtime.h>
#include <cuda_bf16.h>
#include <math.h>
#include <stdint.h>

// ---- problem constants ----
#define Bb   2
#define Ll   512
#define Qq   512
#define Ee   1024
#define Ww   1024
#define Dd   8
#define Hn   32
#define NHh  16
#define HDd  64
#define SAa  512
#define SOo  1024
#define Vv   8192
#define Tt   6
#define SHh  2048
#define BQ   (Bb*Qq)
#define BL   (Bb*Ll)

typedef __nv_bfloat16 bf;

// ---- fp32 scratch ----
__device__ float g_tmp [BQ*Ee];
__device__ float g_qh  [Bb*NHh*Qq*HDd];
__device__ float g_kh  [Bb*NHh*Ll*HDd];
__device__ float g_vh  [Bb*NHh*Ll*HDd];
__device__ float g_z   [BQ*Ww];
__device__ float g_pah [Dd*BQ*Ww];          // 8 planes of [BQ][Ww]
__device__ float g_Na  [BQ*SAa];
__device__ float g_No  [BQ*SOo];

// ---- bf16 hi/lo activation buffers ----
__device__ bf g_embh[BL*Ee],        g_embl[BL*Ee];
__device__ bf g_kvh [BL*Ee],        g_kvl [BL*Ee];
__device__ bf g_ctxh[BQ*Ee],        g_ctxl[BQ*Ee];
__device__ bf g_cath[BQ*(Ee+Ww)],   g_catl[BQ*(Ee+Ww)];
__device__ bf g_h1h [BQ*SHh],       g_h1l [BQ*SHh];
__device__ bf g_sah [BQ*SAa],       g_sal [BQ*SAa];
__device__ bf g_soh [BQ*SOo],       g_sol [BQ*SOo];

// ---- bf16 hi/lo weights (transposed [N,K] unless noted) ----
__device__ bf g_wkvT_h[Ee*Ee],       g_wkvT_l[Ee*Ee];
__device__ bf g_wqT_h [Ee*Ee],       g_wqT_l [Ee*Ee];
__device__ bf g_wkT_h [Ee*Ee],       g_wkT_l [Ee*Ee];
__device__ bf g_wvT_h [Ee*Ee],       g_wvT_l [Ee*Ee];
__device__ bf g_woT_h [Ee*Ee],       g_woT_l [Ee*Ee];
__device__ bf g_ws1T_h[SHh*(Ee+Ww)], g_ws1T_l[SHh*(Ee+Ww)];
__device__ bf g_ws2T_h[Ww*SHh],      g_ws2T_l[Ww*SHh];
__device__ bf g_owT_h [Vv*SOo],      g_owT_l [Vv*SOo];
__device__ bf g_wqs_h [SAa*Ee],      g_wqs_l [SAa*Ee];   // raw [SA][E]
__device__ bf g_Wch   [Ee*SAa],      g_Wcl   [Ee*SAa];   // combined (wqs@wq)^T

__device__ __forceinline__ float gelu_f(float x) {
    float x3 = x*x*x;
    return 0.5f*x*(1.0f + tanhf(0.7978845608028654f*(x + 0.044715f*x3)));
}

// ====================== mma.sync GEMM ======================
__device__ __forceinline__ void cpa16(uint32_t s, const void* g){
    asm volatile("cp.async.cg.shared.global [%0], [%1], 16;" :: "r"(s), "l"(g));
}
__device__ __forceinline__ void cpcommit(){ asm volatile("cp.async.commit_group;" ::: "memory"); }
template<int N> __device__ __forceinline__ void cpwait(){ asm volatile("cp.async.wait_group %0;" :: "n"(N) : "memory"); }
__device__ __forceinline__ void ldmx4(uint32_t* r, uint32_t a){
    asm volatile("ldmatrix.sync.aligned.m8n8.x4.shared.b16 {%0,%1,%2,%3}, [%4];"
        : "=r"(r[0]),"=r"(r[1]),"=r"(r[2]),"=r"(r[3]) : "r"(a));
}
__device__ __forceinline__ void mma16816(float* c, const uint32_t* a, uint32_t b0, uint32_t b1){
    asm volatile("mma.sync.aligned.m16n8k16.row.col.f32.bf16.bf16.f32 "
        "{%0,%1,%2,%3}, {%4,%5,%6,%7}, {%8,%9}, {%0,%1,%2,%3};"
        : "+f"(c[0]),"+f"(c[1]),"+f"(c[2]),"+f"(c[3])
        : "r"(a[0]),"r"(a[1]),"r"(a[2]),"r"(a[3]), "r"(b0),"r"(b1));
}

// C(M,N) = epi(A @ B^T [+bias]); A,B bf16 hi/lo, B stored [N,K].
// BM x 128 x 32 tiles, 256 thr, 2-stage cp.async.
// EPI: 0=none 1=+bias 2=gelu(+bias).  OSPLIT: 1 -> write bf16 hi/lo (row stride ldh)
template<int EPI, int BM, int OSPLIT>
__global__ void __launch_bounds__(256, (BM==64)?2:1) hgemm(
    const bf* __restrict__ Ah, const bf* __restrict__ Al,
    const bf* __restrict__ Bh, const bf* __restrict__ Bl,
    const float* __restrict__ bias,
    float* __restrict__ C, bf* __restrict__ Ch, bf* __restrict__ Cl,
    int M, int N, int K, long ldcm, long ldcn, long ldh)
{
    constexpr int WMW = BM/32;            // warps along M
    constexpr int WNW = 8/WMW;            // warps along N
    constexpr int WARP_N = 128/WNW;
    constexpr int NJ = WARP_N/8;
    constexpr int TILE_A = BM*40*2;
    constexpr int TILE_Bt = 128*40*2;
    constexpr int STAGE = 2*TILE_A + 2*TILE_Bt;

    extern __shared__ __align__(16) char dyn[];
    const int tid  = threadIdx.x;
    const int wid  = tid >> 5, lane = tid & 31;
    const int bm = blockIdx.y*BM, bn = blockIdx.x*128;
    const int wm = wid % WMW, wn = wid / WMW;

    uint32_t sbase = (uint32_t)__cvta_generic_to_shared(dyn);

    const bf* gAh = Ah + (long)bm*K;
    const bf* gAl = Al + (long)bm*K;
    const bf* gBh = Bh + (long)bn*K;
    const bf* gBl = Bl + (long)bn*K;

    auto load_stage = [&](int st, int k0){
        uint32_t s0 = sbase + st*STAGE;
        #pragma unroll
        for (int c = 0; c < BM/64; ++c) {
            int ch = tid + c*256;
            int row = ch >> 2, seg = ch & 3;
            cpa16(s0 + row*80 + seg*16,          gAh + (long)row*K + k0 + seg*8);
            cpa16(s0 + TILE_A + row*80 + seg*16, gAl + (long)row*K + k0 + seg*8);
        }
        #pragma unroll
        for (int c = 0; c < 2; ++c) {
            int ch = tid + c*256;
            int row = ch >> 2, seg = ch & 3;
            cpa16(s0 + 2*TILE_A + row*80 + seg*16,           gBh + (long)row*K + k0 + seg*8);
            cpa16(s0 + 2*TILE_A + TILE_Bt + row*80 + seg*16, gBl + (long)row*K + k0 + seg*8);
        }
    };

    float acc[2][NJ][4];
    #pragma unroll
    for (int i = 0; i < 2; i++)
        #pragma unroll
        for (int j = 0; j < NJ; j++)
            #pragma unroll
            for (int q = 0; q < 4; q++) acc[i][j][q] = 0.f;

    const int NC = K >> 5;
    load_stage(0, 0); cpcommit();

    const int l = lane & 7, sel = lane >> 3;
    const int rofs = l + ((sel & 1) << 3);
    const int cofs = (sel >> 1) << 3;

    for (int c = 0; c < NC; ++c) {
        if (c + 1 < NC) { load_stage((c+1)&1, (c+1)*32); cpcommit(); cpwait<1>(); }
        else            { cpwait<0>(); }
        __syncthreads();

        uint32_t s0  = sbase + (c&1)*STAGE;
        uint32_t sAh = s0, sAl = s0 + TILE_A, sBh = s0 + 2*TILE_A, sBl = sBh + TILE_Bt;

        #pragma unroll
        for (int k16 = 0; k16 < 2; ++k16) {
            int colo = k16*16 + cofs;
            uint32_t ah[2][4], al[2][4];
            #pragma unroll
            for (int mi = 0; mi < 2; ++mi) {
                uint32_t off = (uint32_t)((wm*32 + mi*16 + rofs)*40 + colo)*2;
                ldmx4(ah[mi], sAh + off);
                ldmx4(al[mi], sAl + off);
            }
            uint32_t bh[NJ/2][4], bl[NJ/2][4];
            #pragma unroll
            for (int ni = 0; ni < NJ/2; ++ni) {
                uint32_t off = (uint32_t)((wn*WARP_N + ni*16 + rofs)*40 + colo)*2;
                ldmx4(bh[ni], sBh + off);
                ldmx4(bl[ni], sBl + off);
            }
            #pragma unroll
            for (int mi = 0; mi < 2; ++mi)
                #pragma unroll
                for (int nj = 0; nj < NJ; ++nj) {
                    int g = nj >> 1, h8 = nj & 1;
                    mma16816(acc[mi][nj], ah[mi], bh[g][h8], bh[g][h8+2]);
                    mma16816(acc[mi][nj], al[mi], bh[g][h8], bh[g][h8+2]);
                    mma16816(acc[mi][nj], ah[mi], bl[g][h8], bl[g][h8+2]);
                }
        }
        __syncthreads();
    }

    const int tr = lane >> 2, tc = (lane & 3)*2;
    #pragma unroll
    for (int mi = 0; mi < 2; ++mi) {
        #pragma unroll
        for (int nj = 0; nj < NJ; ++nj) {
            int m0 = bm + wm*32 + mi*16 + tr;
            int n0 = bn + wn*WARP_N + nj*8 + tc;
            float v[4] = {acc[mi][nj][0], acc[mi][nj][1], acc[mi][nj][2], acc[mi][nj][3]};
            if (EPI >= 1) {
                float b0 = __ldg(bias + n0), b1 = __ldg(bias + n0 + 1);
                v[0] += b0; v[1] += b1; v[2] += b0; v[3] += b1;
            }
            if (EPI == 2) {
                v[0] = gelu_f(v[0]); v[1] = gelu_f(v[1]);
                v[2] = gelu_f(v[2]); v[3] = gelu_f(v[3]);
            }
            if (OSPLIT) {
                #pragma unroll
                for (int rr = 0; rr < 2; ++rr) {
                    long base = (long)(m0 + rr*8)*ldh + n0;
                    bf h0 = __float2bfloat16(v[rr*2+0]);
                    bf h1 = __float2bfloat16(v[rr*2+1]);
                    bf l0 = __float2bfloat16(v[rr*2+0] - __bfloat162float(h0));
                    bf l1 = __float2bfloat16(v[rr*2+1] - __bfloat162float(h1));
                    __nv_bfloat162 hh; hh.x = h0; hh.y = h1;
                    __nv_bfloat162 llv; llv.x = l0; llv.y = l1;
                    *reinterpret_cast<__nv_bfloat162*>(Ch + base) = hh;
                    *reinterpret_cast<__nv_bfloat162*>(Cl + base) = llv;
                }
            } else if (ldcn == 1) {
                *(float2*)(C + (long)m0*ldcm + n0)     = make_float2(v[0], v[1]);
                *(float2*)(C + (long)(m0+8)*ldcm + n0) = make_float2(v[2], v[3]);
            } else {
                C[(long)m0*ldcm     + (long)n0*ldcn]     = v[0];
                C[(long)m0*ldcm     + (long)(n0+1)*ldcn] = v[1];
                C[(long)(m0+8)*ldcm + (long)n0*ldcn]     = v[2];
                C[(long)(m0+8)*ldcm + (long)(n0+1)*ldcn] = v[3];
            }
        }
    }
}

// ======================= flash attention =======================
// block: 16 queries x (head, batch); exact two-pass softmax; smem-tiled K/V.
// writes ctx split to bf16 hi/lo at [(b*Q+q)*E + h*64 + d]
#define FA_QS   0
#define FA_KC   (16*68)
#define FA_SC   (FA_KC + 64*68)
#define FA_FLT  (FA_SC + 16*512)
#define FA_SMEM (FA_FLT*4)

__global__ void __launch_bounds__(256) k_fattn(
    const float* __restrict__ qh, const float* __restrict__ kh,
    const float* __restrict__ vh, bf* __restrict__ ctxh, bf* __restrict__ ctxl)
{
    extern __shared__ __align__(16) float sm[];
    float* qs = sm + FA_QS;
    float* kc = sm + FA_KC;
    float* sc = sm + FA_SC;

    const int tid = threadIdx.x;
    const int q0 = blockIdx.x*16, h = blockIdx.y, b = blockIdx.z;
    const int qi = tid >> 4, tsub = tid & 15;

    const float* Qb = qh + ((long)(b*NHh + h)*Qq + q0)*HDd;
    const float* Kb = kh + ((long)(b*NHh + h)*Ll)*HDd;
    const float* Vb = vh + ((long)(b*NHh + h)*Ll)*HDd;

    // load Q tile: one float4 per thread
    {
        int row = tid >> 4, d = (tid & 15)*4;
        *(float4*)(qs + row*68 + d) = *(const float4*)(Qb + row*HDd + d);
    }

    const int NCv = (q0 + 15)/64 + 1;          // chunks with any unmasked key
    const int KLIM = NCv*64;
    const int qg = q0 + qi;

    // ---- pass 1: scores ----
    for (int c = 0; c < NCv; ++c) {
        __syncthreads();
        for (int j = tid; j < 1024; j += 256) {
            int row = j >> 4, d = (j & 15)*4;
            *(float4*)(kc + row*68 + d) = *(const float4*)(Kb + (long)(c*64 + row)*HDd + d);
        }
        __syncthreads();
        #pragma unroll
        for (int jk = 0; jk < 4; ++jk) {
            int kl = jk*16 + tsub;
            int kg = c*64 + kl;
            float s = -1e30f;
            if (kg <= qg) {
                float4 acc4 = make_float4(0.f,0.f,0.f,0.f);
                #pragma unroll
                for (int d = 0; d < HDd; d += 4) {
                    float4 qv = *(float4*)(qs + qi*68 + d);
                    float4 kv4 = *(float4*)(kc + kl*68 + d);
                    acc4.x += qv.x*kv4.x; acc4.y += qv.y*kv4.y;
                    acc4.z += qv.z*kv4.z; acc4.w += qv.w*kv4.w;
                }
                s = (acc4.x + acc4.y + acc4.z + acc4.w) * 0.125f;
            }
            sc[qi*512 + kg] = s;
        }
    }
    __syncthreads();

    // ---- softmax (16 threads per query) ----
    float m = -1e30f;
    for (int k = tsub; k < KLIM; k += 16) m = fmaxf(m, sc[qi*512 + k]);
    #pragma unroll
    for (int o = 8; o > 0; o >>= 1) m = fmaxf(m, __shfl_xor_sync(0xffffffffu, m, o, 16));
    float sum = 0.f;
    for (int k = tsub; k < KLIM; k += 16) {
        float e = expf(sc[qi*512 + k] - m);
        sc[qi*512 + k] = e;
        sum += e;
    }
    #pragma unroll
    for (int o = 8; o > 0; o >>= 1) sum += __shfl_xor_sync(0xffffffffu, sum, o, 16);
    const float inv = 1.f / sum;

    // ---- pass 2: PV ----
    float a0 = 0.f, a1 = 0.f, a2 = 0.f, a3 = 0.f;
    const int d0 = tsub*4;
    for (int c = 0; c < NCv; ++c) {
        __syncthreads();
        for (int j = tid; j < 1024; j += 256) {
            int row = j >> 4, d = (j & 15)*4;
            *(float4*)(kc + row*68 + d) = *(const float4*)(Vb + (long)(c*64 + row)*HDd + d);
        }
        __syncthreads();
        #pragma unroll 8
        for (int k = 0; k < 64; ++k) {
            float p = sc[qi*512 + c*64 + k];
            float4 vv = *(float4*)(kc + k*68 + d0);
            a0 += p*vv.x; a1 += p*vv.y; a2 += p*vv.z; a3 += p*vv.w;
        }
    }

    // ---- output split ----
    a0 *= inv; a1 *= inv; a2 *= inv; a3 *= inv;
    long base = (long)(b*Qq + q0 + qi)*Ee + h*HDd + d0;
    float v[4] = {a0, a1, a2, a3};
    #pragma unroll
    for (int rr = 0; rr < 2; ++rr) {
        bf h0 = __float2bfloat16(v[rr*2+0]);
        bf h1 = __float2bfloat16(v[rr*2+1]);
        bf l0 = __float2bfloat16(v[rr*2+0] - __bfloat162float(h0));
        bf l1 = __float2bfloat16(v[rr*2+1] - __bfloat162float(h1));
        __nv_bfloat162 hh; hh.x = h0; hh.y = h1;
        __nv_bfloat162 llv; llv.x = l0; llv.y = l1;
        *reinterpret_cast<__nv_bfloat162*>(ctxh + base + rr*2) = hh;
        *reinterpret_cast<__nv_bfloat162*>(ctxl + base + rr*2) = llv;
    }
}

// ======================= small kernels =======================
__global__ void k_wsplit(const float* __restrict__ w, bf* __restrict__ hi,
                         bf* __restrict__ lo, int K, int N) {
    __shared__ float t[32][33];
    int k0 = blockIdx.y*32, n0 = blockIdx.x*32;
    for (int r = threadIdx.y; r < 32; r += 8)
        t[r][threadIdx.x] = w[(long)(k0+r)*N + n0 + threadIdx.x];
    __syncthreads();
    for (int r = threadIdx.y; r < 32; r += 8) {
        float v = t[threadIdx.x][r];
        bf h = __float2bfloat16(v);
        long o = (long)(n0+r)*K + k0 + threadIdx.x;
        hi[o] = h;
        lo[o] = __float2bfloat16(v - __bfloat162float(h));
    }
}

__global__ void k_split(const float* __restrict__ in, bf* __restrict__ hi,
                        bf* __restrict__ lo, int n) {
    int i = blockIdx.x*blockDim.x + threadIdx.x;
    if (i >= n) return;
    float v = in[i];
    bf h = __float2bfloat16(v);
    hi[i] = h;
    lo[i] = __float2bfloat16(v - __bfloat162float(h));
}

__global__ void k_gather(const int* __restrict__ x, const float* __restrict__ emb,
                         bf* __restrict__ hi, bf* __restrict__ lo) {
    int i = blockIdx.x*blockDim.x + threadIdx.x;
    if (i >= BL*Ee) return;
    int e = i % Ee, bl = i / Ee;
    float v = emb[(long)x[bl]*Ee + e];
    bf h = __float2bfloat16(v);
    hi[i] = h;
    lo[i] = __float2bfloat16(v - __bfloat162float(h));
}

// init: z (fp32 + cat hi/lo cols), pah planes, numerators
__global__ void k_init(const float* __restrict__ z0, const float* __restrict__ p0,
                       float* __restrict__ z, float* __restrict__ pah,
                       float* __restrict__ Na, float* __restrict__ No,
                       bf* __restrict__ cath, bf* __restrict__ catl) {
    int i = blockIdx.x*blockDim.x + threadIdx.x;
    if (i < Dd*BQ*Ww) {
        int d = i / (BQ*Ww);
        int w = i % Ww;
        pah[i] = p0[w*Dd + d];
    }
    if (i < BQ*Ww) {
        int w = i % Ww, bq = i / Ww;
        float v = z0[w];
        z[i] = v;
        bf h = __float2bfloat16(v);
        cath[(long)bq*(Ee+Ww) + Ee + w] = h;
        catl[(long)bq*(Ee+Ww) + Ee + w] = __float2bfloat16(v - __bfloat162float(h));
    }
    if (i < BQ*SAa) Na[i] = 0.f;
    if (i < BQ*SOo) No[i] = 0.f;
}

__global__ void k_rope_split(const float* __restrict__ in, float* __restrict__ out,
                             int S, int do_rope) {
    int i = blockIdx.x*blockDim.x + threadIdx.x;
    if (i >= Bb*S*Ee) return;
    int d = i % HDd;
    int h = (i / HDd) % NHh;
    int s = (i / Ee) % S;
    int b = i / (Ee*S);
    const float* row = in + ((long)(b*S + s))*Ee + h*HDd;
    float v;
    if (do_rope) {
        const int half = HDd/2;
        int j = d % half;
        float inv = expf(-(float)j * (9.210340371976184f / (float)half));
        float ang = (float)s * inv;
        float c = cosf(ang), sn = sinf(ang);
        float x1 = row[j], x2 = row[j + half];
        v = (d < half) ? (x1*c - x2*sn) : (x2*c + x1*sn);
    } else {
        v = row[d];
    }
    out[(((long)(b*NHh + h))*S + s)*HDd + d] = v;
}

// NLM: 32 w's per block (weights in smem), threads (32w x 8bq), bq-loop.
// writes z fp32 and z hi/lo into cat columns [Ee, Ee+Ww)
__global__ void __launch_bounds__(256) k_nlm(
    const float* __restrict__ pah, const float* __restrict__ w1,
    const float* __restrict__ b1, const float* __restrict__ w2,
    const float* __restrict__ b2, float* __restrict__ z,
    bf* __restrict__ cath, bf* __restrict__ catl, int start)
{
    __shared__ float w1s[32*257];
    __shared__ float b1s[32*33];
    __shared__ float w2s[32*33];
    __shared__ float b2s[32];
    const int tid = threadIdx.x;
    const int w0 = blockIdx.x*32, bq0 = blockIdx.y*128;

    for (int j = tid; j < 32*256; j += 256) w1s[(j>>8)*257 + (j&255)] = w1[(long)w0*256 + j];
    for (int j = tid; j < 32*32;  j += 256) {
        b1s[(j>>5)*33 + (j&31)] = b1[(long)w0*32 + j];
        w2s[(j>>5)*33 + (j&31)] = w2[(long)w0*32 + j];
    }
    if (tid < 32) b2s[tid] = b2[w0 + tid];
    __syncthreads();

    const int wl = tid & 31, bql = tid >> 5;
    const int w = w0 + wl;
    for (int bq = bq0 + bql; bq < bq0 + 128; bq += 8) {
        float pv[Dd];
        #pragma unroll
        for (int d = 0; d < Dd; d++)
            pv[d] = pah[(long)((start + d) & 7)*BQ*Ww + (long)bq*Ww + w];
        float zacc = b2s[wl];
        #pragma unroll
        for (int hh = 0; hh < Hn; hh++) {
            float a = b1s[wl*33 + hh];
            #pragma unroll
            for (int d = 0; d < Dd; d++) a += pv[d]*w1s[wl*257 + d*32 + hh];
            zacc += gelu_f(a)*w2s[wl*33 + hh];
        }
        z[(long)bq*Ww + w] = zacc;
        bf h = __float2bfloat16(zacc);
        cath[(long)bq*(Ee+Ww) + Ee + w] = h;
        catl[(long)bq*(Ee+Ww) + Ee + w] = __float2bfloat16(zacc - __bfloat162float(h));
    }
}

// incremental sync -> bf16 hi/lo output
__global__ void k_sync(const float* __restrict__ z, float* __restrict__ Nbuf,
                       bf* __restrict__ synh, bf* __restrict__ synl,
                       const int* __restrict__ il, const int* __restrict__ ir,
                       const float* __restrict__ dec, int S, int Tn) {
    int i = blockIdx.x*blockDim.x + threadIdx.x;
    if (i >= BQ*S) return;
    int s = i % S, bq = i / S;
    float d  = dec[s];
    float ed = expf(-d);
    const float* zr = z + (long)bq*Ww;
    float p  = zr[il[s]]*zr[ir[s]];
    float Nn = Nbuf[i]*ed + p;
    Nbuf[i] = Nn;
    float den = 0.f, wgt = 1.f;
    for (int k = 0; k < Tn; k++) { den += wgt; wgt *= ed; }
    float v = Nn / sqrtf(den);
    bf h = __float2bfloat16(v);
    synh[i] = h;
    synl[i] = __float2bfloat16(v - __bfloat162float(h));
}

// ======================= host =======================
static void* symv(const void* s) { void* p = nullptr; cudaGetSymbolAddress(&p, s); return p; }

template<int EPI, int BM, int OSPLIT>
static void rung(const bf* Ah, const bf* Al, const bf* Bh, const bf* Bl,
                 const float* bias, float* C, bf* Ch, bf* Cl,
                 int M, int N, int K, long ldcm, long ldcn, long ldh) {
    constexpr int SM = 2*(2*BM*40*2 + 2*10240);
    cudaFuncSetAttribute(hgemm<EPI,BM,OSPLIT>, cudaFuncAttributeMaxDynamicSharedMemorySize, SM);
    dim3 g(N/128, M/BM);
    hgemm<EPI,BM,OSPLIT><<<g, 256, SM>>>(Ah, Al, Bh, Bl, bias, C, Ch, Cl, M, N, K, ldcm, ldcn, ldh);
}

extern "C" void kernel_launch(void* const* d_in, const int* in_sizes, int n_in,
                              void* d_out, int out_size) {
    (void)in_sizes; (void)n_in; (void)out_size;
    const int*   x      = (const int*)  d_in[0];
    const float* emb    = (const float*)d_in[2];
    const float* w_kv   = (const float*)d_in[3];
    const float* w_qs   = (const float*)d_in[4];
    const float* wq     = (const float*)d_in[5];
    const float* wk     = (const float*)d_in[6];
    const float* wv     = (const float*)d_in[7];
    const float* wo     = (const float*)d_in[8];
    const float* ws1    = (const float*)d_in[9];
    const float* bs1    = (const float*)d_in[10];
    const float* ws2    = (const float*)d_in[11];
    const float* bs2    = (const float*)d_in[12];
    const float* nw1    = (const float*)d_in[13];
    const float* nb1    = (const float*)d_in[14];
    const float* nw2    = (const float*)d_in[15];
    const float* nb2    = (const float*)d_in[16];
    const float* out_w  = (const float*)d_in[17];
    const float* out_b  = (const float*)d_in[18];
    const float* z_init = (const float*)d_in[19];
    const float* p_init = (const float*)d_in[20];
    const float* dec_a  = (const float*)d_in[21];
    const float* dec_o  = (const float*)d_in[22];
    const int*   idx_la = (const int*)  d_in[23];
    const int*   idx_ra = (const int*)  d_in[24];
    const int*   idx_lo = (const int*)  d_in[25];
    const int*   idx_ro = (const int*)  d_in[26];
    float* out = (float*)d_out;

    float *tmp = (float*)symv(g_tmp);
    float *qh = (float*)symv(g_qh), *kh = (float*)symv(g_kh), *vh = (float*)symv(g_vh);
    float *z = (float*)symv(g_z), *pah = (float*)symv(g_pah);
    float *Na = (float*)symv(g_Na), *No = (float*)symv(g_No);

    bf *embh=(bf*)symv(g_embh), *embl=(bf*)symv(g_embl);
    bf *kvh=(bf*)symv(g_kvh),   *kvl=(bf*)symv(g_kvl);
    bf *ctxh=(bf*)symv(g_ctxh), *ctxl=(bf*)symv(g_ctxl);
    bf *cath=(bf*)symv(g_cath), *catl=(bf*)symv(g_catl);
    bf *h1h=(bf*)symv(g_h1h),   *h1l=(bf*)symv(g_h1l);
    bf *sah=(bf*)symv(g_sah),   *sal=(bf*)symv(g_sal);
    bf *soh=(bf*)symv(g_soh),   *sol=(bf*)symv(g_sol);

    bf *wkvTh=(bf*)symv(g_wkvT_h), *wkvTl=(bf*)symv(g_wkvT_l);
    bf *wqTh =(bf*)symv(g_wqT_h),  *wqTl =(bf*)symv(g_wqT_l);
    bf *wkTh =(bf*)symv(g_wkT_h),  *wkTl =(bf*)symv(g_wkT_l);
    bf *wvTh =(bf*)symv(g_wvT_h),  *wvTl =(bf*)symv(g_wvT_l);
    bf *woTh =(bf*)symv(g_woT_h),  *woTl =(bf*)symv(g_woT_l);
    bf *ws1Th=(bf*)symv(g_ws1T_h), *ws1Tl=(bf*)symv(g_ws1T_l);
    bf *ws2Th=(bf*)symv(g_ws2T_h), *ws2Tl=(bf*)symv(g_ws2T_l);
    bf *owTh =(bf*)symv(g_owT_h),  *owTl =(bf*)symv(g_owT_l);
    bf *wqsh =(bf*)symv(g_wqs_h),  *wqsl =(bf*)symv(g_wqs_l);
    bf *Wch  =(bf*)symv(g_Wch),    *Wcl  =(bf*)symv(g_Wcl);

    const int TPB = 256;
    dim3 wb(32, 8);

    // ---- weight prep (loop-invariant) ----
    k_wsplit<<<dim3(Ee/32,  Ee/32),  wb>>>(w_kv,  wkvTh, wkvTl, Ee,  Ee);
    k_wsplit<<<dim3(Ee/32,  Ee/32),  wb>>>(wq,    wqTh,  wqTl,  Ee,  Ee);
    k_wsplit<<<dim3(Ee/32,  Ee/32),  wb>>>(wk,    wkTh,  wkTl,  Ee,  Ee);
    k_wsplit<<<dim3(Ee/32,  Ee/32),  wb>>>(wv,    wvTh,  wvTl,  Ee,  Ee);
    k_wsplit<<<dim3(Ee/32,  Ee/32),  wb>>>(wo,    woTh,  woTl,  Ee,  Ee);
    k_wsplit<<<dim3(SHh/32, (Ee+Ww)/32), wb>>>(ws1, ws1Th, ws1Tl, Ee+Ww, SHh);
    k_wsplit<<<dim3(Ww/32,  SHh/32), wb>>>(ws2,   ws2Th, ws2Tl, SHh, Ww);
    k_wsplit<<<dim3(Vv/32,  SOo/32), wb>>>(out_w, owTh,  owTl,  SOo, Vv);
    k_split<<<(SAa*Ee + TPB-1)/TPB, TPB>>>(w_qs, wqsh, wqsl, SAa*Ee);
    // combined W^T = wq^T @ wqs^T  -> [E][SA] split
    rung<0,64,1>(wqTh, wqTl, wqsh, wqsl, nullptr, nullptr, Wch, Wcl,
                 Ee, SAa, Ee, 0, 0, SAa);

    // ---- prologue: kv, kh, vh ----
    k_gather<<<(BL*Ee + TPB-1)/TPB, TPB>>>(x, emb, embh, embl);
    rung<0,64,1>(embh, embl, wkvTh, wkvTl, nullptr, nullptr, kvh, kvl, BL, Ee, Ee, 0, 0, Ee);
    rung<0,64,0>(kvh, kvl, wkTh, wkTl, nullptr, tmp, nullptr, nullptr, BL, Ee, Ee, Ee, 1, 0);
    k_rope_split<<<(Bb*Ll*Ee + TPB-1)/TPB, TPB>>>(tmp, kh, Ll, 1);
    rung<0,64,0>(kvh, kvl, wvTh, wvTl, nullptr, tmp, nullptr, nullptr, BL, Ee, Ee, Ee, 1, 0);
    k_rope_split<<<(Bb*Ll*Ee + TPB-1)/TPB, TPB>>>(tmp, vh, Ll, 0);

    k_init<<<(Dd*BQ*Ww + TPB-1)/TPB, TPB>>>(z_init, p_init, z, pah, Na, No, cath, catl);
    k_sync<<<(BQ*SAa + TPB-1)/TPB, TPB>>>(z, Na, sah, sal, idx_la, idx_ra, dec_a, SAa, 1);
    k_sync<<<(BQ*SOo + TPB-1)/TPB, TPB>>>(z, No, soh, sol, idx_lo, idx_ro, dec_o, SOo, 1);

    cudaFuncSetAttribute(k_fattn, cudaFuncAttributeMaxDynamicSharedMemorySize, FA_SMEM);

    // ---- T iterations ----
    for (int t = 0; t < Tt; t++) {
        // q = sa @ (wqs@wq)  -> fp32 tmp -> rope
        rung<0,64,0>(sah, sal, Wch, Wcl, nullptr, tmp, nullptr, nullptr, BQ, Ee, SAa, Ee, 1, 0);
        k_rope_split<<<(Bb*Qq*Ee + TPB-1)/TPB, TPB>>>(tmp, qh, Qq, 1);
        k_fattn<<<dim3(Qq/16, NHh, Bb), 256, FA_SMEM>>>(qh, kh, vh, ctxh, ctxl);
        // attn_out -> cat columns [0,Ee)
        rung<0,64,1>(ctxh, ctxl, woTh, woTl, nullptr, nullptr, cath, catl, BQ, Ee, Ee, 0, 0, Ee+Ww);
        // synapse MLP
        rung<2,64,1>(cath, catl, ws1Th, ws1Tl, bs1, nullptr, h1h, h1l, BQ, SHh, Ee+Ww, 0, 0, SHh);
        rung<1,64,0>(h1h, h1l, ws2Th, ws2Tl, bs2, pah + (long)t*BQ*Ww, nullptr, nullptr,
                     BQ, Ww, SHh, Ww, 1, 0);
        // neuron-level models + sync
        k_nlm<<<dim3(Ww/32, BQ/128), 256>>>(pah, nw1, nb1, nw2, nb2, z, cath, catl, t + 1);
        k_sync<<<(BQ*SAa + TPB-1)/TPB, TPB>>>(z, Na, sah, sal, idx_la, idx_ra, dec_a, SAa, t + 2);
        k_sync<<<(BQ*SOo + TPB-1)/TPB, TPB>>>(z, No, soh, sol, idx_lo, idx_ro, dec_o, SOo, t + 2);
        // logits
        rung<1,128,0>(soh, sol, owTh, owTl, out_b, out + (long)t*BQ*Vv, nullptr, nullptr,
                      BQ, Vv, SOo, Vv, 1, 0);
    }
}

// round 11
// speedup vs baseline: 3.3207x; 1.0791x over previous
#include <cuda_runtime.h>
#include <cuda_bf16.h>
#include <cuda_fp16.h>
#include <math.h>
#include <stdint.h>

// ---- problem constants ----
#define Bb   2
#define Ll   512
#define Qq   512
#define Ee   1024
#define Ww   1024
#define Dd   8
#define Hn   32
#define NHh  16
#define HDd  64
#define SAa  512
#define SOo  1024
#define Vv   8192
#define Tt   6
#define SHh  2048
#define BQ   (Bb*Qq)
#define BL   (Bb*Ll)

typedef __nv_bfloat16 bf;
typedef __half hf;

// ---- fp32 scratch ----
__device__ float g_tmp [BQ*Ee];
__device__ float g_qh  [Bb*NHh*Qq*HDd];
__device__ float g_kh  [Bb*NHh*Ll*HDd];
__device__ float g_vh  [Bb*NHh*Ll*HDd];
__device__ float g_z   [BQ*Ww];
__device__ float g_pah [Dd*BQ*Ww];          // 8 planes of [BQ][Ww]
__device__ float g_Na  [BQ*SAa];
__device__ float g_No  [BQ*SOo];

// ---- bf16 hi/lo activation buffers (3-pass path) ----
__device__ bf g_embh[BL*Ee],        g_embl[BL*Ee];
__device__ bf g_kvh [BL*Ee],        g_kvl [BL*Ee];
__device__ bf g_ctxh[BQ*Ee],        g_ctxl[BQ*Ee];
__device__ bf g_cath[BQ*(Ee+Ww)],   g_catl[BQ*(Ee+Ww)];
__device__ bf g_h1h [BQ*SHh],       g_h1l [BQ*SHh];

// ---- fp16 single activations (2-pass path) ----
__device__ hf g_sa16[BQ*SAa];
__device__ hf g_so16[BQ*SOo];

// ---- bf16 hi/lo weights (transposed [N,K]) for 3-pass ----
__device__ bf g_wkvT_h[Ee*Ee],       g_wkvT_l[Ee*Ee];
__device__ bf g_wkT_h [Ee*Ee],       g_wkT_l [Ee*Ee];
__device__ bf g_wvT_h [Ee*Ee],       g_wvT_l [Ee*Ee];
__device__ bf g_woT_h [Ee*Ee],       g_woT_l [Ee*Ee];
__device__ bf g_ws1T_h[SHh*(Ee+Ww)], g_ws1T_l[SHh*(Ee+Ww)];
__device__ bf g_ws2T_h[Ww*SHh],      g_ws2T_l[Ww*SHh];

// ---- fp16 hi/scaled-lo weights (2-pass) ----
__device__ hf g_wqT16h[Ee*Ee],   g_wqT16l[Ee*Ee];     // only hi used (A of Wc prep)
__device__ hf g_wqs16h[SAa*Ee],  g_wqs16l[SAa*Ee];    // raw [SA][E]
__device__ hf g_Wc16h [Ee*SAa],  g_Wc16l [Ee*SAa];    // combined (wqs@wq)^T
__device__ hf g_ow16h [Vv*SOo],  g_ow16l [Vv*SOo];

__device__ __forceinline__ float gelu_f(float x) {
    float x3 = x*x*x;
    return 0.5f*x*(1.0f + tanhf(0.7978845608028654f*(x + 0.044715f*x3)));
}

// ====================== common mma primitives ======================
__device__ __forceinline__ void cpa16(uint32_t s, const void* g){
    asm volatile("cp.async.cg.shared.global [%0], [%1], 16;" :: "r"(s), "l"(g));
}
__device__ __forceinline__ void cpcommit(){ asm volatile("cp.async.commit_group;" ::: "memory"); }
template<int N> __device__ __forceinline__ void cpwait(){ asm volatile("cp.async.wait_group %0;" :: "n"(N) : "memory"); }
__device__ __forceinline__ void ldmx4(uint32_t* r, uint32_t a){
    asm volatile("ldmatrix.sync.aligned.m8n8.x4.shared.b16 {%0,%1,%2,%3}, [%4];"
        : "=r"(r[0]),"=r"(r[1]),"=r"(r[2]),"=r"(r[3]) : "r"(a));
}
__device__ __forceinline__ void mma_bf16(float* c, const uint32_t* a, uint32_t b0, uint32_t b1){
    asm volatile("mma.sync.aligned.m16n8k16.row.col.f32.bf16.bf16.f32 "
        "{%0,%1,%2,%3}, {%4,%5,%6,%7}, {%8,%9}, {%0,%1,%2,%3};"
        : "+f"(c[0]),"+f"(c[1]),"+f"(c[2]),"+f"(c[3])
        : "r"(a[0]),"r"(a[1]),"r"(a[2]),"r"(a[3]), "r"(b0),"r"(b1));
}
__device__ __forceinline__ void mma_fp16(float* c, const uint32_t* a, uint32_t b0, uint32_t b1){
    asm volatile("mma.sync.aligned.m16n8k16.row.col.f32.f16.f16.f32 "
        "{%0,%1,%2,%3}, {%4,%5,%6,%7}, {%8,%9}, {%0,%1,%2,%3};"
        : "+f"(c[0]),"+f"(c[1]),"+f"(c[2]),"+f"(c[3])
        : "r"(a[0]),"r"(a[1]),"r"(a[2]),"r"(a[3]), "r"(b0),"r"(b1));
}

// ================= bf16 3-pass GEMM (loop + prologue GEMMs) =================
// C(M,N)=epi(A@B^T[+bias]); A,B bf16 hi/lo; B stored [N,K].
template<int EPI, int BM, int OSPLIT>
__global__ void __launch_bounds__(256, (BM==64)?2:1) hgemm(
    const bf* __restrict__ Ah, const bf* __restrict__ Al,
    const bf* __restrict__ Bh, const bf* __restrict__ Bl,
    const float* __restrict__ bias,
    float* __restrict__ C, bf* __restrict__ Ch, bf* __restrict__ Cl,
    int M, int N, int K, long ldcm, long ldcn, long ldh)
{
    constexpr int WMW = BM/32;
    constexpr int WNW = 8/WMW;
    constexpr int WARP_N = 128/WNW;
    constexpr int NJ = WARP_N/8;
    constexpr int TILE_A = BM*40*2;
    constexpr int TILE_Bt = 128*40*2;
    constexpr int STAGE = 2*TILE_A + 2*TILE_Bt;

    extern __shared__ __align__(16) char dyn[];
    const int tid  = threadIdx.x;
    const int wid  = tid >> 5, lane = tid & 31;
    const int bm = blockIdx.y*BM, bn = blockIdx.x*128;
    const int wm = wid % WMW, wn = wid / WMW;

    uint32_t sbase = (uint32_t)__cvta_generic_to_shared(dyn);

    const bf* gAh = Ah + (long)bm*K;
    const bf* gAl = Al + (long)bm*K;
    const bf* gBh = Bh + (long)bn*K;
    const bf* gBl = Bl + (long)bn*K;

    auto load_stage = [&](int st, int k0){
        uint32_t s0 = sbase + st*STAGE;
        #pragma unroll
        for (int c = 0; c < BM/64; ++c) {
            int ch = tid + c*256;
            int row = ch >> 2, seg = ch & 3;
            cpa16(s0 + row*80 + seg*16,          gAh + (long)row*K + k0 + seg*8);
            cpa16(s0 + TILE_A + row*80 + seg*16, gAl + (long)row*K + k0 + seg*8);
        }
        #pragma unroll
        for (int c = 0; c < 2; ++c) {
            int ch = tid + c*256;
            int row = ch >> 2, seg = ch & 3;
            cpa16(s0 + 2*TILE_A + row*80 + seg*16,           gBh + (long)row*K + k0 + seg*8);
            cpa16(s0 + 2*TILE_A + TILE_Bt + row*80 + seg*16, gBl + (long)row*K + k0 + seg*8);
        }
    };

    float acc[2][NJ][4];
    #pragma unroll
    for (int i = 0; i < 2; i++)
        #pragma unroll
        for (int j = 0; j < NJ; j++)
            #pragma unroll
            for (int q = 0; q < 4; q++) acc[i][j][q] = 0.f;

    const int NC = K >> 5;
    load_stage(0, 0); cpcommit();

    const int l = lane & 7, sel = lane >> 3;
    const int rofs = l + ((sel & 1) << 3);
    const int cofs = (sel >> 1) << 3;

    for (int c = 0; c < NC; ++c) {
        if (c + 1 < NC) { load_stage((c+1)&1, (c+1)*32); cpcommit(); cpwait<1>(); }
        else            { cpwait<0>(); }
        __syncthreads();

        uint32_t s0  = sbase + (c&1)*STAGE;
        uint32_t sAh = s0, sAl = s0 + TILE_A, sBh = s0 + 2*TILE_A, sBl = sBh + TILE_Bt;

        #pragma unroll
        for (int k16 = 0; k16 < 2; ++k16) {
            int colo = k16*16 + cofs;
            uint32_t ah[2][4], al[2][4];
            #pragma unroll
            for (int mi = 0; mi < 2; ++mi) {
                uint32_t off = (uint32_t)((wm*32 + mi*16 + rofs)*40 + colo)*2;
                ldmx4(ah[mi], sAh + off);
                ldmx4(al[mi], sAl + off);
            }
            uint32_t bh[NJ/2][4], bl[NJ/2][4];
            #pragma unroll
            for (int ni = 0; ni < NJ/2; ++ni) {
                uint32_t off = (uint32_t)((wn*WARP_N + ni*16 + rofs)*40 + colo)*2;
                ldmx4(bh[ni], sBh + off);
                ldmx4(bl[ni], sBl + off);
            }
            #pragma unroll
            for (int mi = 0; mi < 2; ++mi)
                #pragma unroll
                for (int nj = 0; nj < NJ; ++nj) {
                    int g = nj >> 1, h8 = nj & 1;
                    mma_bf16(acc[mi][nj], ah[mi], bh[g][h8], bh[g][h8+2]);
                    mma_bf16(acc[mi][nj], al[mi], bh[g][h8], bh[g][h8+2]);
                    mma_bf16(acc[mi][nj], ah[mi], bl[g][h8], bl[g][h8+2]);
                }
        }
        __syncthreads();
    }

    const int tr = lane >> 2, tc = (lane & 3)*2;
    #pragma unroll
    for (int mi = 0; mi < 2; ++mi) {
        #pragma unroll
        for (int nj = 0; nj < NJ; ++nj) {
            int m0 = bm + wm*32 + mi*16 + tr;
            int n0 = bn + wn*WARP_N + nj*8 + tc;
            float v[4] = {acc[mi][nj][0], acc[mi][nj][1], acc[mi][nj][2], acc[mi][nj][3]};
            if (EPI >= 1) {
                float b0 = __ldg(bias + n0), b1 = __ldg(bias + n0 + 1);
                v[0] += b0; v[1] += b1; v[2] += b0; v[3] += b1;
            }
            if (EPI == 2) {
                v[0] = gelu_f(v[0]); v[1] = gelu_f(v[1]);
                v[2] = gelu_f(v[2]); v[3] = gelu_f(v[3]);
            }
            if (OSPLIT) {
                #pragma unroll
                for (int rr = 0; rr < 2; ++rr) {
                    long base = (long)(m0 + rr*8)*ldh + n0;
                    bf h0 = __float2bfloat16(v[rr*2+0]);
                    bf h1 = __float2bfloat16(v[rr*2+1]);
                    bf l0 = __float2bfloat16(v[rr*2+0] - __bfloat162float(h0));
                    bf l1 = __float2bfloat16(v[rr*2+1] - __bfloat162float(h1));
                    __nv_bfloat162 hh; hh.x = h0; hh.y = h1;
                    __nv_bfloat162 llv; llv.x = l0; llv.y = l1;
                    *reinterpret_cast<__nv_bfloat162*>(Ch + base) = hh;
                    *reinterpret_cast<__nv_bfloat162*>(Cl + base) = llv;
                }
            } else if (ldcn == 1) {
                *(float2*)(C + (long)m0*ldcm + n0)     = make_float2(v[0], v[1]);
                *(float2*)(C + (long)(m0+8)*ldcm + n0) = make_float2(v[2], v[3]);
            } else {
                C[(long)m0*ldcm     + (long)n0*ldcn]     = v[0];
                C[(long)m0*ldcm     + (long)(n0+1)*ldcn] = v[1];
                C[(long)(m0+8)*ldcm + (long)n0*ldcn]     = v[2];
                C[(long)(m0+8)*ldcm + (long)(n0+1)*ldcn] = v[3];
            }
        }
    }
}

// ================= fp16 2-pass GEMM (q + logits + Wc prep) =================
// A single fp16 [M,K]; B split Bh=fp16(B), Bl=fp16((B-Bh)*1024) stored [N,K].
// Dual fp32 accumulators; C = acc1 + acc2/1024.
// OMODE: 0=fp32 C (+bias opt), 2=fp16 hi/scaled-lo planes, 3=rope->qh layout
#define G2_TILE  10240                       // 128*40*2
#define G2_STAGE (3*G2_TILE)
#define G2_SMEM  (2*G2_STAGE)

template<int EPI, int OMODE>
__global__ void __launch_bounds__(256, 1) hgemm2(
    const hf* __restrict__ A,
    const hf* __restrict__ Bh, const hf* __restrict__ Bl,
    const float* __restrict__ bias,
    float* __restrict__ C, hf* __restrict__ Ch, hf* __restrict__ Cl,
    int M, int N, int K, long ldcm, long ldcn, long ldh)
{
    extern __shared__ __align__(16) char dyn[];
    const int tid  = threadIdx.x;
    const int wid  = tid >> 5, lane = tid & 31;
    const int bm = blockIdx.y*128, bn = blockIdx.x*128;
    const int wm = wid & 3, wn = wid >> 2;    // 4x2 warps, warp tile 32x64

    uint32_t sbase = (uint32_t)__cvta_generic_to_shared(dyn);

    const hf* gA  = A  + (long)bm*K;
    const hf* gBh = Bh + (long)bn*K;
    const hf* gBl = Bl + (long)bn*K;

    auto load_stage = [&](int st, int k0){
        uint32_t s0 = sbase + st*G2_STAGE;
        #pragma unroll
        for (int c = 0; c < 2; ++c) {
            int ch = tid + c*256;
            int row = ch >> 2, seg = ch & 3;
            cpa16(s0 + row*80 + seg*16,             gA  + (long)row*K + k0 + seg*8);
            cpa16(s0 + G2_TILE   + row*80 + seg*16, gBh + (long)row*K + k0 + seg*8);
            cpa16(s0 + 2*G2_TILE + row*80 + seg*16, gBl + (long)row*K + k0 + seg*8);
        }
    };

    float acc1[2][8][4], acc2[2][8][4];
    #pragma unroll
    for (int i = 0; i < 2; i++)
        #pragma unroll
        for (int j = 0; j < 8; j++)
            #pragma unroll
            for (int q = 0; q < 4; q++) { acc1[i][j][q] = 0.f; acc2[i][j][q] = 0.f; }

    const int NC = K >> 5;
    load_stage(0, 0); cpcommit();

    const int l = lane & 7, sel = lane >> 3;
    const int rofs = l + ((sel & 1) << 3);
    const int cofs = (sel >> 1) << 3;

    for (int c = 0; c < NC; ++c) {
        if (c + 1 < NC) { load_stage((c+1)&1, (c+1)*32); cpcommit(); cpwait<1>(); }
        else            { cpwait<0>(); }
        __syncthreads();

        uint32_t s0  = sbase + (c&1)*G2_STAGE;
        uint32_t sA = s0, sBh = s0 + G2_TILE, sBl = s0 + 2*G2_TILE;

        #pragma unroll
        for (int k16 = 0; k16 < 2; ++k16) {
            int colo = k16*16 + cofs;
            uint32_t a[2][4];
            #pragma unroll
            for (int mi = 0; mi < 2; ++mi) {
                uint32_t off = (uint32_t)((wm*32 + mi*16 + rofs)*40 + colo)*2;
                ldmx4(a[mi], sA + off);
            }
            uint32_t bh[4][4], bl[4][4];
            #pragma unroll
            for (int ni = 0; ni < 4; ++ni) {
                uint32_t off = (uint32_t)((wn*64 + ni*16 + rofs)*40 + colo)*2;
                ldmx4(bh[ni], sBh + off);
                ldmx4(bl[ni], sBl + off);
            }
            #pragma unroll
            for (int mi = 0; mi < 2; ++mi)
                #pragma unroll
                for (int nj = 0; nj < 8; ++nj) {
                    int g = nj >> 1, h8 = nj & 1;
                    mma_fp16(acc1[mi][nj], a[mi], bh[g][h8], bh[g][h8+2]);
                    mma_fp16(acc2[mi][nj], a[mi], bl[g][h8], bl[g][h8+2]);
                }
        }
        __syncthreads();
    }

    const float SC = 1.f/1024.f;
    const int tr = lane >> 2, tc = (lane & 3)*2;

    if (OMODE == 3) {
        // rope epilogue -> C = qh[(b*NH+h)*512 + s][64]
        #pragma unroll
        for (int mi = 0; mi < 2; ++mi)
            #pragma unroll
            for (int njl = 0; njl < 4; ++njl) {
                float vlo[4], vhi[4];
                #pragma unroll
                for (int q = 0; q < 4; ++q) {
                    vlo[q] = acc1[mi][njl][q]   + acc2[mi][njl][q]*SC;
                    vhi[q] = acc1[mi][njl+4][q] + acc2[mi][njl+4][q]*SC;
                }
                #pragma unroll
                for (int r = 0; r < 2; ++r)
                    #pragma unroll
                    for (int cc = 0; cc < 2; ++cc) {
                        int m = bm + wm*32 + mi*16 + tr + r*8;
                        int s = m & 511, bb = m >> 9;
                        int hh = (bn + wn*64) >> 6;
                        int j = njl*8 + tc + cc;
                        float inv = expf(-(float)j * (9.210340371976184f/32.f));
                        float ang = (float)s * inv;
                        float sn, cs;
                        sincosf(ang, &sn, &cs);
                        float x1 = vlo[r*2+cc], x2 = vhi[r*2+cc];
                        long base = (((long)(bb*NHh + hh))*512 + s)*64;
                        C[base + j]      = x1*cs - x2*sn;
                        C[base + j + 32] = x2*cs + x1*sn;
                    }
            }
        return;
    }

    #pragma unroll
    for (int mi = 0; mi < 2; ++mi) {
        #pragma unroll
        for (int nj = 0; nj < 8; ++nj) {
            int m0 = bm + wm*32 + mi*16 + tr;
            int n0 = bn + wn*64 + nj*8 + tc;
            float v[4];
            #pragma unroll
            for (int q = 0; q < 4; ++q) v[q] = acc1[mi][nj][q] + acc2[mi][nj][q]*SC;
            if (EPI >= 1) {
                float b0 = __ldg(bias + n0), b1 = __ldg(bias + n0 + 1);
                v[0] += b0; v[1] += b1; v[2] += b0; v[3] += b1;
            }
            if (OMODE == 2) {
                #pragma unroll
                for (int rr = 0; rr < 2; ++rr) {
                    long base = (long)(m0 + rr*8)*ldh + n0;
                    hf h0 = __float2half(v[rr*2+0]);
                    hf h1 = __float2half(v[rr*2+1]);
                    hf l0 = __float2half((v[rr*2+0] - __half2float(h0))*1024.f);
                    hf l1 = __float2half((v[rr*2+1] - __half2float(h1))*1024.f);
                    __half2 hh; hh.x = h0; hh.y = h1;
                    __half2 llv; llv.x = l0; llv.y = l1;
                    *reinterpret_cast<__half2*>(Ch + base) = hh;
                    *reinterpret_cast<__half2*>(Cl + base) = llv;
                }
            } else if (ldcn == 1) {
                *(float2*)(C + (long)m0*ldcm + n0)     = make_float2(v[0], v[1]);
                *(float2*)(C + (long)(m0+8)*ldcm + n0) = make_float2(v[2], v[3]);
            } else {
                C[(long)m0*ldcm     + (long)n0*ldcn]     = v[0];
                C[(long)m0*ldcm     + (long)(n0+1)*ldcn] = v[1];
                C[(long)(m0+8)*ldcm + (long)n0*ldcn]     = v[2];
                C[(long)(m0+8)*ldcm + (long)(n0+1)*ldcn] = v[3];
            }
        }
    }
}

// ======================= flash attention =======================
#define FA_QS   0
#define FA_KC   (16*68)
#define FA_SC   (FA_KC + 64*68)
#define FA_FLT  (FA_SC + 16*512)
#define FA_SMEM (FA_FLT*4)

__global__ void __launch_bounds__(256) k_fattn(
    const float* __restrict__ qh, const float* __restrict__ kh,
    const float* __restrict__ vh, bf* __restrict__ ctxh, bf* __restrict__ ctxl)
{
    extern __shared__ __align__(16) float sm[];
    float* qs = sm + FA_QS;
    float* kc = sm + FA_KC;
    float* sc = sm + FA_SC;

    const int tid = threadIdx.x;
    const int q0 = blockIdx.x*16, h = blockIdx.y, b = blockIdx.z;
    const int qi = tid >> 4, tsub = tid & 15;

    const float* Qb = qh + ((long)(b*NHh + h)*Qq + q0)*HDd;
    const float* Kb = kh + ((long)(b*NHh + h)*Ll)*HDd;
    const float* Vb = vh + ((long)(b*NHh + h)*Ll)*HDd;

    {
        int row = tid >> 4, d = (tid & 15)*4;
        *(float4*)(qs + row*68 + d) = *(const float4*)(Qb + row*HDd + d);
    }

    const int NCv = (q0 + 15)/64 + 1;
    const int KLIM = NCv*64;
    const int qg = q0 + qi;

    for (int c = 0; c < NCv; ++c) {
        __syncthreads();
        for (int j = tid; j < 1024; j += 256) {
            int row = j >> 4, d = (j & 15)*4;
            *(float4*)(kc + row*68 + d) = *(const float4*)(Kb + (long)(c*64 + row)*HDd + d);
        }
        __syncthreads();
        #pragma unroll
        for (int jk = 0; jk < 4; ++jk) {
            int kl = jk*16 + tsub;
            int kg = c*64 + kl;
            float s = -1e30f;
            if (kg <= qg) {
                float4 acc4 = make_float4(0.f,0.f,0.f,0.f);
                #pragma unroll
                for (int d = 0; d < HDd; d += 4) {
                    float4 qv = *(float4*)(qs + qi*68 + d);
                    float4 kv4 = *(float4*)(kc + kl*68 + d);
                    acc4.x += qv.x*kv4.x; acc4.y += qv.y*kv4.y;
                    acc4.z += qv.z*kv4.z; acc4.w += qv.w*kv4.w;
                }
                s = (acc4.x + acc4.y + acc4.z + acc4.w) * 0.125f;
            }
            sc[qi*512 + kg] = s;
        }
    }
    __syncthreads();

    float m = -1e30f;
    for (int k = tsub; k < KLIM; k += 16) m = fmaxf(m, sc[qi*512 + k]);
    #pragma unroll
    for (int o = 8; o > 0; o >>= 1) m = fmaxf(m, __shfl_xor_sync(0xffffffffu, m, o, 16));
    float sum = 0.f;
    for (int k = tsub; k < KLIM; k += 16) {
        float e = expf(sc[qi*512 + k] - m);
        sc[qi*512 + k] = e;
        sum += e;
    }
    #pragma unroll
    for (int o = 8; o > 0; o >>= 1) sum += __shfl_xor_sync(0xffffffffu, sum, o, 16);
    const float inv = 1.f / sum;

    float a0 = 0.f, a1 = 0.f, a2 = 0.f, a3 = 0.f;
    const int d0 = tsub*4;
    for (int c = 0; c < NCv; ++c) {
        __syncthreads();
        for (int j = tid; j < 1024; j += 256) {
            int row = j >> 4, d = (j & 15)*4;
            *(float4*)(kc + row*68 + d) = *(const float4*)(Vb + (long)(c*64 + row)*HDd + d);
        }
        __syncthreads();
        #pragma unroll 8
        for (int k = 0; k < 64; ++k) {
            float p = sc[qi*512 + c*64 + k];
            float4 vv = *(float4*)(kc + k*68 + d0);
            a0 += p*vv.x; a1 += p*vv.y; a2 += p*vv.z; a3 += p*vv.w;
        }
    }

    a0 *= inv; a1 *= inv; a2 *= inv; a3 *= inv;
    long base = (long)(b*Qq + q0 + qi)*Ee + h*HDd + d0;
    float v[4] = {a0, a1, a2, a3};
    #pragma unroll
    for (int rr = 0; rr < 2; ++rr) {
        bf h0 = __float2bfloat16(v[rr*2+0]);
        bf h1 = __float2bfloat16(v[rr*2+1]);
        bf l0 = __float2bfloat16(v[rr*2+0] - __bfloat162float(h0));
        bf l1 = __float2bfloat16(v[rr*2+1] - __bfloat162float(h1));
        __nv_bfloat162 hh; hh.x = h0; hh.y = h1;
        __nv_bfloat162 llv; llv.x = l0; llv.y = l1;
        *reinterpret_cast<__nv_bfloat162*>(ctxh + base + rr*2) = hh;
        *reinterpret_cast<__nv_bfloat162*>(ctxl + base + rr*2) = llv;
    }
}

// ======================= small kernels =======================
__global__ void k_wsplit(const float* __restrict__ w, bf* __restrict__ hi,
                         bf* __restrict__ lo, int K, int N) {
    __shared__ float t[32][33];
    int k0 = blockIdx.y*32, n0 = blockIdx.x*32;
    for (int r = threadIdx.y; r < 32; r += 8)
        t[r][threadIdx.x] = w[(long)(k0+r)*N + n0 + threadIdx.x];
    __syncthreads();
    for (int r = threadIdx.y; r < 32; r += 8) {
        float v = t[threadIdx.x][r];
        bf h = __float2bfloat16(v);
        long o = (long)(n0+r)*K + k0 + threadIdx.x;
        hi[o] = h;
        lo[o] = __float2bfloat16(v - __bfloat162float(h));
    }
}

// fp16 transpose-split: hi = fp16(v), lo = fp16((v-hi)*1024)
__global__ void k_wsplit16(const float* __restrict__ w, hf* __restrict__ hi,
                           hf* __restrict__ lo, int K, int N) {
    __shared__ float t[32][33];
    int k0 = blockIdx.y*32, n0 = blockIdx.x*32;
    for (int r = threadIdx.y; r < 32; r += 8)
        t[r][threadIdx.x] = w[(long)(k0+r)*N + n0 + threadIdx.x];
    __syncthreads();
    for (int r = threadIdx.y; r < 32; r += 8) {
        float v = t[threadIdx.x][r];
        hf h = __float2half(v);
        long o = (long)(n0+r)*K + k0 + threadIdx.x;
        hi[o] = h;
        lo[o] = __float2half((v - __half2float(h))*1024.f);
    }
}

__global__ void k_split16(const float* __restrict__ in, hf* __restrict__ hi,
                          hf* __restrict__ lo, int n) {
    int i = blockIdx.x*blockDim.x + threadIdx.x;
    if (i >= n) return;
    float v = in[i];
    hf h = __float2half(v);
    hi[i] = h;
    lo[i] = __float2half((v - __half2float(h))*1024.f);
}

__global__ void k_gather(const int* __restrict__ x, const float* __restrict__ emb,
                         bf* __restrict__ hi, bf* __restrict__ lo) {
    int i = blockIdx.x*blockDim.x + threadIdx.x;
    if (i >= BL*Ee) return;
    int e = i % Ee, bl = i / Ee;
    float v = emb[(long)x[bl]*Ee + e];
    bf h = __float2bfloat16(v);
    hi[i] = h;
    lo[i] = __float2bfloat16(v - __bfloat162float(h));
}

__global__ void k_init(const float* __restrict__ z0, const float* __restrict__ p0,
                       float* __restrict__ z, float* __restrict__ pah,
                       float* __restrict__ Na, float* __restrict__ No,
                       bf* __restrict__ cath, bf* __restrict__ catl) {
    int i = blockIdx.x*blockDim.x + threadIdx.x;
    if (i < Dd*BQ*Ww) {
        int d = i / (BQ*Ww);
        int w = i % Ww;
        pah[i] = p0[w*Dd + d];
    }
    if (i < BQ*Ww) {
        int w = i % Ww, bq = i / Ww;
        float v = z0[w];
        z[i] = v;
        bf h = __float2bfloat16(v);
        cath[(long)bq*(Ee+Ww) + Ee + w] = h;
        catl[(long)bq*(Ee+Ww) + Ee + w] = __float2bfloat16(v - __bfloat162float(h));
    }
    if (i < BQ*SAa) Na[i] = 0.f;
    if (i < BQ*SOo) No[i] = 0.f;
}

__global__ void k_rope_split(const float* __restrict__ in, float* __restrict__ out,
                             int S, int do_rope) {
    int i = blockIdx.x*blockDim.x + threadIdx.x;
    if (i >= Bb*S*Ee) return;
    int d = i % HDd;
    int h = (i / HDd) % NHh;
    int s = (i / Ee) % S;
    int b = i / (Ee*S);
    const float* row = in + ((long)(b*S + s))*Ee + h*HDd;
    float v;
    if (do_rope) {
        const int half = HDd/2;
        int j = d % half;
        float inv = expf(-(float)j * (9.210340371976184f / (float)half));
        float ang = (float)s * inv;
        float c = cosf(ang), sn = sinf(ang);
        float x1 = row[j], x2 = row[j + half];
        v = (d < half) ? (x1*c - x2*sn) : (x2*c + x1*sn);
    } else {
        v = row[d];
    }
    out[(((long)(b*NHh + h))*S + s)*HDd + d] = v;
}

__global__ void __launch_bounds__(256) k_nlm(
    const float* __restrict__ pah, const float* __restrict__ w1,
    const float* __restrict__ b1, const float* __restrict__ w2,
    const float* __restrict__ b2, float* __restrict__ z,
    bf* __restrict__ cath, bf* __restrict__ catl, int start)
{
    __shared__ float w1s[32*257];
    __shared__ float b1s[32*33];
    __shared__ float w2s[32*33];
    __shared__ float b2s[32];
    const int tid = threadIdx.x;
    const int w0 = blockIdx.x*32, bq0 = blockIdx.y*128;

    for (int j = tid; j < 32*256; j += 256) w1s[(j>>8)*257 + (j&255)] = w1[(long)w0*256 + j];
    for (int j = tid; j < 32*32;  j += 256) {
        b1s[(j>>5)*33 + (j&31)] = b1[(long)w0*32 + j];
        w2s[(j>>5)*33 + (j&31)] = w2[(long)w0*32 + j];
    }
    if (tid < 32) b2s[tid] = b2[w0 + tid];
    __syncthreads();

    const int wl = tid & 31, bql = tid >> 5;
    const int w = w0 + wl;
    for (int bq = bq0 + bql; bq < bq0 + 128; bq += 8) {
        float pv[Dd];
        #pragma unroll
        for (int d = 0; d < Dd; d++)
            pv[d] = pah[(long)((start + d) & 7)*BQ*Ww + (long)bq*Ww + w];
        float zacc = b2s[wl];
        #pragma unroll
        for (int hh = 0; hh < Hn; hh++) {
            float a = b1s[wl*33 + hh];
            #pragma unroll
            for (int d = 0; d < Dd; d++) a += pv[d]*w1s[wl*257 + d*32 + hh];
            zacc += gelu_f(a)*w2s[wl*33 + hh];
        }
        z[(long)bq*Ww + w] = zacc;
        bf h = __float2bfloat16(zacc);
        cath[(long)bq*(Ee+Ww) + Ee + w] = h;
        catl[(long)bq*(Ee+Ww) + Ee + w] = __float2bfloat16(zacc - __bfloat162float(h));
    }
}

// incremental sync -> single fp16 output
__global__ void k_sync(const float* __restrict__ z, float* __restrict__ Nbuf,
                       hf* __restrict__ syn,
                       const int* __restrict__ il, const int* __restrict__ ir,
                       const float* __restrict__ dec, int S, int Tn) {
    int i = blockIdx.x*blockDim.x + threadIdx.x;
    if (i >= BQ*S) return;
    int s = i % S, bq = i / S;
    float d  = dec[s];
    float ed = expf(-d);
    const float* zr = z + (long)bq*Ww;
    float p  = zr[il[s]]*zr[ir[s]];
    float Nn = Nbuf[i]*ed + p;
    Nbuf[i] = Nn;
    float den = 0.f, wgt = 1.f;
    for (int k = 0; k < Tn; k++) { den += wgt; wgt *= ed; }
    syn[i] = __float2half(Nn / sqrtf(den));
}

// ======================= host =======================
static void* symv(const void* s) { void* p = nullptr; cudaGetSymbolAddress(&p, s); return p; }

template<int EPI, int BM, int OSPLIT>
static void rung(const bf* Ah, const bf* Al, const bf* Bh, const bf* Bl,
                 const float* bias, float* C, bf* Ch, bf* Cl,
                 int M, int N, int K, long ldcm, long ldcn, long ldh) {
    constexpr int SM = 2*(2*BM*40*2 + 2*10240);
    cudaFuncSetAttribute(hgemm<EPI,BM,OSPLIT>, cudaFuncAttributeMaxDynamicSharedMemorySize, SM);
    dim3 g(N/128, M/BM);
    hgemm<EPI,BM,OSPLIT><<<g, 256, SM>>>(Ah, Al, Bh, Bl, bias, C, Ch, Cl, M, N, K, ldcm, ldcn, ldh);
}

template<int EPI, int OMODE>
static void rung2(const hf* A, const hf* Bh, const hf* Bl,
                  const float* bias, float* C, hf* Ch, hf* Cl,
                  int M, int N, int K, long ldcm, long ldcn, long ldh) {
    cudaFuncSetAttribute(hgemm2<EPI,OMODE>, cudaFuncAttributeMaxDynamicSharedMemorySize, G2_SMEM);
    dim3 g(N/128, M/128);
    hgemm2<EPI,OMODE><<<g, 256, G2_SMEM>>>(A, Bh, Bl, bias, C, Ch, Cl, M, N, K, ldcm, ldcn, ldh);
}

extern "C" void kernel_launch(void* const* d_in, const int* in_sizes, int n_in,
                              void* d_out, int out_size) {
    (void)in_sizes; (void)n_in; (void)out_size;
    const int*   x      = (const int*)  d_in[0];
    const float* emb    = (const float*)d_in[2];
    const float* w_kv   = (const float*)d_in[3];
    const float* w_qs   = (const float*)d_in[4];
    const float* wq     = (const float*)d_in[5];
    const float* wk     = (const float*)d_in[6];
    const float* wv     = (const float*)d_in[7];
    const float* wo     = (const float*)d_in[8];
    const float* ws1    = (const float*)d_in[9];
    const float* bs1    = (const float*)d_in[10];
    const float* ws2    = (const float*)d_in[11];
    const float* bs2    = (const float*)d_in[12];
    const float* nw1    = (const float*)d_in[13];
    const float* nb1    = (const float*)d_in[14];
    const float* nw2    = (const float*)d_in[15];
    const float* nb2    = (const float*)d_in[16];
    const float* out_w  = (const float*)d_in[17];
    const float* out_b  = (const float*)d_in[18];
    const float* z_init = (const float*)d_in[19];
    const float* p_init = (const float*)d_in[20];
    const float* dec_a  = (const float*)d_in[21];
    const float* dec_o  = (const float*)d_in[22];
    const int*   idx_la = (const int*)  d_in[23];
    const int*   idx_ra = (const int*)  d_in[24];
    const int*   idx_lo = (const int*)  d_in[25];
    const int*   idx_ro = (const int*)  d_in[26];
    float* out = (float*)d_out;

    float *tmp = (float*)symv(g_tmp);
    float *qh = (float*)symv(g_qh), *kh = (float*)symv(g_kh), *vh = (float*)symv(g_vh);
    float *z = (float*)symv(g_z), *pah = (float*)symv(g_pah);
    float *Na = (float*)symv(g_Na), *No = (float*)symv(g_No);

    bf *embh=(bf*)symv(g_embh), *embl=(bf*)symv(g_embl);
    bf *kvh=(bf*)symv(g_kvh),   *kvl=(bf*)symv(g_kvl);
    bf *ctxh=(bf*)symv(g_ctxh), *ctxl=(bf*)symv(g_ctxl);
    bf *cath=(bf*)symv(g_cath), *catl=(bf*)symv(g_catl);
    bf *h1h=(bf*)symv(g_h1h),   *h1l=(bf*)symv(g_h1l);
    hf *sa16=(hf*)symv(g_sa16), *so16=(hf*)symv(g_so16);

    bf *wkvTh=(bf*)symv(g_wkvT_h), *wkvTl=(bf*)symv(g_wkvT_l);
    bf *wkTh =(bf*)symv(g_wkT_h),  *wkTl =(bf*)symv(g_wkT_l);
    bf *wvTh =(bf*)symv(g_wvT_h),  *wvTl =(bf*)symv(g_wvT_l);
    bf *woTh =(bf*)symv(g_woT_h),  *woTl =(bf*)symv(g_woT_l);
    bf *ws1Th=(bf*)symv(g_ws1T_h), *ws1Tl=(bf*)symv(g_ws1T_l);
    bf *ws2Th=(bf*)symv(g_ws2T_h), *ws2Tl=(bf*)symv(g_ws2T_l);

    hf *wqT16h=(hf*)symv(g_wqT16h), *wqT16l=(hf*)symv(g_wqT16l);
    hf *wqs16h=(hf*)symv(g_wqs16h), *wqs16l=(hf*)symv(g_wqs16l);
    hf *Wc16h =(hf*)symv(g_Wc16h),  *Wc16l =(hf*)symv(g_Wc16l);
    hf *ow16h =(hf*)symv(g_ow16h),  *ow16l =(hf*)symv(g_ow16l);

    const int TPB = 256;
    dim3 wb(32, 8);

    // ---- weight prep (loop-invariant) ----
    k_wsplit<<<dim3(Ee/32,  Ee/32),  wb>>>(w_kv,  wkvTh, wkvTl, Ee,  Ee);
    k_wsplit<<<dim3(Ee/32,  Ee/32),  wb>>>(wk,    wkTh,  wkTl,  Ee,  Ee);
    k_wsplit<<<dim3(Ee/32,  Ee/32),  wb>>>(wv,    wvTh,  wvTl,  Ee,  Ee);
    k_wsplit<<<dim3(Ee/32,  Ee/32),  wb>>>(wo,    woTh,  woTl,  Ee,  Ee);
    k_wsplit<<<dim3(SHh/32, (Ee+Ww)/32), wb>>>(ws1, ws1Th, ws1Tl, Ee+Ww, SHh);
    k_wsplit<<<dim3(Ww/32,  SHh/32), wb>>>(ws2,   ws2Th, ws2Tl, SHh, Ww);
    k_wsplit16<<<dim3(Ee/32, Ee/32), wb>>>(wq,    wqT16h, wqT16l, Ee, Ee);
    k_wsplit16<<<dim3(Vv/32, SOo/32), wb>>>(out_w, ow16h, ow16l, SOo, Vv);
    k_split16<<<(SAa*Ee + TPB-1)/TPB, TPB>>>(w_qs, wqs16h, wqs16l, SAa*Ee);
    // combined W^T = wq^T @ wqs^T -> [E][SA] fp16 split
    rung2<0,2>(wqT16h, wqs16h, wqs16l, nullptr, nullptr, Wc16h, Wc16l,
               Ee, SAa, Ee, 0, 0, SAa);

    // ---- prologue: kv, kh, vh (bf16 3-pass, full precision path) ----
    k_gather<<<(BL*Ee + TPB-1)/TPB, TPB>>>(x, emb, embh, embl);
    rung<0,64,1>(embh, embl, wkvTh, wkvTl, nullptr, nullptr, kvh, kvl, BL, Ee, Ee, 0, 0, Ee);
    rung<0,64,0>(kvh, kvl, wkTh, wkTl, nullptr, tmp, nullptr, nullptr, BL, Ee, Ee, Ee, 1, 0);
    k_rope_split<<<(Bb*Ll*Ee + TPB-1)/TPB, TPB>>>(tmp, kh, Ll, 1);
    rung<0,64,0>(kvh, kvl, wvTh, wvTl, nullptr, tmp, nullptr, nullptr, BL, Ee, Ee, Ee, 1, 0);
    k_rope_split<<<(Bb*Ll*Ee + TPB-1)/TPB, TPB>>>(tmp, vh, Ll, 0);

    k_init<<<(Dd*BQ*Ww + TPB-1)/TPB, TPB>>>(z_init, p_init, z, pah, Na, No, cath, catl);
    k_sync<<<(BQ*SAa + TPB-1)/TPB, TPB>>>(z, Na, sa16, idx_la, idx_ra, dec_a, SAa, 1);
    k_sync<<<(BQ*SOo + TPB-1)/TPB, TPB>>>(z, No, so16, idx_lo, idx_ro, dec_o, SOo, 1);

    cudaFuncSetAttribute(k_fattn, cudaFuncAttributeMaxDynamicSharedMemorySize, FA_SMEM);

    // ---- T iterations ----
    for (int t = 0; t < Tt; t++) {
        // q = sa @ (wqs@wq), rope fused in epilogue -> qh
        rung2<0,3>(sa16, Wc16h, Wc16l, nullptr, qh, nullptr, nullptr,
                   BQ, Ee, SAa, 0, 0, 0);
        k_fattn<<<dim3(Qq/16, NHh, Bb), 256, FA_SMEM>>>(qh, kh, vh, ctxh, ctxl);
        // attn_out -> cat columns [0,Ee)  (bf16 3-pass)
        rung<0,64,1>(ctxh, ctxl, woTh, woTl, nullptr, nullptr, cath, catl, BQ, Ee, Ee, 0, 0, Ee+Ww);
        // synapse MLP (bf16 3-pass)
        rung<2,64,1>(cath, catl, ws1Th, ws1Tl, bs1, nullptr, h1h, h1l, BQ, SHh, Ee+Ww, 0, 0, SHh);
        rung<1,64,0>(h1h, h1l, ws2Th, ws2Tl, bs2, pah + (long)t*BQ*Ww, nullptr, nullptr,
                     BQ, Ww, SHh, Ww, 1, 0);
        // neuron-level models + sync
        k_nlm<<<dim3(Ww/32, BQ/128), 256>>>(pah, nw1, nb1, nw2, nb2, z, cath, catl, t + 1);
        k_sync<<<(BQ*SAa + TPB-1)/TPB, TPB>>>(z, Na, sa16, idx_la, idx_ra, dec_a, SAa, t + 2);
        k_sync<<<(BQ*SOo + TPB-1)/TPB, TPB>>>(z, No, so16, idx_lo, idx_ro, dec_o, SOo, t + 2);
        // logits (fp16 2-pass)
        rung2<1,0>(so16, ow16h, ow16l, out_b, out + (long)t*BQ*Vv, nullptr, nullptr,
                   BQ, Vv, SOo, Vv, 1, 0);
    }
}

// round 13
// speedup vs baseline: 3.6035x; 1.0852x over previous
#include <cuda_runtime.h>
#include <cuda_bf16.h>
#include <cuda_fp16.h>
#include <math.h>
#include <stdint.h>

// ---- problem constants ----
#define Bb   2
#define Ll   512
#define Qq   512
#define Ee   1024
#define Ww   1024
#define Dd   8
#define Hn   32
#define NHh  16
#define HDd  64
#define SAa  512
#define SOo  1024
#define Vv   8192
#define Tt   6
#define SHh  2048
#define BQ   (Bb*Qq)
#define BL   (Bb*Ll)

typedef __half hf;

// ---- fp32 scratch ----
__device__ float g_tmp [BQ*Ee];
__device__ float g_qh  [Bb*NHh*Qq*HDd];
__device__ float g_kh  [Bb*NHh*Ll*HDd];
__device__ float g_vh  [Bb*NHh*Ll*HDd];
__device__ float g_z   [BQ*Ww];
__device__ float g_pah [Dd*BQ*Ww];          // 8 planes of [BQ][Ww]
__device__ float g_Na  [BQ*SAa];
__device__ float g_No  [BQ*SOo];

// ---- fp16 single activations ----
__device__ hf g_emb16[BL*Ee];
__device__ hf g_kv16 [BL*Ee];
__device__ hf g_ctx16[BQ*Ee];
__device__ hf g_cat16[BQ*(Ee+Ww)];
__device__ hf g_h116 [BQ*SHh];
__device__ hf g_sa16 [BQ*SAa];
__device__ hf g_so16 [BQ*SOo];

// ---- fp16 hi/scaled-lo weights (transposed [N,K]) ----
__device__ hf g_wkvTh[Ee*Ee],       g_wkvTl[Ee*Ee];
__device__ hf g_wkTh [Ee*Ee],       g_wkTl [Ee*Ee];
__device__ hf g_wvTh [Ee*Ee],       g_wvTl [Ee*Ee];
__device__ hf g_woTh [Ee*Ee],       g_woTl [Ee*Ee];
__device__ hf g_ws1Th[SHh*(Ee+Ww)], g_ws1Tl[SHh*(Ee+Ww)];
__device__ hf g_ws2Th[Ww*SHh],      g_ws2Tl[Ww*SHh];
__device__ hf g_owTh [Vv*SOo],      g_owTl [Vv*SOo];
__device__ hf g_wqTh [Ee*Ee],       g_wqTl [Ee*Ee];
__device__ hf g_wqs16h[SAa*Ee],     g_wqs16l[SAa*Ee];
__device__ hf g_Wch  [Ee*SAa],      g_Wcl  [Ee*SAa];

__device__ __forceinline__ float gelu_f(float x) {
    float x3 = x*x*x;
    return 0.5f*x*(1.0f + tanhf(0.7978845608028654f*(x + 0.044715f*x3)));
}

// ====================== mma primitives ======================
__device__ __forceinline__ void cpa16(uint32_t s, const void* g){
    asm volatile("cp.async.cg.shared.global [%0], [%1], 16;" :: "r"(s), "l"(g));
}
__device__ __forceinline__ void cpcommit(){ asm volatile("cp.async.commit_group;" ::: "memory"); }
template<int N> __device__ __forceinline__ void cpwait(){ asm volatile("cp.async.wait_group %0;" :: "n"(N) : "memory"); }
__device__ __forceinline__ void ldmx4(uint32_t* r, uint32_t a){
    asm volatile("ldmatrix.sync.aligned.m8n8.x4.shared.b16 {%0,%1,%2,%3}, [%4];"
        : "=r"(r[0]),"=r"(r[1]),"=r"(r[2]),"=r"(r[3]) : "r"(a));
}
__device__ __forceinline__ void mma_fp16(float* c, const uint32_t* a, uint32_t b0, uint32_t b1){
    asm volatile("mma.sync.aligned.m16n8k16.row.col.f32.f16.f16.f32 "
        "{%0,%1,%2,%3}, {%4,%5,%6,%7}, {%8,%9}, {%0,%1,%2,%3};"
        : "+f"(c[0]),"+f"(c[1]),"+f"(c[2]),"+f"(c[3])
        : "r"(a[0]),"r"(a[1]),"r"(a[2]),"r"(a[3]), "r"(b0),"r"(b1));
}

// ============ unified fp16 2-pass GEMM, 3-stage cp.async ============
// C(M,N) = epi(A @ B^T [+bias]); A fp16 [M,K]; Bh=fp16(B), Bl=fp16((B-Bh)*1024), [N,K].
// Dual fp32 accumulators; result = acc1 + acc2/1024.
// EPI: 0 none, 1 +bias, 2 gelu(+bias)
// OMODE: 0 fp32 C (ldcm/ldcn), 1 fp16 single out (ldh), 2 fp16 hi/scaled-lo (ldh), 3 rope->qh
template<int EPI, int BM, int OMODE>
__global__ void __launch_bounds__(256, (BM==64)?2:1) hg(
    const hf* __restrict__ A,
    const hf* __restrict__ Bh, const hf* __restrict__ Bl,
    const float* __restrict__ bias,
    float* __restrict__ C, hf* __restrict__ Ch, hf* __restrict__ Cl,
    int M, int N, int K, long ldcm, long ldcn, long ldh)
{
    constexpr int WMW = BM/32;            // warps along M
    constexpr int WNW = 8/WMW;
    constexpr int WARP_N = 128/WNW;
    constexpr int NJ = WARP_N/8;
    constexpr int TILE_A = BM*80;         // bytes
    constexpr int TILE_B = 128*80;
    constexpr int STAGE = TILE_A + 2*TILE_B;

    extern __shared__ __align__(16) char dyn[];
    const int tid  = threadIdx.x;
    const int wid  = tid >> 5, lane = tid & 31;
    const int bm = blockIdx.y*BM, bn = blockIdx.x*128;
    const int wm = wid % WMW, wn = wid / WMW;

    uint32_t sbase = (uint32_t)__cvta_generic_to_shared(dyn);

    const hf* gA  = A  + (long)bm*K;
    const hf* gBh = Bh + (long)bn*K;
    const hf* gBl = Bl + (long)bn*K;

    auto load_stage = [&](int st, int k0){
        uint32_t s0 = sbase + st*STAGE;
        #pragma unroll
        for (int c = 0; c < BM/64; ++c) {
            int ch = tid + c*256;
            int row = ch >> 2, seg = ch & 3;
            cpa16(s0 + row*80 + seg*16, gA + (long)row*K + k0 + seg*8);
        }
        #pragma unroll
        for (int c = 0; c < 2; ++c) {
            int ch = tid + c*256;
            int row = ch >> 2, seg = ch & 3;
            cpa16(s0 + TILE_A + row*80 + seg*16,          gBh + (long)row*K + k0 + seg*8);
            cpa16(s0 + TILE_A + TILE_B + row*80 + seg*16, gBl + (long)row*K + k0 + seg*8);
        }
    };

    float acc1[2][NJ][4], acc2[2][NJ][4];
    #pragma unroll
    for (int i = 0; i < 2; i++)
        #pragma unroll
        for (int j = 0; j < NJ; j++)
            #pragma unroll
            for (int q = 0; q < 4; q++) { acc1[i][j][q] = 0.f; acc2[i][j][q] = 0.f; }

    const int NC = K >> 5;
    load_stage(0, 0); cpcommit();
    if (NC > 1) { load_stage(1, 32); cpcommit(); }

    const int l = lane & 7, sel = lane >> 3;
    const int rofs = l + ((sel & 1) << 3);
    const int cofs = (sel >> 1) << 3;

    for (int c = 0; c < NC; ++c) {
        if (c + 2 < NC) { load_stage((c+2)%3, (c+2)*32); cpcommit(); cpwait<2>(); }
        else if (c + 1 < NC) cpwait<1>();
        else cpwait<0>();
        __syncthreads();

        uint32_t s0  = sbase + (c%3)*STAGE;
        uint32_t sA = s0, sBh = s0 + TILE_A, sBl = sBh + TILE_B;

        #pragma unroll
        for (int k16 = 0; k16 < 2; ++k16) {
            int colo = k16*16 + cofs;
            uint32_t a[2][4];
            #pragma unroll
            for (int mi = 0; mi < 2; ++mi) {
                uint32_t off = (uint32_t)((wm*32 + mi*16 + rofs)*40 + colo)*2;
                ldmx4(a[mi], sA + off);
            }
            uint32_t bhf[NJ/2][4], blf[NJ/2][4];
            #pragma unroll
            for (int ni = 0; ni < NJ/2; ++ni) {
                uint32_t off = (uint32_t)((wn*WARP_N + ni*16 + rofs)*40 + colo)*2;
                ldmx4(bhf[ni], sBh + off);
                ldmx4(blf[ni], sBl + off);
            }
            #pragma unroll
            for (int mi = 0; mi < 2; ++mi)
                #pragma unroll
                for (int nj = 0; nj < NJ; ++nj) {
                    int g = nj >> 1, h8 = nj & 1;
                    mma_fp16(acc1[mi][nj], a[mi], bhf[g][h8], bhf[g][h8+2]);
                    mma_fp16(acc2[mi][nj], a[mi], blf[g][h8], blf[g][h8+2]);
                }
        }
        __syncthreads();
    }

    const float SC = 1.f/1024.f;
    const int tr = lane >> 2, tc = (lane & 3)*2;

    if (OMODE == 3) {
        // rope epilogue -> qh[(b*NH+h)*512 + s][64]; requires BM=128 (WARP_N=64)
        #pragma unroll
        for (int mi = 0; mi < 2; ++mi)
            #pragma unroll
            for (int njl = 0; njl < NJ/2; ++njl) {
                float vlo[4], vhi[4];
                #pragma unroll
                for (int q = 0; q < 4; ++q) {
                    vlo[q] = acc1[mi][njl][q]        + acc2[mi][njl][q]*SC;
                    vhi[q] = acc1[mi][njl+NJ/2][q]   + acc2[mi][njl+NJ/2][q]*SC;
                }
                #pragma unroll
                for (int r = 0; r < 2; ++r)
                    #pragma unroll
                    for (int cc = 0; cc < 2; ++cc) {
                        int m = bm + wm*32 + mi*16 + tr + r*8;
                        int s = m & 511, bb = m >> 9;
                        int hh = (bn + wn*WARP_N) >> 6;
                        int j = njl*8 + tc + cc;
                        float inv = expf(-(float)j * (9.210340371976184f/32.f));
                        float ang = (float)s * inv;
                        float sn, cs;
                        sincosf(ang, &sn, &cs);
                        float x1 = vlo[r*2+cc], x2 = vhi[r*2+cc];
                        long base = (((long)(bb*NHh + hh))*512 + s)*64;
                        C[base + j]      = x1*cs - x2*sn;
                        C[base + j + 32] = x2*cs + x1*sn;
                    }
            }
        return;
    }

    #pragma unroll
    for (int mi = 0; mi < 2; ++mi) {
        #pragma unroll
        for (int nj = 0; nj < NJ; ++nj) {
            int m0 = bm + wm*32 + mi*16 + tr;
            int n0 = bn + wn*WARP_N + nj*8 + tc;
            float v[4];
            #pragma unroll
            for (int q = 0; q < 4; ++q) v[q] = acc1[mi][nj][q] + acc2[mi][nj][q]*SC;
            if (EPI >= 1) {
                float b0 = __ldg(bias + n0), b1 = __ldg(bias + n0 + 1);
                v[0] += b0; v[1] += b1; v[2] += b0; v[3] += b1;
            }
            if (EPI == 2) {
                v[0] = gelu_f(v[0]); v[1] = gelu_f(v[1]);
                v[2] = gelu_f(v[2]); v[3] = gelu_f(v[3]);
            }
            if (OMODE == 1) {
                #pragma unroll
                for (int rr = 0; rr < 2; ++rr) {
                    long base = (long)(m0 + rr*8)*ldh + n0;
                    __half2 hh;
                    hh.x = __float2half(v[rr*2+0]);
                    hh.y = __float2half(v[rr*2+1]);
                    *reinterpret_cast<__half2*>(Ch + base) = hh;
                }
            } else if (OMODE == 2) {
                #pragma unroll
                for (int rr = 0; rr < 2; ++rr) {
                    long base = (long)(m0 + rr*8)*ldh + n0;
                    hf h0 = __float2half(v[rr*2+0]);
                    hf h1 = __float2half(v[rr*2+1]);
                    hf l0 = __float2half((v[rr*2+0] - __half2float(h0))*1024.f);
                    hf l1 = __float2half((v[rr*2+1] - __half2float(h1))*1024.f);
                    __half2 hh; hh.x = h0; hh.y = h1;
                    __half2 llv; llv.x = l0; llv.y = l1;
                    *reinterpret_cast<__half2*>(Ch + base) = hh;
                    *reinterpret_cast<__half2*>(Cl + base) = llv;
                }
            } else if (ldcn == 1) {
                *(float2*)(C + (long)m0*ldcm + n0)     = make_float2(v[0], v[1]);
                *(float2*)(C + (long)(m0+8)*ldcm + n0) = make_float2(v[2], v[3]);
            } else {
                C[(long)m0*ldcm     + (long)n0*ldcn]     = v[0];
                C[(long)m0*ldcm     + (long)(n0+1)*ldcn] = v[1];
                C[(long)(m0+8)*ldcm + (long)n0*ldcn]     = v[2];
                C[(long)(m0+8)*ldcm + (long)(n0+1)*ldcn] = v[3];
            }
        }
    }
}

// ======================= flash attention =======================
#define FA_QS   0
#define FA_KC   (16*68)
#define FA_SC   (FA_KC + 64*68)
#define FA_FLT  (FA_SC + 16*512)
#define FA_SMEM (FA_FLT*4)

__global__ void __launch_bounds__(256) k_fattn(
    const float* __restrict__ qh, const float* __restrict__ kh,
    const float* __restrict__ vh, hf* __restrict__ ctx16)
{
    extern __shared__ __align__(16) float sm[];
    float* qs = sm + FA_QS;
    float* kc = sm + FA_KC;
    float* sc = sm + FA_SC;

    const int tid = threadIdx.x;
    const int q0 = blockIdx.x*16, h = blockIdx.y, b = blockIdx.z;
    const int qi = tid >> 4, tsub = tid & 15;

    const float* Qb = qh + ((long)(b*NHh + h)*Qq + q0)*HDd;
    const float* Kb = kh + ((long)(b*NHh + h)*Ll)*HDd;
    const float* Vb = vh + ((long)(b*NHh + h)*Ll)*HDd;

    {
        int row = tid >> 4, d = (tid & 15)*4;
        *(float4*)(qs + row*68 + d) = *(const float4*)(Qb + row*HDd + d);
    }

    const int NCv = (q0 + 15)/64 + 1;
    const int KLIM = NCv*64;
    const int qg = q0 + qi;

    for (int c = 0; c < NCv; ++c) {
        __syncthreads();
        for (int j = tid; j < 1024; j += 256) {
            int row = j >> 4, d = (j & 15)*4;
            *(float4*)(kc + row*68 + d) = *(const float4*)(Kb + (long)(c*64 + row)*HDd + d);
        }
        __syncthreads();
        #pragma unroll
        for (int jk = 0; jk < 4; ++jk) {
            int kl = jk*16 + tsub;
            int kg = c*64 + kl;
            float s = -1e30f;
            if (kg <= qg) {
                float4 acc4 = make_float4(0.f,0.f,0.f,0.f);
                #pragma unroll
                for (int d = 0; d < HDd; d += 4) {
                    float4 qv = *(float4*)(qs + qi*68 + d);
                    float4 kv4 = *(float4*)(kc + kl*68 + d);
                    acc4.x += qv.x*kv4.x; acc4.y += qv.y*kv4.y;
                    acc4.z += qv.z*kv4.z; acc4.w += qv.w*kv4.w;
                }
                s = (acc4.x + acc4.y + acc4.z + acc4.w) * 0.125f;
            }
            sc[qi*512 + kg] = s;
        }
    }
    __syncthreads();

    float m = -1e30f;
    for (int k = tsub; k < KLIM; k += 16) m = fmaxf(m, sc[qi*512 + k]);
    #pragma unroll
    for (int o = 8; o > 0; o >>= 1) m = fmaxf(m, __shfl_xor_sync(0xffffffffu, m, o, 16));
    float sum = 0.f;
    for (int k = tsub; k < KLIM; k += 16) {
        float e = expf(sc[qi*512 + k] - m);
        sc[qi*512 + k] = e;
        sum += e;
    }
    #pragma unroll
    for (int o = 8; o > 0; o >>= 1) sum += __shfl_xor_sync(0xffffffffu, sum, o, 16);
    const float inv = 1.f / sum;

    float a0 = 0.f, a1 = 0.f, a2 = 0.f, a3 = 0.f;
    const int d0 = tsub*4;
    for (int c = 0; c < NCv; ++c) {
        __syncthreads();
        for (int j = tid; j < 1024; j += 256) {
            int row = j >> 4, d = (j & 15)*4;
            *(float4*)(kc + row*68 + d) = *(const float4*)(Vb + (long)(c*64 + row)*HDd + d);
        }
        __syncthreads();
        #pragma unroll 8
        for (int k = 0; k < 64; ++k) {
            float p = sc[qi*512 + c*64 + k];
            float4 vv = *(float4*)(kc + k*68 + d0);
            a0 += p*vv.x; a1 += p*vv.y; a2 += p*vv.z; a3 += p*vv.w;
        }
    }

    long base = (long)(b*Qq + q0 + qi)*Ee + h*HDd + d0;
    __half2 p0, p1;
    p0.x = __float2half(a0*inv); p0.y = __float2half(a1*inv);
    p1.x = __float2half(a2*inv); p1.y = __float2half(a3*inv);
    *reinterpret_cast<__half2*>(ctx16 + base)     = p0;
    *reinterpret_cast<__half2*>(ctx16 + base + 2) = p1;
}

// ======================= small kernels =======================
// fp16 transpose-split: hi = fp16(v), lo = fp16((v-hi)*1024); w[K,N] -> [N,K]
__global__ void k_wsplit16(const float* __restrict__ w, hf* __restrict__ hi,
                           hf* __restrict__ lo, int K, int N) {
    __shared__ float t[32][33];
    int k0 = blockIdx.y*32, n0 = blockIdx.x*32;
    for (int r = threadIdx.y; r < 32; r += 8)
        t[r][threadIdx.x] = w[(long)(k0+r)*N + n0 + threadIdx.x];
    __syncthreads();
    for (int r = threadIdx.y; r < 32; r += 8) {
        float v = t[threadIdx.x][r];
        hf h = __float2half(v);
        long o = (long)(n0+r)*K + k0 + threadIdx.x;
        hi[o] = h;
        lo[o] = __float2half((v - __half2float(h))*1024.f);
    }
}

__global__ void k_split16(const float* __restrict__ in, hf* __restrict__ hi,
                          hf* __restrict__ lo, int n) {
    int i = blockIdx.x*blockDim.x + threadIdx.x;
    if (i >= n) return;
    float v = in[i];
    hf h = __float2half(v);
    hi[i] = h;
    lo[i] = __float2half((v - __half2float(h))*1024.f);
}

__global__ void k_gather(const int* __restrict__ x, const float* __restrict__ emb,
                         hf* __restrict__ o16) {
    int i = blockIdx.x*blockDim.x + threadIdx.x;
    if (i >= BL*Ee) return;
    int e = i % Ee, bl = i / Ee;
    o16[i] = __float2half(emb[(long)x[bl]*Ee + e]);
}

__global__ void k_init(const float* __restrict__ z0, const float* __restrict__ p0,
                       float* __restrict__ z, float* __restrict__ pah,
                       float* __restrict__ Na, float* __restrict__ No,
                       hf* __restrict__ cat16) {
    int i = blockIdx.x*blockDim.x + threadIdx.x;
    if (i < Dd*BQ*Ww) {
        int d = i / (BQ*Ww);
        int w = i % Ww;
        pah[i] = p0[w*Dd + d];
    }
    if (i < BQ*Ww) {
        int w = i % Ww, bq = i / Ww;
        float v = z0[w];
        z[i] = v;
        cat16[(long)bq*(Ee+Ww) + Ee + w] = __float2half(v);
    }
    if (i < BQ*SAa) Na[i] = 0.f;
    if (i < BQ*SOo) No[i] = 0.f;
}

__global__ void k_rope_split(const float* __restrict__ in, float* __restrict__ out,
                             int S, int do_rope) {
    int i = blockIdx.x*blockDim.x + threadIdx.x;
    if (i >= Bb*S*Ee) return;
    int d = i % HDd;
    int h = (i / HDd) % NHh;
    int s = (i / Ee) % S;
    int b = i / (Ee*S);
    const float* row = in + ((long)(b*S + s))*Ee + h*HDd;
    float v;
    if (do_rope) {
        const int half = HDd/2;
        int j = d % half;
        float inv = expf(-(float)j * (9.210340371976184f / (float)half));
        float ang = (float)s * inv;
        float c = cosf(ang), sn = sinf(ang);
        float x1 = row[j], x2 = row[j + half];
        v = (d < half) ? (x1*c - x2*sn) : (x2*c + x1*sn);
    } else {
        v = row[d];
    }
    out[(((long)(b*NHh + h))*S + s)*HDd + d] = v;
}

__global__ void __launch_bounds__(256) k_nlm(
    const float* __restrict__ pah, const float* __restrict__ w1,
    const float* __restrict__ b1, const float* __restrict__ w2,
    const float* __restrict__ b2, float* __restrict__ z,
    hf* __restrict__ cat16, int start)
{
    __shared__ float w1s[32*257];
    __shared__ float b1s[32*33];
    __shared__ float w2s[32*33];
    __shared__ float b2s[32];
    const int tid = threadIdx.x;
    const int w0 = blockIdx.x*32, bq0 = blockIdx.y*128;

    for (int j = tid; j < 32*256; j += 256) w1s[(j>>8)*257 + (j&255)] = w1[(long)w0*256 + j];
    for (int j = tid; j < 32*32;  j += 256) {
        b1s[(j>>5)*33 + (j&31)] = b1[(long)w0*32 + j];
        w2s[(j>>5)*33 + (j&31)] = w2[(long)w0*32 + j];
    }
    if (tid < 32) b2s[tid] = b2[w0 + tid];
    __syncthreads();

    const int wl = tid & 31, bql = tid >> 5;
    const int w = w0 + wl;
    for (int bq = bq0 + bql; bq < bq0 + 128; bq += 8) {
        float pv[Dd];
        #pragma unroll
        for (int d = 0; d < Dd; d++)
            pv[d] = pah[(long)((start + d) & 7)*BQ*Ww + (long)bq*Ww + w];
        float zacc = b2s[wl];
        #pragma unroll
        for (int hh = 0; hh < Hn; hh++) {
            float a = b1s[wl*33 + hh];
            #pragma unroll
            for (int d = 0; d < Dd; d++) a += pv[d]*w1s[wl*257 + d*32 + hh];
            zacc += gelu_f(a)*w2s[wl*33 + hh];
        }
        z[(long)bq*Ww + w] = zacc;
        cat16[(long)bq*(Ee+Ww) + Ee + w] = __float2half(zacc);
    }
}

__global__ void k_sync(const float* __restrict__ z, float* __restrict__ Nbuf,
                       hf* __restrict__ syn,
                       const int* __restrict__ il, const int* __restrict__ ir,
                       const float* __restrict__ dec, int S, int Tn) {
    int i = blockIdx.x*blockDim.x + threadIdx.x;
    if (i >= BQ*S) return;
    int s = i % S, bq = i / S;
    float d  = dec[s];
    float ed = expf(-d);
    const float* zr = z + (long)bq*Ww;
    float p  = zr[il[s]]*zr[ir[s]];
    float Nn = Nbuf[i]*ed + p;
    Nbuf[i] = Nn;
    float den = 0.f, wgt = 1.f;
    for (int k = 0; k < Tn; k++) { den += wgt; wgt *= ed; }
    syn[i] = __float2half(Nn / sqrtf(den));
}

// ======================= host =======================
static void* symv(const void* s) { void* p = nullptr; cudaGetSymbolAddress(&p, s); return p; }

template<int EPI, int BM, int OMODE>
static void rung(const hf* A, const hf* Bh, const hf* Bl,
                 const float* bias, float* C, hf* Ch, hf* Cl,
                 int M, int N, int K, long ldcm, long ldcn, long ldh) {
    constexpr int SM = 3*(BM*80 + 2*128*80);
    cudaFuncSetAttribute(hg<EPI,BM,OMODE>, cudaFuncAttributeMaxDynamicSharedMemorySize, SM);
    dim3 g(N/128, M/BM);
    hg<EPI,BM,OMODE><<<g, 256, SM>>>(A, Bh, Bl, bias, C, Ch, Cl, M, N, K, ldcm, ldcn, ldh);
}

extern "C" void kernel_launch(void* const* d_in, const int* in_sizes, int n_in,
                              void* d_out, int out_size) {
    (void)in_sizes; (void)n_in; (void)out_size;
    const int*   x      = (const int*)  d_in[0];
    const float* emb    = (const float*)d_in[2];
    const float* w_kv   = (const float*)d_in[3];
    const float* w_qs   = (const float*)d_in[4];
    const float* wq     = (const float*)d_in[5];
    const float* wk     = (const float*)d_in[6];
    const float* wv     = (const float*)d_in[7];
    const float* wo     = (const float*)d_in[8];
    const float* ws1    = (const float*)d_in[9];
    const float* bs1    = (const float*)d_in[10];
    const float* ws2    = (const float*)d_in[11];
    const float* bs2    = (const float*)d_in[12];
    const float* nw1    = (const float*)d_in[13];
    const float* nb1    = (const float*)d_in[14];
    const float* nw2    = (const float*)d_in[15];
    const float* nb2    = (const float*)d_in[16];
    const float* out_w  = (const float*)d_in[17];
    const float* out_b  = (const float*)d_in[18];
    const float* z_init = (const float*)d_in[19];
    const float* p_init = (const float*)d_in[20];
    const float* dec_a  = (const float*)d_in[21];
    const float* dec_o  = (const float*)d_in[22];
    const int*   idx_la = (const int*)  d_in[23];
    const int*   idx_ra = (const int*)  d_in[24];
    const int*   idx_lo = (const int*)  d_in[25];
    const int*   idx_ro = (const int*)  d_in[26];
    float* out = (float*)d_out;

    float *tmp = (float*)symv(g_tmp);
    float *qh = (float*)symv(g_qh), *kh = (float*)symv(g_kh), *vh = (float*)symv(g_vh);
    float *z = (float*)symv(g_z), *pah = (float*)symv(g_pah);
    float *Na = (float*)symv(g_Na), *No = (float*)symv(g_No);

    hf *emb16=(hf*)symv(g_emb16), *kv16=(hf*)symv(g_kv16);
    hf *ctx16=(hf*)symv(g_ctx16), *cat16=(hf*)symv(g_cat16);
    hf *h116=(hf*)symv(g_h116);
    hf *sa16=(hf*)symv(g_sa16), *so16=(hf*)symv(g_so16);

    hf *wkvTh=(hf*)symv(g_wkvTh), *wkvTl=(hf*)symv(g_wkvTl);
    hf *wkTh =(hf*)symv(g_wkTh),  *wkTl =(hf*)symv(g_wkTl);
    hf *wvTh =(hf*)symv(g_wvTh),  *wvTl =(hf*)symv(g_wvTl);
    hf *woTh =(hf*)symv(g_woTh),  *woTl =(hf*)symv(g_woTl);
    hf *ws1Th=(hf*)symv(g_ws1Th), *ws1Tl=(hf*)symv(g_ws1Tl);
    hf *ws2Th=(hf*)symv(g_ws2Th), *ws2Tl=(hf*)symv(g_ws2Tl);
    hf *owTh =(hf*)symv(g_owTh),  *owTl =(hf*)symv(g_owTl);
    hf *wqTh =(hf*)symv(g_wqTh),  *wqTl =(hf*)symv(g_wqTl);
    hf *wqs16h=(hf*)symv(g_wqs16h), *wqs16l=(hf*)symv(g_wqs16l);
    hf *Wch  =(hf*)symv(g_Wch),   *Wcl  =(hf*)symv(g_Wcl);

    const int TPB = 256;
    dim3 wb(32, 8);

    // ---- weight prep (loop-invariant) ----
    k_wsplit16<<<dim3(Ee/32,  Ee/32),  wb>>>(w_kv,  wkvTh, wkvTl, Ee,  Ee);
    k_wsplit16<<<dim3(Ee/32,  Ee/32),  wb>>>(wk,    wkTh,  wkTl,  Ee,  Ee);
    k_wsplit16<<<dim3(Ee/32,  Ee/32),  wb>>>(wv,    wvTh,  wvTl,  Ee,  Ee);
    k_wsplit16<<<dim3(Ee/32,  Ee/32),  wb>>>(wo,    woTh,  woTl,  Ee,  Ee);
    k_wsplit16<<<dim3(SHh/32, (Ee+Ww)/32), wb>>>(ws1, ws1Th, ws1Tl, Ee+Ww, SHh);
    k_wsplit16<<<dim3(Ww/32,  SHh/32), wb>>>(ws2,   ws2Th, ws2Tl, SHh, Ww);
    k_wsplit16<<<dim3(Vv/32,  SOo/32), wb>>>(out_w, owTh,  owTl,  SOo, Vv);
    k_wsplit16<<<dim3(Ee/32,  Ee/32),  wb>>>(wq,    wqTh,  wqTl,  Ee,  Ee);
    k_split16<<<(SAa*Ee + TPB-1)/TPB, TPB>>>(w_qs, wqs16h, wqs16l, SAa*Ee);
    // combined W^T = wq^T @ wqs^T -> [E][SA] fp16 hi/scaled-lo
    rung<0,64,2>(wqTh, wqs16h, wqs16l, nullptr, nullptr, Wch, Wcl, Ee, SAa, Ee, 0, 0, SAa);

    // ---- prologue: kv, kh, vh ----
    k_gather<<<(BL*Ee + TPB-1)/TPB, TPB>>>(x, emb, emb16);
    rung<0,64,1>(emb16, wkvTh, wkvTl, nullptr, nullptr, kv16, nullptr, BL, Ee, Ee, 0, 0, Ee);
    rung<0,64,0>(kv16, wkTh, wkTl, nullptr, tmp, nullptr, nullptr, BL, Ee, Ee, Ee, 1, 0);
    k_rope_split<<<(Bb*Ll*Ee + TPB-1)/TPB, TPB>>>(tmp, kh, Ll, 1);
    rung<0,64,0>(kv16, wvTh, wvTl, nullptr, tmp, nullptr, nullptr, BL, Ee, Ee, Ee, 1, 0);
    k_rope_split<<<(Bb*Ll*Ee + TPB-1)/TPB, TPB>>>(tmp, vh, Ll, 0);

    k_init<<<(Dd*BQ*Ww + TPB-1)/TPB, TPB>>>(z_init, p_init, z, pah, Na, No, cat16);
    k_sync<<<(BQ*SAa + TPB-1)/TPB, TPB>>>(z, Na, sa16, idx_la, idx_ra, dec_a, SAa, 1);
    k_sync<<<(BQ*SOo + TPB-1)/TPB, TPB>>>(z, No, so16, idx_lo, idx_ro, dec_o, SOo, 1);

    cudaFuncSetAttribute(k_fattn, cudaFuncAttributeMaxDynamicSharedMemorySize, FA_SMEM);

    // ---- T iterations ----
    for (int t = 0; t < Tt; t++) {
        // q = sa @ (wqs@wq), rope fused -> qh
        rung<0,128,3>(sa16, Wch, Wcl, nullptr, qh, nullptr, nullptr, BQ, Ee, SAa, 0, 0, 0);
        k_fattn<<<dim3(Qq/16, NHh, Bb), 256, FA_SMEM>>>(qh, kh, vh, ctx16);
        // attn_out -> cat[:, 0:Ee)
        rung<0,64,1>(ctx16, woTh, woTl, nullptr, nullptr, cat16, nullptr, BQ, Ee, Ee, 0, 0, Ee+Ww);
        // synapse MLP
        rung<2,64,1>(cat16, ws1Th, ws1Tl, bs1, nullptr, h116, nullptr, BQ, SHh, Ee+Ww, 0, 0, SHh);
        rung<1,64,0>(h116, ws2Th, ws2Tl, bs2, pah + (long)t*BQ*Ww, nullptr, nullptr,
                     BQ, Ww, SHh, Ww, 1, 0);
        // neuron-level models + sync
        k_nlm<<<dim3(Ww/32, BQ/128), 256>>>(pah, nw1, nb1, nw2, nb2, z, cat16, t + 1);
        k_sync<<<(BQ*SAa + TPB-1)/TPB, TPB>>>(z, Na, sa16, idx_la, idx_ra, dec_a, SAa, t + 2);
        k_sync<<<(BQ*SOo + TPB-1)/TPB, TPB>>>(z, No, so16, idx_lo, idx_ro, dec_o, SOo, t + 2);
        // logits
        rung<1,128,0>(so16, owTh, owTl, out_b, out + (long)t*BQ*Vv, nullptr, nullptr,
                      BQ, Vv, SOo, Vv, 1, 0);
    }
}

// round 14
// speedup vs baseline: 3.9369x; 1.0925x over previous
#include <cuda_runtime.h>
#include <cuda_bf16.h>
#include <cuda_fp16.h>
#include <math.h>
#include <stdint.h>

// ---- problem constants ----
#define Bb   2
#define Ll   512
#define Qq   512
#define Ee   1024
#define Ww   1024
#define Dd   8
#define Hn   32
#define NHh  16
#define HDd  64
#define SAa  512
#define SOo  1024
#define Vv   8192
#define Tt   6
#define SHh  2048
#define BQ   (Bb*Qq)
#define BL   (Bb*Ll)

typedef __half hf;

// ---- fp32 scratch ----
__device__ float g_tmp [BQ*Ee];
__device__ float g_qh  [Bb*NHh*Qq*HDd];
__device__ float g_kh  [Bb*NHh*Ll*HDd];
__device__ float g_vh  [Bb*NHh*Ll*HDd];
__device__ float g_z   [BQ*Ww];
__device__ float g_pah [Dd*BQ*Ww];          // 8 planes of [BQ][Ww]
__device__ float g_Na  [BQ*SAa];
__device__ float g_No  [BQ*SOo];

// ---- fp16 single activations ----
__device__ hf g_emb16[BL*Ee];
__device__ hf g_kv16 [BL*Ee];
__device__ hf g_cat16[BQ*(Ee+Ww)];          // [ctx | z]
__device__ hf g_h116 [BQ*SHh];
__device__ hf g_sa16 [BQ*SAa];
__device__ hf g_so16 [BQ*SOo];

// ---- fp16 hi/scaled-lo weights ----
__device__ hf g_wkvTh[Ee*Ee],       g_wkvTl[Ee*Ee];
__device__ hf g_wkTh [Ee*Ee],       g_wkTl [Ee*Ee];
__device__ hf g_wvTh [Ee*Ee],       g_wvTl [Ee*Ee];
__device__ hf g_ws1Th[SHh*(Ee+Ww)], g_ws1Tl[SHh*(Ee+Ww)];   // ws1^T source
__device__ hf g_wsFh [SHh*(Ee+Ww)], g_wsFl [SHh*(Ee+Ww)];   // fused [Wos^T | ws1_botT]
__device__ hf g_ws2Th[Ww*SHh],      g_ws2Tl[Ww*SHh];
__device__ hf g_owTh [Vv*SOo],      g_owTl [Vv*SOo];
__device__ hf g_wqTh [Ee*Ee],       g_wqTl [Ee*Ee];
__device__ hf g_wqs16h[SAa*Ee],     g_wqs16l[SAa*Ee];
__device__ hf g_wo16h[Ee*Ee],       g_wo16l[Ee*Ee];         // wo raw rows
__device__ hf g_Wch  [Ee*SAa],      g_Wcl  [Ee*SAa];

__device__ __forceinline__ float gelu_f(float x) {
    // x * sigmoid(2*0.79788456*(x + 0.044715 x^3)) == tanh-gelu
    float y = 1.5957691216057308f*(x + 0.044715f*x*x*x);
    return x / (1.0f + __expf(-y));
}

// ====================== mma primitives ======================
__device__ __forceinline__ void cpa16(uint32_t s, const void* g){
    asm volatile("cp.async.cg.shared.global [%0], [%1], 16;" :: "r"(s), "l"(g));
}
__device__ __forceinline__ void cpcommit(){ asm volatile("cp.async.commit_group;" ::: "memory"); }
template<int N> __device__ __forceinline__ void cpwait(){ asm volatile("cp.async.wait_group %0;" :: "n"(N) : "memory"); }
__device__ __forceinline__ void ldmx4(uint32_t* r, uint32_t a){
    asm volatile("ldmatrix.sync.aligned.m8n8.x4.shared.b16 {%0,%1,%2,%3}, [%4];"
        : "=r"(r[0]),"=r"(r[1]),"=r"(r[2]),"=r"(r[3]) : "r"(a));
}
__device__ __forceinline__ void mma_fp16(float* c, const uint32_t* a, uint32_t b0, uint32_t b1){
    asm volatile("mma.sync.aligned.m16n8k16.row.col.f32.f16.f16.f32 "
        "{%0,%1,%2,%3}, {%4,%5,%6,%7}, {%8,%9}, {%0,%1,%2,%3};"
        : "+f"(c[0]),"+f"(c[1]),"+f"(c[2]),"+f"(c[3])
        : "r"(a[0]),"r"(a[1]),"r"(a[2]),"r"(a[3]), "r"(b0),"r"(b1));
}

// ============ fp16 GEMM, 3-stage cp.async ============
// C(M,N) = epi(A @ B^T [+bias]); A fp16 [M,K]; Bh=fp16(B), Bl=fp16((B-Bh)*1024), [N,K].
// NPASS=2: result = acc1 + acc2/1024 (effective ~fp32). NPASS=1: hi-only.
// EPI: 0 none, 1 +bias, 2 gelu(+bias)
// OMODE: 0 fp32 C, 1 fp16 single out (ldh), 3 rope->qh
template<int EPI, int BM, int OMODE, int NPASS>
__global__ void __launch_bounds__(256, (BM==64)?2:1) hg(
    const hf* __restrict__ A,
    const hf* __restrict__ Bh, const hf* __restrict__ Bl,
    const float* __restrict__ bias,
    float* __restrict__ C, hf* __restrict__ Ch,
    int M, int N, int K, long ldcm, long ldcn, long ldh)
{
    constexpr int WMW = BM/32;
    constexpr int WNW = 8/WMW;
    constexpr int WARP_N = 128/WNW;
    constexpr int NJ = WARP_N/8;
    constexpr int TILE_A = BM*80;
    constexpr int TILE_B = 128*80;
    constexpr int STAGE = TILE_A + NPASS*TILE_B;

    extern __shared__ __align__(16) char dyn[];
    const int tid  = threadIdx.x;
    const int wid  = tid >> 5, lane = tid & 31;
    const int bm = blockIdx.y*BM, bn = blockIdx.x*128;
    const int wm = wid % WMW, wn = wid / WMW;

    uint32_t sbase = (uint32_t)__cvta_generic_to_shared(dyn);

    const hf* gA  = A  + (long)bm*K;
    const hf* gBh = Bh + (long)bn*K;
    const hf* gBl = Bl + (long)bn*K;

    auto load_stage = [&](int st, int k0){
        uint32_t s0 = sbase + st*STAGE;
        #pragma unroll
        for (int c = 0; c < BM/64; ++c) {
            int ch = tid + c*256;
            int row = ch >> 2, seg = ch & 3;
            cpa16(s0 + row*80 + seg*16, gA + (long)row*K + k0 + seg*8);
        }
        #pragma unroll
        for (int c = 0; c < 2; ++c) {
            int ch = tid + c*256;
            int row = ch >> 2, seg = ch & 3;
            cpa16(s0 + TILE_A + row*80 + seg*16, gBh + (long)row*K + k0 + seg*8);
            if (NPASS == 2)
                cpa16(s0 + TILE_A + TILE_B + row*80 + seg*16, gBl + (long)row*K + k0 + seg*8);
        }
    };

    float acc1[2][NJ][4], acc2[2][NJ][4];
    #pragma unroll
    for (int i = 0; i < 2; i++)
        #pragma unroll
        for (int j = 0; j < NJ; j++)
            #pragma unroll
            for (int q = 0; q < 4; q++) { acc1[i][j][q] = 0.f; acc2[i][j][q] = 0.f; }

    const int NC = K >> 5;
    load_stage(0, 0); cpcommit();
    if (NC > 1) { load_stage(1, 32); cpcommit(); }

    const int l = lane & 7, sel = lane >> 3;
    const int rofs = l + ((sel & 1) << 3);
    const int cofs = (sel >> 1) << 3;

    for (int c = 0; c < NC; ++c) {
        if (c + 2 < NC) { load_stage((c+2)%3, (c+2)*32); cpcommit(); cpwait<2>(); }
        else if (c + 1 < NC) cpwait<1>();
        else cpwait<0>();
        __syncthreads();

        uint32_t s0  = sbase + (c%3)*STAGE;
        uint32_t sA = s0, sBh = s0 + TILE_A, sBl = sBh + TILE_B;

        #pragma unroll
        for (int k16 = 0; k16 < 2; ++k16) {
            int colo = k16*16 + cofs;
            uint32_t a[2][4];
            #pragma unroll
            for (int mi = 0; mi < 2; ++mi) {
                uint32_t off = (uint32_t)((wm*32 + mi*16 + rofs)*40 + colo)*2;
                ldmx4(a[mi], sA + off);
            }
            uint32_t bhf[NJ/2][4], blf[NJ/2][4];
            #pragma unroll
            for (int ni = 0; ni < NJ/2; ++ni) {
                uint32_t off = (uint32_t)((wn*WARP_N + ni*16 + rofs)*40 + colo)*2;
                ldmx4(bhf[ni], sBh + off);
                if (NPASS == 2) ldmx4(blf[ni], sBl + off);
            }
            #pragma unroll
            for (int mi = 0; mi < 2; ++mi)
                #pragma unroll
                for (int nj = 0; nj < NJ; ++nj) {
                    int g = nj >> 1, h8 = nj & 1;
                    mma_fp16(acc1[mi][nj], a[mi], bhf[g][h8], bhf[g][h8+2]);
                    if (NPASS == 2) mma_fp16(acc2[mi][nj], a[mi], blf[g][h8], blf[g][h8+2]);
                }
        }
        __syncthreads();
    }

    const float SC = 1.f/1024.f;
    const int tr = lane >> 2, tc = (lane & 3)*2;

    if (OMODE == 3) {
        // rope epilogue -> qh[(b*NH+h)*512 + s][64]; BM=128 (WARP_N=64)
        #pragma unroll
        for (int mi = 0; mi < 2; ++mi)
            #pragma unroll
            for (int njl = 0; njl < NJ/2; ++njl) {
                float vlo[4], vhi[4];
                #pragma unroll
                for (int q = 0; q < 4; ++q) {
                    vlo[q] = acc1[mi][njl][q]      + acc2[mi][njl][q]*SC;
                    vhi[q] = acc1[mi][njl+NJ/2][q] + acc2[mi][njl+NJ/2][q]*SC;
                }
                #pragma unroll
                for (int r = 0; r < 2; ++r)
                    #pragma unroll
                    for (int cc = 0; cc < 2; ++cc) {
                        int m = bm + wm*32 + mi*16 + tr + r*8;
                        int s = m & 511, bb = m >> 9;
                        int hh = (bn + wn*WARP_N) >> 6;
                        int j = njl*8 + tc + cc;
                        float inv = expf(-(float)j * (9.210340371976184f/32.f));
                        float ang = (float)s * inv;
                        float sn, cs;
                        sincosf(ang, &sn, &cs);
                        float x1 = vlo[r*2+cc], x2 = vhi[r*2+cc];
                        long base = (((long)(bb*NHh + hh))*512 + s)*64;
                        C[base + j]      = x1*cs - x2*sn;
                        C[base + j + 32] = x2*cs + x1*sn;
                    }
            }
        return;
    }

    #pragma unroll
    for (int mi = 0; mi < 2; ++mi) {
        #pragma unroll
        for (int nj = 0; nj < NJ; ++nj) {
            int m0 = bm + wm*32 + mi*16 + tr;
            int n0 = bn + wn*WARP_N + nj*8 + tc;
            float v[4];
            #pragma unroll
            for (int q = 0; q < 4; ++q)
                v[q] = (NPASS == 2) ? (acc1[mi][nj][q] + acc2[mi][nj][q]*SC) : acc1[mi][nj][q];
            if (EPI >= 1) {
                float b0 = __ldg(bias + n0), b1 = __ldg(bias + n0 + 1);
                v[0] += b0; v[1] += b1; v[2] += b0; v[3] += b1;
            }
            if (EPI == 2) {
                v[0] = gelu_f(v[0]); v[1] = gelu_f(v[1]);
                v[2] = gelu_f(v[2]); v[3] = gelu_f(v[3]);
            }
            if (OMODE == 1) {
                #pragma unroll
                for (int rr = 0; rr < 2; ++rr) {
                    long base = (long)(m0 + rr*8)*ldh + n0;
                    __half2 hh;
                    hh.x = __float2half(v[rr*2+0]);
                    hh.y = __float2half(v[rr*2+1]);
                    *reinterpret_cast<__half2*>(Ch + base) = hh;
                }
            } else if (ldcn == 1) {
                *(float2*)(C + (long)m0*ldcm + n0)     = make_float2(v[0], v[1]);
                *(float2*)(C + (long)(m0+8)*ldcm + n0) = make_float2(v[2], v[3]);
            } else {
                C[(long)m0*ldcm     + (long)n0*ldcn]     = v[0];
                C[(long)m0*ldcm     + (long)(n0+1)*ldcn] = v[1];
                C[(long)(m0+8)*ldcm + (long)n0*ldcn]     = v[2];
                C[(long)(m0+8)*ldcm + (long)(n0+1)*ldcn] = v[3];
            }
        }
    }
}

// ===== prep 3-pass GEMM: A hi/lo, B hi/lo -> fp16 hi/scaled-lo out (ldh) =====
// C = (Ah + Al/1024) @ (Bh + Bl/1024)^T, BM=128, 2-stage. A row stride lda.
__global__ void __launch_bounds__(256, 1) hg3(
    const hf* __restrict__ Ah, const hf* __restrict__ Al,
    const hf* __restrict__ Bh, const hf* __restrict__ Bl,
    hf* __restrict__ Ch, hf* __restrict__ Cl,
    int M, int N, int K, long lda, long ldh)
{
    constexpr int TILE = 128*80;
    constexpr int STAGE = 4*TILE;
    extern __shared__ __align__(16) char dyn[];
    const int tid  = threadIdx.x;
    const int wid  = tid >> 5, lane = tid & 31;
    const int bm = blockIdx.y*128, bn = blockIdx.x*128;
    const int wm = wid & 3, wn = wid >> 2;

    uint32_t sbase = (uint32_t)__cvta_generic_to_shared(dyn);
    const hf* gAh = Ah + (long)bm*lda;
    const hf* gAl = Al + (long)bm*lda;
    const hf* gBh = Bh + (long)bn*K;
    const hf* gBl = Bl + (long)bn*K;

    auto load_stage = [&](int st, int k0){
        uint32_t s0 = sbase + st*STAGE;
        #pragma unroll
        for (int c = 0; c < 2; ++c) {
            int ch = tid + c*256;
            int row = ch >> 2, seg = ch & 3;
            cpa16(s0 + row*80 + seg*16,          gAh + (long)row*lda + k0 + seg*8);
            cpa16(s0 + TILE   + row*80 + seg*16, gAl + (long)row*lda + k0 + seg*8);
            cpa16(s0 + 2*TILE + row*80 + seg*16, gBh + (long)row*K + k0 + seg*8);
            cpa16(s0 + 3*TILE + row*80 + seg*16, gBl + (long)row*K + k0 + seg*8);
        }
    };

    float acc1[2][8][4], acc2[2][8][4];
    #pragma unroll
    for (int i = 0; i < 2; i++)
        #pragma unroll
        for (int j = 0; j < 8; j++)
            #pragma unroll
            for (int q = 0; q < 4; q++) { acc1[i][j][q] = 0.f; acc2[i][j][q] = 0.f; }

    const int NC = K >> 5;
    load_stage(0, 0); cpcommit();

    const int l = lane & 7, sel = lane >> 3;
    const int rofs = l + ((sel & 1) << 3);
    const int cofs = (sel >> 1) << 3;

    for (int c = 0; c < NC; ++c) {
        if (c + 1 < NC) { load_stage((c+1)&1, (c+1)*32); cpcommit(); cpwait<1>(); }
        else cpwait<0>();
        __syncthreads();
        uint32_t s0 = sbase + (c&1)*STAGE;
        uint32_t sAh = s0, sAl = s0 + TILE, sBh = s0 + 2*TILE, sBl = s0 + 3*TILE;
        #pragma unroll
        for (int k16 = 0; k16 < 2; ++k16) {
            int colo = k16*16 + cofs;
            uint32_t ah[2][4], al[2][4];
            #pragma unroll
            for (int mi = 0; mi < 2; ++mi) {
                uint32_t off = (uint32_t)((wm*32 + mi*16 + rofs)*40 + colo)*2;
                ldmx4(ah[mi], sAh + off);
                ldmx4(al[mi], sAl + off);
            }
            uint32_t bh[4][4], bl[4][4];
            #pragma unroll
            for (int ni = 0; ni < 4; ++ni) {
                uint32_t off = (uint32_t)((wn*64 + ni*16 + rofs)*40 + colo)*2;
                ldmx4(bh[ni], sBh + off);
                ldmx4(bl[ni], sBl + off);
            }
            #pragma unroll
            for (int mi = 0; mi < 2; ++mi)
                #pragma unroll
                for (int nj = 0; nj < 8; ++nj) {
                    int g = nj >> 1, h8 = nj & 1;
                    mma_fp16(acc1[mi][nj], ah[mi], bh[g][h8], bh[g][h8+2]);
                    mma_fp16(acc2[mi][nj], ah[mi], bl[g][h8], bl[g][h8+2]);
                    mma_fp16(acc2[mi][nj], al[mi], bh[g][h8], bh[g][h8+2]);
                }
        }
        __syncthreads();
    }

    const float SC = 1.f/1024.f;
    const int tr = lane >> 2, tc = (lane & 3)*2;
    #pragma unroll
    for (int mi = 0; mi < 2; ++mi)
        #pragma unroll
        for (int nj = 0; nj < 8; ++nj) {
            int m0 = bm + wm*32 + mi*16 + tr;
            int n0 = bn + wn*64 + nj*8 + tc;
            float v[4];
            #pragma unroll
            for (int q = 0; q < 4; ++q) v[q] = acc1[mi][nj][q] + acc2[mi][nj][q]*SC;
            #pragma unroll
            for (int rr = 0; rr < 2; ++rr) {
                long base = (long)(m0 + rr*8)*ldh + n0;
                hf h0 = __float2half(v[rr*2+0]);
                hf h1 = __float2half(v[rr*2+1]);
                hf l0 = __float2half((v[rr*2+0] - __half2float(h0))*1024.f);
                hf l1 = __float2half((v[rr*2+1] - __half2float(h1))*1024.f);
                __half2 hh; hh.x = h0; hh.y = h1;
                __half2 llv; llv.x = l0; llv.y = l1;
                *reinterpret_cast<__half2*>(Ch + base) = hh;
                *reinterpret_cast<__half2*>(Cl + base) = llv;
            }
        }
}

// ======================= flash attention =======================
#define FA_QS   0
#define FA_KC   (16*68)
#define FA_SC   (FA_KC + 64*68)
#define FA_FLT  (FA_SC + 16*512)
#define FA_SMEM (FA_FLT*4)

__global__ void __launch_bounds__(256) k_fattn(
    const float* __restrict__ qh, const float* __restrict__ kh,
    const float* __restrict__ vh, hf* __restrict__ dst, int ldd)
{
    extern __shared__ __align__(16) float sm[];
    float* qs = sm + FA_QS;
    float* kc = sm + FA_KC;
    float* sc = sm + FA_SC;

    const int tid = threadIdx.x;
    const int q0 = blockIdx.x*16, h = blockIdx.y, b = blockIdx.z;
    const int qi = tid >> 4, tsub = tid & 15;

    const float* Qb = qh + ((long)(b*NHh + h)*Qq + q0)*HDd;
    const float* Kb = kh + ((long)(b*NHh + h)*Ll)*HDd;
    const float* Vb = vh + ((long)(b*NHh + h)*Ll)*HDd;

    {
        int row = tid >> 4, d = (tid & 15)*4;
        *(float4*)(qs + row*68 + d) = *(const float4*)(Qb + row*HDd + d);
    }

    const int NCv = (q0 + 15)/64 + 1;
    const int KLIM = NCv*64;
    const int qg = q0 + qi;

    for (int c = 0; c < NCv; ++c) {
        __syncthreads();
        for (int j = tid; j < 1024; j += 256) {
            int row = j >> 4, d = (j & 15)*4;
            *(float4*)(kc + row*68 + d) = *(const float4*)(Kb + (long)(c*64 + row)*HDd + d);
        }
        __syncthreads();
        #pragma unroll
        for (int jk = 0; jk < 4; ++jk) {
            int kl = jk*16 + tsub;
            int kg = c*64 + kl;
            float s = -1e30f;
            if (kg <= qg) {
                float4 acc4 = make_float4(0.f,0.f,0.f,0.f);
                #pragma unroll
                for (int d = 0; d < HDd; d += 4) {
                    float4 qv = *(float4*)(qs + qi*68 + d);
                    float4 kv4 = *(float4*)(kc + kl*68 + d);
                    acc4.x += qv.x*kv4.x; acc4.y += qv.y*kv4.y;
                    acc4.z += qv.z*kv4.z; acc4.w += qv.w*kv4.w;
                }
                s = (acc4.x + acc4.y + acc4.z + acc4.w) * 0.125f;
            }
            sc[qi*512 + kg] = s;
        }
    }
    __syncthreads();

    float m = -1e30f;
    for (int k = tsub; k < KLIM; k += 16) m = fmaxf(m, sc[qi*512 + k]);
    #pragma unroll
    for (int o = 8; o > 0; o >>= 1) m = fmaxf(m, __shfl_xor_sync(0xffffffffu, m, o, 16));
    float sum = 0.f;
    for (int k = tsub; k < KLIM; k += 16) {
        float e = expf(sc[qi*512 + k] - m);
        sc[qi*512 + k] = e;
        sum += e;
    }
    #pragma unroll
    for (int o = 8; o > 0; o >>= 1) sum += __shfl_xor_sync(0xffffffffu, sum, o, 16);
    const float inv = 1.f / sum;

    float a0 = 0.f, a1 = 0.f, a2 = 0.f, a3 = 0.f;
    const int d0 = tsub*4;
    for (int c = 0; c < NCv; ++c) {
        __syncthreads();
        for (int j = tid; j < 1024; j += 256) {
            int row = j >> 4, d = (j & 15)*4;
            *(float4*)(kc + row*68 + d) = *(const float4*)(Vb + (long)(c*64 + row)*HDd + d);
        }
        __syncthreads();
        #pragma unroll 8
        for (int k = 0; k < 64; ++k) {
            float p = sc[qi*512 + c*64 + k];
            float4 vv = *(float4*)(kc + k*68 + d0);
            a0 += p*vv.x; a1 += p*vv.y; a2 += p*vv.z; a3 += p*vv.w;
        }
    }

    long base = (long)(b*Qq + q0 + qi)*ldd + h*HDd + d0;
    __half2 p0, p1;
    p0.x = __float2half(a0*inv); p0.y = __float2half(a1*inv);
    p1.x = __float2half(a2*inv); p1.y = __float2half(a3*inv);
    *reinterpret_cast<__half2*>(dst + base)     = p0;
    *reinterpret_cast<__half2*>(dst + base + 2) = p1;
}

// ======================= small kernels =======================
__global__ void k_wsplit16(const float* __restrict__ w, hf* __restrict__ hi,
                           hf* __restrict__ lo, int K, int N) {
    __shared__ float t[32][33];
    int k0 = blockIdx.y*32, n0 = blockIdx.x*32;
    for (int r = threadIdx.y; r < 32; r += 8)
        t[r][threadIdx.x] = w[(long)(k0+r)*N + n0 + threadIdx.x];
    __syncthreads();
    for (int r = threadIdx.y; r < 32; r += 8) {
        float v = t[threadIdx.x][r];
        hf h = __float2half(v);
        long o = (long)(n0+r)*K + k0 + threadIdx.x;
        hi[o] = h;
        lo[o] = __float2half((v - __half2float(h))*1024.f);
    }
}

__global__ void k_split16(const float* __restrict__ in, hf* __restrict__ hi,
                          hf* __restrict__ lo, int n) {
    int i = blockIdx.x*blockDim.x + threadIdx.x;
    if (i >= n) return;
    float v = in[i];
    hf h = __float2half(v);
    hi[i] = h;
    lo[i] = __float2half((v - __half2float(h))*1024.f);
}

__global__ void k_gather(const int* __restrict__ x, const float* __restrict__ emb,
                         hf* __restrict__ o16) {
    int i = blockIdx.x*blockDim.x + threadIdx.x;
    if (i >= BL*Ee) return;
    int e = i % Ee, bl = i / Ee;
    o16[i] = __float2half(emb[(long)x[bl]*Ee + e]);
}

__global__ void k_init(const float* __restrict__ z0, const float* __restrict__ p0,
                       float* __restrict__ z, float* __restrict__ pah,
                       float* __restrict__ Na, float* __restrict__ No,
                       hf* __restrict__ cat16) {
    int i = blockIdx.x*blockDim.x + threadIdx.x;
    if (i < Dd*BQ*Ww) {
        int d = i / (BQ*Ww);
        int w = i % Ww;
        pah[i] = p0[w*Dd + d];
    }
    if (i < BQ*Ww) {
        int w = i % Ww, bq = i / Ww;
        float v = z0[w];
        z[i] = v;
        cat16[(long)bq*(Ee+Ww) + Ee + w] = __float2half(v);
    }
    if (i < BQ*SAa) Na[i] = 0.f;
    if (i < BQ*SOo) No[i] = 0.f;
}

__global__ void k_rope_split(const float* __restrict__ in, float* __restrict__ out,
                             int S, int do_rope) {
    int i = blockIdx.x*blockDim.x + threadIdx.x;
    if (i >= Bb*S*Ee) return;
    int d = i % HDd;
    int h = (i / HDd) % NHh;
    int s = (i / Ee) % S;
    int b = i / (Ee*S);
    const float* row = in + ((long)(b*S + s))*Ee + h*HDd;
    float v;
    if (do_rope) {
        const int half = HDd/2;
        int j = d % half;
        float inv = expf(-(float)j * (9.210340371976184f / (float)half));
        float ang = (float)s * inv;
        float c = cosf(ang), sn = sinf(ang);
        float x1 = row[j], x2 = row[j + half];
        v = (d < half) ? (x1*c - x2*sn) : (x2*c + x1*sn);
    } else {
        v = row[d];
    }
    out[(((long)(b*NHh + h))*S + s)*HDd + d] = v;
}

__global__ void __launch_bounds__(256) k_nlm(
    const float* __restrict__ pah, const float* __restrict__ w1,
    const float* __restrict__ b1, const float* __restrict__ w2,
    const float* __restrict__ b2, float* __restrict__ z,
    hf* __restrict__ cat16, int start)
{
    __shared__ float w1s[32*257];
    __shared__ float b1s[32*33];
    __shared__ float w2s[32*33];
    __shared__ float b2s[32];
    const int tid = threadIdx.x;
    const int w0 = blockIdx.x*32, bq0 = blockIdx.y*128;

    for (int j = tid; j < 32*256; j += 256) w1s[(j>>8)*257 + (j&255)] = w1[(long)w0*256 + j];
    for (int j = tid; j < 32*32;  j += 256) {
        b1s[(j>>5)*33 + (j&31)] = b1[(long)w0*32 + j];
        w2s[(j>>5)*33 + (j&31)] = w2[(long)w0*32 + j];
    }
    if (tid < 32) b2s[tid] = b2[w0 + tid];
    __syncthreads();

    const int wl = tid & 31, bql = tid >> 5;
    const int w = w0 + wl;
    for (int bq = bq0 + bql; bq < bq0 + 128; bq += 8) {
        float pv[Dd];
        #pragma unroll
        for (int d = 0; d < Dd; d++)
            pv[d] = pah[(long)((start + d) & 7)*BQ*Ww + (long)bq*Ww + w];
        float zacc = b2s[wl];
        #pragma unroll
        for (int hh = 0; hh < Hn; hh++) {
            float a = b1s[wl*33 + hh];
            #pragma unroll
            for (int d = 0; d < Dd; d++) a += pv[d]*w1s[wl*257 + d*32 + hh];
            zacc += gelu_f(a)*w2s[wl*33 + hh];
        }
        z[(long)bq*Ww + w] = zacc;
        cat16[(long)bq*(Ee+Ww) + Ee + w] = __float2half(zacc);
    }
}

// fused dual sync: sa (S=512) + so (S=1024)
__global__ void k_sync2(const float* __restrict__ z,
                        float* __restrict__ Na, float* __restrict__ No,
                        hf* __restrict__ sa, hf* __restrict__ so,
                        const int* __restrict__ ila, const int* __restrict__ ira,
                        const int* __restrict__ ilo, const int* __restrict__ iro,
                        const float* __restrict__ dec_a, const float* __restrict__ dec_o,
                        int Tn) {
    int i = blockIdx.x*blockDim.x + threadIdx.x;
    if (i >= BQ*(SAa+SOo)) return;
    int s = i % (SAa+SOo), bq = i / (SAa+SOo);
    const float* zr = z + (long)bq*Ww;
    float d, p;
    float* Nbuf; hf* syn; long idx;
    if (s < SAa) {
        d = dec_a[s];
        p = zr[ila[s]]*zr[ira[s]];
        Nbuf = Na; syn = sa; idx = (long)bq*SAa + s;
    } else {
        int so_s = s - SAa;
        d = dec_o[so_s];
        p = zr[ilo[so_s]]*zr[iro[so_s]];
        Nbuf = No; syn = so; idx = (long)bq*SOo + so_s;
    }
    float ed = __expf(-d);
    float Nn = Nbuf[idx]*ed + p;
    Nbuf[idx] = Nn;
    float den = 0.f, wgt = 1.f;
    for (int k = 0; k < Tn; k++) { den += wgt; wgt *= ed; }
    syn[idx] = __float2half(Nn * rsqrtf(den));
}

// ======================= host =======================
static void* symv(const void* s) { void* p = nullptr; cudaGetSymbolAddress(&p, s); return p; }

template<int EPI, int BM, int OMODE, int NPASS>
static void rung(const hf* A, const hf* Bh, const hf* Bl,
                 const float* bias, float* C, hf* Ch,
                 int M, int N, int K, long ldcm, long ldcn, long ldh) {
    constexpr int SM = 3*(BM*80 + NPASS*128*80);
    cudaFuncSetAttribute(hg<EPI,BM,OMODE,NPASS>, cudaFuncAttributeMaxDynamicSharedMemorySize, SM);
    dim3 g(N/128, M/BM);
    hg<EPI,BM,OMODE,NPASS><<<g, 256, SM>>>(A, Bh, Bl, bias, C, Ch, M, N, K, ldcm, ldcn, ldh);
}

extern "C" void kernel_launch(void* const* d_in, const int* in_sizes, int n_in,
                              void* d_out, int out_size) {
    (void)in_sizes; (void)n_in; (void)out_size;
    const int*   x      = (const int*)  d_in[0];
    const float* emb    = (const float*)d_in[2];
    const float* w_kv   = (const float*)d_in[3];
    const float* w_qs   = (const float*)d_in[4];
    const float* wq     = (const float*)d_in[5];
    const float* wk     = (const float*)d_in[6];
    const float* wv     = (const float*)d_in[7];
    const float* wo     = (const float*)d_in[8];
    const float* ws1    = (const float*)d_in[9];
    const float* bs1    = (const float*)d_in[10];
    const float* ws2    = (const float*)d_in[11];
    const float* bs2    = (const float*)d_in[12];
    const float* nw1    = (const float*)d_in[13];
    const float* nb1    = (const float*)d_in[14];
    const float* nw2    = (const float*)d_in[15];
    const float* nb2    = (const float*)d_in[16];
    const float* out_w  = (const float*)d_in[17];
    const float* out_b  = (const float*)d_in[18];
    const float* z_init = (const float*)d_in[19];
    const float* p_init = (const float*)d_in[20];
    const float* dec_a  = (const float*)d_in[21];
    const float* dec_o  = (const float*)d_in[22];
    const int*   idx_la = (const int*)  d_in[23];
    const int*   idx_ra = (const int*)  d_in[24];
    const int*   idx_lo = (const int*)  d_in[25];
    const int*   idx_ro = (const int*)  d_in[26];
    float* out = (float*)d_out;

    float *tmp = (float*)symv(g_tmp);
    float *qh = (float*)symv(g_qh), *kh = (float*)symv(g_kh), *vh = (float*)symv(g_vh);
    float *z = (float*)symv(g_z), *pah = (float*)symv(g_pah);
    float *Na = (float*)symv(g_Na), *No = (float*)symv(g_No);

    hf *emb16=(hf*)symv(g_emb16), *kv16=(hf*)symv(g_kv16);
    hf *cat16=(hf*)symv(g_cat16), *h116=(hf*)symv(g_h116);
    hf *sa16=(hf*)symv(g_sa16), *so16=(hf*)symv(g_so16);

    hf *wkvTh=(hf*)symv(g_wkvTh), *wkvTl=(hf*)symv(g_wkvTl);
    hf *wkTh =(hf*)symv(g_wkTh),  *wkTl =(hf*)symv(g_wkTl);
    hf *wvTh =(hf*)symv(g_wvTh),  *wvTl =(hf*)symv(g_wvTl);
    hf *ws1Th=(hf*)symv(g_ws1Th), *ws1Tl=(hf*)symv(g_ws1Tl);
    hf *wsFh =(hf*)symv(g_wsFh),  *wsFl =(hf*)symv(g_wsFl);
    hf *ws2Th=(hf*)symv(g_ws2Th), *ws2Tl=(hf*)symv(g_ws2Tl);
    hf *owTh =(hf*)symv(g_owTh),  *owTl =(hf*)symv(g_owTl);
    hf *wqTh =(hf*)symv(g_wqTh),  *wqTl =(hf*)symv(g_wqTl);
    hf *wqs16h=(hf*)symv(g_wqs16h), *wqs16l=(hf*)symv(g_wqs16l);
    hf *wo16h=(hf*)symv(g_wo16h), *wo16l=(hf*)symv(g_wo16l);
    hf *Wch  =(hf*)symv(g_Wch),   *Wcl  =(hf*)symv(g_Wcl);

    const int TPB = 256;
    dim3 wb(32, 8);

    // ---- weight prep ----
    k_wsplit16<<<dim3(Ee/32,  Ee/32),  wb>>>(w_kv,  wkvTh, wkvTl, Ee,  Ee);
    k_wsplit16<<<dim3(Ee/32,  Ee/32),  wb>>>(wk,    wkTh,  wkTl,  Ee,  Ee);
    k_wsplit16<<<dim3(Ee/32,  Ee/32),  wb>>>(wv,    wvTh,  wvTl,  Ee,  Ee);
    k_wsplit16<<<dim3(SHh/32, (Ee+Ww)/32), wb>>>(ws1, ws1Th, ws1Tl, Ee+Ww, SHh);
    k_wsplit16<<<dim3(SHh/32, (Ee+Ww)/32), wb>>>(ws1, wsFh,  wsFl,  Ee+Ww, SHh);
    k_wsplit16<<<dim3(Ww/32,  SHh/32), wb>>>(ws2,   ws2Th, ws2Tl, SHh, Ww);
    k_wsplit16<<<dim3(Vv/32,  SOo/32), wb>>>(out_w, owTh,  owTl,  SOo, Vv);
    k_wsplit16<<<dim3(Ee/32,  Ee/32),  wb>>>(wq,    wqTh,  wqTl,  Ee,  Ee);
    k_split16<<<(SAa*Ee + TPB-1)/TPB, TPB>>>(w_qs, wqs16h, wqs16l, SAa*Ee);
    k_split16<<<(Ee*Ee + TPB-1)/TPB, TPB>>>(wo, wo16h, wo16l, Ee*Ee);
    // combined W^T = wq^T @ wqs^T -> [E][SA] fp16 hi/scaled-lo (2-pass OK: used by 2-pass q)
    {
        constexpr int SM3 = 2*4*128*80;
        cudaFuncSetAttribute(hg3, cudaFuncAttributeMaxDynamicSharedMemorySize, SM3);
        // Wc = (wqT) @ (wqs)^T : A = wqT hi/lo [E,E], B = wqs split [SA rows? no: [SA,E]]
        hg3<<<dim3(SAa/128, Ee/128), 256, SM3>>>(wqTh, wqTl, wqs16h, wqs16l,
                                                 Wch, Wcl, Ee, SAa, Ee, Ee, SAa);
        // Wos^T[n=syn, c] = sum_e ws1T[n, e] * wo[c, e]  -> wsF cols 0..1023
        hg3<<<dim3(Ee/128, SHh/128), 256, SM3>>>(ws1Th, ws1Tl, wo16h, wo16l,
                                                 wsFh, wsFl, SHh, Ee, Ee, Ee+Ww, Ee+Ww);
    }

    // ---- prologue: kv, kh, vh ----
    k_gather<<<(BL*Ee + TPB-1)/TPB, TPB>>>(x, emb, emb16);
    rung<0,64,1,2>(emb16, wkvTh, wkvTl, nullptr, nullptr, kv16, BL, Ee, Ee, 0, 0, Ee);
    rung<0,64,0,2>(kv16, wkTh, wkTl, nullptr, tmp, nullptr, BL, Ee, Ee, Ee, 1, 0);
    k_rope_split<<<(Bb*Ll*Ee + TPB-1)/TPB, TPB>>>(tmp, kh, Ll, 1);
    rung<0,64,0,2>(kv16, wvTh, wvTl, nullptr, tmp, nullptr, BL, Ee, Ee, Ee, 1, 0);
    k_rope_split<<<(Bb*Ll*Ee + TPB-1)/TPB, TPB>>>(tmp, vh, Ll, 0);

    k_init<<<(Dd*BQ*Ww + TPB-1)/TPB, TPB>>>(z_init, p_init, z, pah, Na, No, cat16);
    k_sync2<<<(BQ*(SAa+SOo) + TPB-1)/TPB, TPB>>>(z, Na, No, sa16, so16,
        idx_la, idx_ra, idx_lo, idx_ro, dec_a, dec_o, 1);

    cudaFuncSetAttribute(k_fattn, cudaFuncAttributeMaxDynamicSharedMemorySize, FA_SMEM);

    // ---- T iterations ----
    for (int t = 0; t < Tt; t++) {
        // q = sa @ Wc, rope fused -> qh
        rung<0,128,3,2>(sa16, Wch, Wcl, nullptr, qh, nullptr, BQ, Ee, SAa, 0, 0, 0);
        // attention writes ctx directly into cat cols [0, Ee)
        k_fattn<<<dim3(Qq/16, NHh, Bb), 256, FA_SMEM>>>(qh, kh, vh, cat16, Ee+Ww);
        // fused synapse layer 1: h1 = gelu(cat @ wsF^T + bs1)
        rung<2,64,1,2>(cat16, wsFh, wsFl, bs1, nullptr, h116, BQ, SHh, Ee+Ww, 0, 0, SHh);
        rung<1,64,0,2>(h116, ws2Th, ws2Tl, bs2, pah + (long)t*BQ*Ww, nullptr,
                       BQ, Ww, SHh, Ww, 1, 0);
        // neuron-level models + fused sync
        k_nlm<<<dim3(Ww/32, BQ/128), 256>>>(pah, nw1, nb1, nw2, nb2, z, cat16, t + 1);
        k_sync2<<<(BQ*(SAa+SOo) + TPB-1)/TPB, TPB>>>(z, Na, No, sa16, so16,
            idx_la, idx_ra, idx_lo, idx_ro, dec_a, dec_o, t + 2);
        // logits: 1-pass fp16
        rung<1,128,0,1>(so16, owTh, owTl, out_b, out + (long)t*BQ*Vv, nullptr,
                        BQ, Vv, SOo, Vv, 1, 0);
    }
}

// round 16
// speedup vs baseline: 4.8630x; 1.2352x over previous
#include <cuda_runtime.h>
#include <cuda_bf16.h>
#include <cuda_fp16.h>
#include <math.h>
#include <stdint.h>
#include <string.h>

// ---- problem constants ----
#define Bb   2
#define Ll   512
#define Qq   512
#define Ee   1024
#define Ww   1024
#define Dd   8
#define Hn   32
#define NHh  16
#define HDd  64
#define SAa  512
#define SOo  1024
#define Vv   8192
#define Tt   6
#define SHh  2048
#define BQ   (Bb*Qq)
#define BL   (Bb*Ll)

typedef __half hf;

// ---- fp32 scratch ----
__device__ float g_tmp [BQ*Ee];
__device__ float g_z   [BQ*Ww];
__device__ float g_pah [Dd*BQ*Ww];          // 8 planes of [BQ][Ww]
__device__ float g_Na  [BQ*SAa];
__device__ float g_No  [BQ*SOo];

// ---- fp16 activations ----
__device__ hf g_emb16[BL*Ee];
__device__ hf g_kv16 [BL*Ee];
__device__ hf g_qh16 [Bb*NHh*Qq*HDd];
__device__ hf g_kh16 [Bb*NHh*Ll*HDd];
__device__ hf g_vT16 [Bb*NHh*HDd*Ll];       // V transposed per head: [d][k]
__device__ hf g_cat16[BQ*(Ee+Ww)];          // [ctx | z]
__device__ hf g_h116 [BQ*SHh];
__device__ hf g_sa16 [BQ*SAa];
__device__ hf g_so16 [BQ*SOo];

// ---- fp16 hi/scaled-lo weights ----
__device__ hf g_wkvTh[Ee*Ee],       g_wkvTl[Ee*Ee];
__device__ hf g_wkTh [Ee*Ee],       g_wkTl [Ee*Ee];
__device__ hf g_wvTh [Ee*Ee],       g_wvTl [Ee*Ee];
__device__ hf g_ws1Th[SHh*(Ee+Ww)], g_ws1Tl[SHh*(Ee+Ww)];   // ws1^T source
__device__ hf g_wsFh [SHh*(Ee+Ww)], g_wsFl [SHh*(Ee+Ww)];   // fused [Wos^T | ws1_botT]
__device__ hf g_ws2Th[Ww*SHh],      g_ws2Tl[Ww*SHh];
__device__ hf g_owTh [Vv*SOo],      g_owTl [Vv*SOo];
__device__ hf g_wqTh [Ee*Ee],       g_wqTl [Ee*Ee];
__device__ hf g_wqs16h[SAa*Ee],     g_wqs16l[SAa*Ee];
__device__ hf g_wo16h[Ee*Ee],       g_wo16l[Ee*Ee];
__device__ hf g_Wch  [Ee*SAa],      g_Wcl  [Ee*SAa];

__device__ __forceinline__ float gelu_f(float x) {
    float y = 1.5957691216057308f*(x + 0.044715f*x*x*x);
    return x / (1.0f + __expf(-y));
}

__device__ __forceinline__ uint32_t h2u(__half2 h){
    uint32_t u;
    memcpy(&u, &h, 4);
    return u;
}

// ====================== mma primitives ======================
__device__ __forceinline__ void cpa16(uint32_t s, const void* g){
    asm volatile("cp.async.cg.shared.global [%0], [%1], 16;" :: "r"(s), "l"(g));
}
__device__ __forceinline__ void cpcommit(){ asm volatile("cp.async.commit_group;" ::: "memory"); }
template<int N> __device__ __forceinline__ void cpwait(){ asm volatile("cp.async.wait_group %0;" :: "n"(N) : "memory"); }
__device__ __forceinline__ void ldmx4(uint32_t* r, uint32_t a){
    asm volatile("ldmatrix.sync.aligned.m8n8.x4.shared.b16 {%0,%1,%2,%3}, [%4];"
        : "=r"(r[0]),"=r"(r[1]),"=r"(r[2]),"=r"(r[3]) : "r"(a));
}
__device__ __forceinline__ void mma_fp16(float* c, const uint32_t* a, uint32_t b0, uint32_t b1){
    asm volatile("mma.sync.aligned.m16n8k16.row.col.f32.f16.f16.f32 "
        "{%0,%1,%2,%3}, {%4,%5,%6,%7}, {%8,%9}, {%0,%1,%2,%3};"
        : "+f"(c[0]),"+f"(c[1]),"+f"(c[2]),"+f"(c[3])
        : "r"(a[0]),"r"(a[1]),"r"(a[2]),"r"(a[3]), "r"(b0),"r"(b1));
}

// ============ fp16 GEMM, 3-stage cp.async ============
// C(M,N) = epi(A @ B^T [+bias]); A fp16 [M,K]; Bh=fp16(B), Bl=fp16((B-Bh)*1024), [N,K].
// NPASS=2: result = acc1 + acc2/1024. NPASS=1: hi-only.
// EPI: 0 none, 1 +bias, 2 gelu(+bias)
// OMODE: 0 fp32 C, 1 fp16 single out (ldh), 3 rope(*0.125)->qh16
template<int EPI, int BM, int OMODE, int NPASS>
__global__ void __launch_bounds__(256, (BM==64)?2:1) hg(
    const hf* __restrict__ A,
    const hf* __restrict__ Bh, const hf* __restrict__ Bl,
    const float* __restrict__ bias,
    float* __restrict__ C, hf* __restrict__ Ch,
    int M, int N, int K, long ldcm, long ldcn, long ldh)
{
    constexpr int WMW = BM/32;
    constexpr int WNW = 8/WMW;
    constexpr int WARP_N = 128/WNW;
    constexpr int NJ = WARP_N/8;
    constexpr int TILE_A = BM*80;
    constexpr int TILE_B = 128*80;
    constexpr int STAGE = TILE_A + NPASS*TILE_B;

    extern __shared__ __align__(16) char dyn[];
    const int tid  = threadIdx.x;
    const int wid  = tid >> 5, lane = tid & 31;
    const int bm = blockIdx.y*BM, bn = blockIdx.x*128;
    const int wm = wid % WMW, wn = wid / WMW;

    uint32_t sbase = (uint32_t)__cvta_generic_to_shared(dyn);

    const hf* gA  = A  + (long)bm*K;
    const hf* gBh = Bh + (long)bn*K;
    const hf* gBl = Bl + (long)bn*K;

    auto load_stage = [&](int st, int k0){
        uint32_t s0 = sbase + st*STAGE;
        #pragma unroll
        for (int c = 0; c < BM/64; ++c) {
            int ch = tid + c*256;
            int row = ch >> 2, seg = ch & 3;
            cpa16(s0 + row*80 + seg*16, gA + (long)row*K + k0 + seg*8);
        }
        #pragma unroll
        for (int c = 0; c < 2; ++c) {
            int ch = tid + c*256;
            int row = ch >> 2, seg = ch & 3;
            cpa16(s0 + TILE_A + row*80 + seg*16, gBh + (long)row*K + k0 + seg*8);
            if (NPASS == 2)
                cpa16(s0 + TILE_A + TILE_B + row*80 + seg*16, gBl + (long)row*K + k0 + seg*8);
        }
    };

    float acc1[2][NJ][4], acc2[2][NJ][4];
    #pragma unroll
    for (int i = 0; i < 2; i++)
        #pragma unroll
        for (int j = 0; j < NJ; j++)
            #pragma unroll
            for (int q = 0; q < 4; q++) { acc1[i][j][q] = 0.f; acc2[i][j][q] = 0.f; }

    const int NC = K >> 5;
    load_stage(0, 0); cpcommit();
    if (NC > 1) { load_stage(1, 32); cpcommit(); }

    const int l = lane & 7, sel = lane >> 3;
    const int rofs = l + ((sel & 1) << 3);
    const int cofs = (sel >> 1) << 3;

    for (int c = 0; c < NC; ++c) {
        if (c + 2 < NC) { load_stage((c+2)%3, (c+2)*32); cpcommit(); cpwait<2>(); }
        else if (c + 1 < NC) cpwait<1>();
        else cpwait<0>();
        __syncthreads();

        uint32_t s0  = sbase + (c%3)*STAGE;
        uint32_t sA = s0, sBh = s0 + TILE_A, sBl = sBh + TILE_B;

        #pragma unroll
        for (int k16 = 0; k16 < 2; ++k16) {
            int colo = k16*16 + cofs;
            uint32_t a[2][4];
            #pragma unroll
            for (int mi = 0; mi < 2; ++mi) {
                uint32_t off = (uint32_t)((wm*32 + mi*16 + rofs)*40 + colo)*2;
                ldmx4(a[mi], sA + off);
            }
            uint32_t bhf[NJ/2][4], blf[NJ/2][4];
            #pragma unroll
            for (int ni = 0; ni < NJ/2; ++ni) {
                uint32_t off = (uint32_t)((wn*WARP_N + ni*16 + rofs)*40 + colo)*2;
                ldmx4(bhf[ni], sBh + off);
                if (NPASS == 2) ldmx4(blf[ni], sBl + off);
            }
            #pragma unroll
            for (int mi = 0; mi < 2; ++mi)
                #pragma unroll
                for (int nj = 0; nj < NJ; ++nj) {
                    int g = nj >> 1, h8 = nj & 1;
                    mma_fp16(acc1[mi][nj], a[mi], bhf[g][h8], bhf[g][h8+2]);
                    if (NPASS == 2) mma_fp16(acc2[mi][nj], a[mi], blf[g][h8], blf[g][h8+2]);
                }
        }
        __syncthreads();
    }

    const float SC = 1.f/1024.f;
    const int tr = lane >> 2, tc = (lane & 3)*2;

    if (OMODE == 3) {
        // rope epilogue *0.125 -> qh16[(b*NH+h)*512 + s][64]; BM=128 (WARP_N=64)
        #pragma unroll
        for (int mi = 0; mi < 2; ++mi)
            #pragma unroll
            for (int njl = 0; njl < NJ/2; ++njl) {
                float vlo[4], vhi[4];
                #pragma unroll
                for (int q = 0; q < 4; ++q) {
                    vlo[q] = acc1[mi][njl][q]      + acc2[mi][njl][q]*SC;
                    vhi[q] = acc1[mi][njl+NJ/2][q] + acc2[mi][njl+NJ/2][q]*SC;
                }
                #pragma unroll
                for (int r = 0; r < 2; ++r)
                    #pragma unroll
                    for (int cc = 0; cc < 2; ++cc) {
                        int m = bm + wm*32 + mi*16 + tr + r*8;
                        int s = m & 511, bb = m >> 9;
                        int hh = (bn + wn*WARP_N) >> 6;
                        int j = njl*8 + tc + cc;
                        float inv = expf(-(float)j * (9.210340371976184f/32.f));
                        float ang = (float)s * inv;
                        float sn, cs;
                        sincosf(ang, &sn, &cs);
                        float x1 = vlo[r*2+cc], x2 = vhi[r*2+cc];
                        long base = (((long)(bb*NHh + hh))*512 + s)*64;
                        Ch[base + j]      = __float2half((x1*cs - x2*sn)*0.125f);
                        Ch[base + j + 32] = __float2half((x2*cs + x1*sn)*0.125f);
                    }
            }
        return;
    }

    #pragma unroll
    for (int mi = 0; mi < 2; ++mi) {
        #pragma unroll
        for (int nj = 0; nj < NJ; ++nj) {
            int m0 = bm + wm*32 + mi*16 + tr;
            int n0 = bn + wn*WARP_N + nj*8 + tc;
            float v[4];
            #pragma unroll
            for (int q = 0; q < 4; ++q)
                v[q] = (NPASS == 2) ? (acc1[mi][nj][q] + acc2[mi][nj][q]*SC) : acc1[mi][nj][q];
            if (EPI >= 1) {
                float b0 = __ldg(bias + n0), b1 = __ldg(bias + n0 + 1);
                v[0] += b0; v[1] += b1; v[2] += b0; v[3] += b1;
            }
            if (EPI == 2) {
                v[0] = gelu_f(v[0]); v[1] = gelu_f(v[1]);
                v[2] = gelu_f(v[2]); v[3] = gelu_f(v[3]);
            }
            if (OMODE == 1) {
                #pragma unroll
                for (int rr = 0; rr < 2; ++rr) {
                    long base = (long)(m0 + rr*8)*ldh + n0;
                    __half2 hh;
                    hh.x = __float2half(v[rr*2+0]);
                    hh.y = __float2half(v[rr*2+1]);
                    *reinterpret_cast<__half2*>(Ch + base) = hh;
                }
            } else if (ldcn == 1) {
                *(float2*)(C + (long)m0*ldcm + n0)     = make_float2(v[0], v[1]);
                *(float2*)(C + (long)(m0+8)*ldcm + n0) = make_float2(v[2], v[3]);
            } else {
                C[(long)m0*ldcm     + (long)n0*ldcn]     = v[0];
                C[(long)m0*ldcm     + (long)(n0+1)*ldcn] = v[1];
                C[(long)(m0+8)*ldcm + (long)n0*ldcn]     = v[2];
                C[(long)(m0+8)*ldcm + (long)(n0+1)*ldcn] = v[3];
            }
        }
    }
}

// ===== prep 3-pass GEMM: A hi/lo, B hi/lo -> fp16 hi/scaled-lo out (ldh) =====
__global__ void __launch_bounds__(256, 1) hg3(
    const hf* __restrict__ Ah, const hf* __restrict__ Al,
    const hf* __restrict__ Bh, const hf* __restrict__ Bl,
    hf* __restrict__ Ch, hf* __restrict__ Cl,
    int M, int N, int K, long lda, long ldh)
{
    constexpr int TILE = 128*80;
    constexpr int STAGE = 4*TILE;
    extern __shared__ __align__(16) char dyn[];
    const int tid  = threadIdx.x;
    const int wid  = tid >> 5, lane = tid & 31;
    const int bm = blockIdx.y*128, bn = blockIdx.x*128;
    const int wm = wid & 3, wn = wid >> 2;

    uint32_t sbase = (uint32_t)__cvta_generic_to_shared(dyn);
    const hf* gAh = Ah + (long)bm*lda;
    const hf* gAl = Al + (long)bm*lda;
    const hf* gBh = Bh + (long)bn*K;
    const hf* gBl = Bl + (long)bn*K;

    auto load_stage = [&](int st, int k0){
        uint32_t s0 = sbase + st*STAGE;
        #pragma unroll
        for (int c = 0; c < 2; ++c) {
            int ch = tid + c*256;
            int row = ch >> 2, seg = ch & 3;
            cpa16(s0 + row*80 + seg*16,          gAh + (long)row*lda + k0 + seg*8);
            cpa16(s0 + TILE   + row*80 + seg*16, gAl + (long)row*lda + k0 + seg*8);
            cpa16(s0 + 2*TILE + row*80 + seg*16, gBh + (long)row*K + k0 + seg*8);
            cpa16(s0 + 3*TILE + row*80 + seg*16, gBl + (long)row*K + k0 + seg*8);
        }
    };

    float acc1[2][8][4], acc2[2][8][4];
    #pragma unroll
    for (int i = 0; i < 2; i++)
        #pragma unroll
        for (int j = 0; j < 8; j++)
            #pragma unroll
            for (int q = 0; q < 4; q++) { acc1[i][j][q] = 0.f; acc2[i][j][q] = 0.f; }

    const int NC = K >> 5;
    load_stage(0, 0); cpcommit();

    const int l = lane & 7, sel = lane >> 3;
    const int rofs = l + ((sel & 1) << 3);
    const int cofs = (sel >> 1) << 3;

    for (int c = 0; c < NC; ++c) {
        if (c + 1 < NC) { load_stage((c+1)&1, (c+1)*32); cpcommit(); cpwait<1>(); }
        else cpwait<0>();
        __syncthreads();
        uint32_t s0 = sbase + (c&1)*STAGE;
        uint32_t sAh = s0, sAl = s0 + TILE, sBh = s0 + 2*TILE, sBl = s0 + 3*TILE;
        #pragma unroll
        for (int k16 = 0; k16 < 2; ++k16) {
            int colo = k16*16 + cofs;
            uint32_t ah[2][4], al[2][4];
            #pragma unroll
            for (int mi = 0; mi < 2; ++mi) {
                uint32_t off = (uint32_t)((wm*32 + mi*16 + rofs)*40 + colo)*2;
                ldmx4(ah[mi], sAh + off);
                ldmx4(al[mi], sAl + off);
            }
            uint32_t bh[4][4], bl[4][4];
            #pragma unroll
            for (int ni = 0; ni < 4; ++ni) {
                uint32_t off = (uint32_t)((wn*64 + ni*16 + rofs)*40 + colo)*2;
                ldmx4(bh[ni], sBh + off);
                ldmx4(bl[ni], sBl + off);
            }
            #pragma unroll
            for (int mi = 0; mi < 2; ++mi)
                #pragma unroll
                for (int nj = 0; nj < 8; ++nj) {
                    int g = nj >> 1, h8 = nj & 1;
                    mma_fp16(acc1[mi][nj], ah[mi], bh[g][h8], bh[g][h8+2]);
                    mma_fp16(acc2[mi][nj], ah[mi], bl[g][h8], bl[g][h8+2]);
                    mma_fp16(acc2[mi][nj], al[mi], bh[g][h8], bh[g][h8+2]);
                }
        }
        __syncthreads();
    }

    const float SC = 1.f/1024.f;
    const int tr = lane >> 2, tc = (lane & 3)*2;
    #pragma unroll
    for (int mi = 0; mi < 2; ++mi)
        #pragma unroll
        for (int nj = 0; nj < 8; ++nj) {
            int m0 = bm + wm*32 + mi*16 + tr;
            int n0 = bn + wn*64 + nj*8 + tc;
            float v[4];
            #pragma unroll
            for (int q = 0; q < 4; ++q) v[q] = acc1[mi][nj][q] + acc2[mi][nj][q]*SC;
            #pragma unroll
            for (int rr = 0; rr < 2; ++rr) {
                long base = (long)(m0 + rr*8)*ldh + n0;
                hf h0 = __float2half(v[rr*2+0]);
                hf h1 = __float2half(v[rr*2+1]);
                hf l0 = __float2half((v[rr*2+0] - __half2float(h0))*1024.f);
                hf l1 = __float2half((v[rr*2+1] - __half2float(h1))*1024.f);
                __half2 hh; hh.x = h0; hh.y = h1;
                __half2 llv; llv.x = l0; llv.y = l1;
                *reinterpret_cast<__half2*>(Ch + base) = hh;
                *reinterpret_cast<__half2*>(Cl + base) = llv;
            }
        }
}

// ============== tensor-core flash attention ==============
// 64 queries per block, one (h,b). Q scaled by 1/8 at creation.
// Q/K [row][dim] fp16, V^T [dim][key] fp16; output -> cat16 cols [0,Ee)
#define AT_STR 72

__global__ void __launch_bounds__(128) k_fattn2(
    const hf* __restrict__ qh, const hf* __restrict__ kh,
    const hf* __restrict__ vt, hf* __restrict__ dst, int ldd)
{
    __shared__ hf sQ[64*AT_STR];
    __shared__ hf sK[2][64*AT_STR];
    __shared__ hf sV[2][64*AT_STR];

    const int tid = threadIdx.x;
    const int wid = tid >> 5, lane = tid & 31;
    const int q0 = blockIdx.x*64, h = blockIdx.y, b = blockIdx.z;
    const long bh = b*NHh + h;

    const hf* gQ = qh + (bh*Qq + q0)*HDd;
    const hf* gK = kh + bh*Ll*HDd;
    const hf* gV = vt + bh*HDd*Ll;

    uint32_t sQa = (uint32_t)__cvta_generic_to_shared(sQ);
    uint32_t sKa = (uint32_t)__cvta_generic_to_shared(sK);
    uint32_t sVa = (uint32_t)__cvta_generic_to_shared(sV);

    for (int i = tid; i < 512; i += 128) {
        int row = i >> 3, seg = i & 7;
        cpa16(sQa + (row*AT_STR + seg*8)*2, gQ + row*HDd + seg*8);
    }
    auto loadKV = [&](int st, int c){
        uint32_t k0 = sKa + st*64*AT_STR*2;
        uint32_t v0 = sVa + st*64*AT_STR*2;
        for (int i = tid; i < 512; i += 128) {
            int row = i >> 3, seg = i & 7;
            cpa16(k0 + (row*AT_STR + seg*8)*2, gK + (long)(c*64 + row)*HDd + seg*8);
            cpa16(v0 + (row*AT_STR + seg*8)*2, gV + (long)row*Ll + c*64 + seg*8);
        }
    };

    const int NC = blockIdx.x + 1;
    loadKV(0, 0); cpcommit();
    if (NC > 1) { loadKV(1, 1); cpcommit(); }

    const int l = lane & 7, sel = lane >> 3;
    const int rofs = l + ((sel & 1) << 3);
    const int cofs = (sel >> 1) << 3;
    const int tr = lane >> 2, tc = (lane & 3)*2;

    float O[8][4];
    #pragma unroll
    for (int i = 0; i < 8; i++)
        #pragma unroll
        for (int q = 0; q < 4; q++) O[i][q] = 0.f;
    float mrun0 = -1e30f, mrun1 = -1e30f, sum0 = 0.f, sum1 = 0.f;
    uint32_t aq[4][4];

    const int rowg0 = q0 + wid*16 + tr, rowg1 = rowg0 + 8;

    for (int c = 0; c < NC; ++c) {
        if (c + 1 < NC) cpwait<1>(); else cpwait<0>();
        __syncthreads();
        if (c == 0) {
            #pragma unroll
            for (int g = 0; g < 4; ++g)
                ldmx4(aq[g], sQa + ((wid*16 + rofs)*AT_STR + g*16 + cofs)*2);
        }
        uint32_t kb = sKa + (c&1)*64*AT_STR*2;
        uint32_t vb = sVa + (c&1)*64*AT_STR*2;

        float S[8][4];
        #pragma unroll
        for (int i = 0; i < 8; i++)
            #pragma unroll
            for (int q = 0; q < 4; q++) S[i][q] = 0.f;

        #pragma unroll
        for (int g = 0; g < 4; ++g) {
            #pragma unroll
            for (int nt = 0; nt < 4; ++nt) {
                uint32_t bk[4];
                ldmx4(bk, kb + ((nt*16 + rofs)*AT_STR + g*16 + cofs)*2);
                mma_fp16(S[2*nt],   aq[g], bk[0], bk[2]);
                mma_fp16(S[2*nt+1], aq[g], bk[1], bk[3]);
            }
        }

        if (c == NC - 1) {   // diagonal chunk mask
            #pragma unroll
            for (int nj = 0; nj < 8; ++nj) {
                int colg = c*64 + nj*8 + tc;
                if (colg     > rowg0) S[nj][0] = -1e30f;
                if (colg + 1 > rowg0) S[nj][1] = -1e30f;
                if (colg     > rowg1) S[nj][2] = -1e30f;
                if (colg + 1 > rowg1) S[nj][3] = -1e30f;
            }
        }

        float mx0 = -1e30f, mx1 = -1e30f;
        #pragma unroll
        for (int nj = 0; nj < 8; ++nj) {
            mx0 = fmaxf(mx0, fmaxf(S[nj][0], S[nj][1]));
            mx1 = fmaxf(mx1, fmaxf(S[nj][2], S[nj][3]));
        }
        mx0 = fmaxf(mx0, __shfl_xor_sync(0xffffffffu, mx0, 1));
        mx0 = fmaxf(mx0, __shfl_xor_sync(0xffffffffu, mx0, 2));
        mx1 = fmaxf(mx1, __shfl_xor_sync(0xffffffffu, mx1, 1));
        mx1 = fmaxf(mx1, __shfl_xor_sync(0xffffffffu, mx1, 2));
        float mn0 = fmaxf(mrun0, mx0), mn1 = fmaxf(mrun1, mx1);
        float sc0 = __expf(mrun0 - mn0), sc1 = __expf(mrun1 - mn1);
        mrun0 = mn0; mrun1 = mn1;

        float ps0 = 0.f, ps1 = 0.f;
        uint32_t Ph[8][2];
        #pragma unroll
        for (int nj = 0; nj < 8; ++nj) {
            float p0 = __expf(S[nj][0] - mn0), p1 = __expf(S[nj][1] - mn0);
            float p2 = __expf(S[nj][2] - mn1), p3 = __expf(S[nj][3] - mn1);
            ps0 += p0 + p1; ps1 += p2 + p3;
            Ph[nj][0] = h2u(__floats2half2_rn(p0, p1));
            Ph[nj][1] = h2u(__floats2half2_rn(p2, p3));
        }
        sum0 = sum0*sc0 + ps0;
        sum1 = sum1*sc1 + ps1;
        #pragma unroll
        for (int nt = 0; nt < 8; ++nt) {
            O[nt][0] *= sc0; O[nt][1] *= sc0;
            O[nt][2] *= sc1; O[nt][3] *= sc1;
        }

        #pragma unroll
        for (int g = 0; g < 4; ++g) {     // k16 over keys
            uint32_t aP[4] = { Ph[2*g][0], Ph[2*g][1], Ph[2*g+1][0], Ph[2*g+1][1] };
            #pragma unroll
            for (int nt = 0; nt < 4; ++nt) {
                uint32_t bv[4];
                ldmx4(bv, vb + ((nt*16 + rofs)*AT_STR + g*16 + cofs)*2);
                mma_fp16(O[2*nt],   aP, bv[0], bv[2]);
                mma_fp16(O[2*nt+1], aP, bv[1], bv[3]);
            }
        }
        __syncthreads();
        if (c + 2 < NC) { loadKV(c & 1, c + 2); cpcommit(); }
    }

    sum0 += __shfl_xor_sync(0xffffffffu, sum0, 1);
    sum0 += __shfl_xor_sync(0xffffffffu, sum0, 2);
    sum1 += __shfl_xor_sync(0xffffffffu, sum1, 1);
    sum1 += __shfl_xor_sync(0xffffffffu, sum1, 2);
    const float i0 = 1.f/sum0, i1 = 1.f/sum1;

    long r0 = (long)(b*Qq + rowg0)*ldd + h*HDd;
    long r1 = r0 + 8*ldd;
    #pragma unroll
    for (int nt = 0; nt < 8; ++nt) {
        int col = nt*8 + tc;
        *reinterpret_cast<__half2*>(dst + r0 + col) = __floats2half2_rn(O[nt][0]*i0, O[nt][1]*i0);
        *reinterpret_cast<__half2*>(dst + r1 + col) = __floats2half2_rn(O[nt][2]*i1, O[nt][3]*i1);
    }
}

// ======================= small kernels =======================
__global__ void k_wsplit16(const float* __restrict__ w, hf* __restrict__ hi,
                           hf* __restrict__ lo, int K, int N) {
    __shared__ float t[32][33];
    int k0 = blockIdx.y*32, n0 = blockIdx.x*32;
    for (int r = threadIdx.y; r < 32; r += 8)
        t[r][threadIdx.x] = w[(long)(k0+r)*N + n0 + threadIdx.x];
    __syncthreads();
    for (int r = threadIdx.y; r < 32; r += 8) {
        float v = t[threadIdx.x][r];
        hf h = __float2half(v);
        long o = (long)(n0+r)*K + k0 + threadIdx.x;
        hi[o] = h;
        lo[o] = __float2half((v - __half2float(h))*1024.f);
    }
}

__global__ void k_split16(const float* __restrict__ in, hf* __restrict__ hi,
                          hf* __restrict__ lo, int n) {
    int i = blockIdx.x*blockDim.x + threadIdx.x;
    if (i >= n) return;
    float v = in[i];
    hf h = __float2half(v);
    hi[i] = h;
    lo[i] = __float2half((v - __half2float(h))*1024.f);
}

__global__ void k_gather(const int* __restrict__ x, const float* __restrict__ emb,
                         hf* __restrict__ o16) {
    int i = blockIdx.x*blockDim.x + threadIdx.x;
    if (i >= BL*Ee) return;
    int e = i % Ee, bl = i / Ee;
    o16[i] = __float2half(emb[(long)x[bl]*Ee + e]);
}

__global__ void k_init(const float* __restrict__ z0, const float* __restrict__ p0,
                       float* __restrict__ z, float* __restrict__ pah,
                       float* __restrict__ Na, float* __restrict__ No,
                       hf* __restrict__ cat16) {
    int i = blockIdx.x*blockDim.x + threadIdx.x;
    if (i < Dd*BQ*Ww) {
        int d = i / (BQ*Ww);
        int w = i % Ww;
        pah[i] = p0[w*Dd + d];
    }
    if (i < BQ*Ww) {
        int w = i % Ww, bq = i / Ww;
        float v = z0[w];
        z[i] = v;
        cat16[(long)bq*(Ee+Ww) + Ee + w] = __float2half(v);
    }
    if (i < BQ*SAa) Na[i] = 0.f;
    if (i < BQ*SOo) No[i] = 0.f;
}

// K rope: fp32 proj (B,S,E) -> fp16 kh16 (B,NH,S,HD)
__global__ void k_ropeK(const float* __restrict__ in, hf* __restrict__ out) {
    int i = blockIdx.x*blockDim.x + threadIdx.x;
    if (i >= Bb*Ll*Ee) return;
    int d = i % HDd;
    int h = (i / HDd) % NHh;
    int s = (i / Ee) % Ll;
    int b = i / (Ee*Ll);
    const float* row = in + ((long)(b*Ll + s))*Ee + h*HDd;
    const int half = HDd/2;
    int j = d % half;
    float inv = expf(-(float)j * (9.210340371976184f / (float)half));
    float ang = (float)s * inv;
    float c = cosf(ang), sn = sinf(ang);
    float x1 = row[j], x2 = row[j + half];
    float v = (d < half) ? (x1*c - x2*sn) : (x2*c + x1*sn);
    out[(((long)(b*NHh + h))*Ll + s)*HDd + d] = __float2half(v);
}

// V transpose: fp32 proj (B,S,E) -> fp16 vT (B,NH,HD,S)
__global__ void k_vtrans(const float* __restrict__ in, hf* __restrict__ out) {
    __shared__ float t[32][33];
    int s0 = blockIdx.x*32;
    int d0 = (blockIdx.y & 1)*32;
    int bh = blockIdx.y >> 1;
    int b = bh >> 4, h = bh & 15;
    for (int r = threadIdx.y; r < 32; r += 8)
        t[r][threadIdx.x] = in[((long)(b*Ll + s0 + r))*Ee + h*HDd + d0 + threadIdx.x];
    __syncthreads();
    for (int r = threadIdx.y; r < 32; r += 8)
        out[(((long)bh)*HDd + d0 + r)*Ll + s0 + threadIdx.x] = __float2half(t[threadIdx.x][r]);
}

__global__ void __launch_bounds__(256) k_nlm(
    const float* __restrict__ pah, const float* __restrict__ w1,
    const float* __restrict__ b1, const float* __restrict__ w2,
    const float* __restrict__ b2, float* __restrict__ z,
    hf* __restrict__ cat16, int start)
{
    __shared__ float w1s[32*257];
    __shared__ float b1s[32*33];
    __shared__ float w2s[32*33];
    __shared__ float b2s[32];
    const int tid = threadIdx.x;
    const int w0 = blockIdx.x*32, bq0 = blockIdx.y*128;

    for (int j = tid; j < 32*256; j += 256) w1s[(j>>8)*257 + (j&255)] = w1[(long)w0*256 + j];
    for (int j = tid; j < 32*32;  j += 256) {
        b1s[(j>>5)*33 + (j&31)] = b1[(long)w0*32 + j];
        w2s[(j>>5)*33 + (j&31)] = w2[(long)w0*32 + j];
    }
    if (tid < 32) b2s[tid] = b2[w0 + tid];
    __syncthreads();

    const int wl = tid & 31, bql = tid >> 5;
    const int w = w0 + wl;
    for (int bq = bq0 + bql; bq < bq0 + 128; bq += 8) {
        float pv[Dd];
        #pragma unroll
        for (int d = 0; d < Dd; d++)
            pv[d] = pah[(long)((start + d) & 7)*BQ*Ww + (long)bq*Ww + w];
        float zacc = b2s[wl];
        #pragma unroll
        for (int hh = 0; hh < Hn; hh++) {
            float a = b1s[wl*33 + hh];
            #pragma unroll
            for (int d = 0; d < Dd; d++) a += pv[d]*w1s[wl*257 + d*32 + hh];
            zacc += gelu_f(a)*w2s[wl*33 + hh];
        }
        z[(long)bq*Ww + w] = zacc;
        cat16[(long)bq*(Ee+Ww) + Ee + w] = __float2half(zacc);
    }
}

__global__ void k_sync2(const float* __restrict__ z,
                        float* __restrict__ Na, float* __restrict__ No,
                        hf* __restrict__ sa, hf* __restrict__ so,
                        const int* __restrict__ ila, const int* __restrict__ ira,
                        const int* __restrict__ ilo, const int* __restrict__ iro,
                        const float* __restrict__ dec_a, const float* __restrict__ dec_o,
                        int Tn) {
    int i = blockIdx.x*blockDim.x + threadIdx.x;
    if (i >= BQ*(SAa+SOo)) return;
    int s = i % (SAa+SOo), bq = i / (SAa+SOo);
    const float* zr = z + (long)bq*Ww;
    float d, p;
    float* Nbuf; hf* syn; long idx;
    if (s < SAa) {
        d = dec_a[s];
        p = zr[ila[s]]*zr[ira[s]];
        Nbuf = Na; syn = sa; idx = (long)bq*SAa + s;
    } else {
        int so_s = s - SAa;
        d = dec_o[so_s];
        p = zr[ilo[so_s]]*zr[iro[so_s]];
        Nbuf = No; syn = so; idx = (long)bq*SOo + so_s;
    }
    float ed = __expf(-d);
    float Nn = Nbuf[idx]*ed + p;
    Nbuf[idx] = Nn;
    float den = 0.f, wgt = 1.f;
    for (int k = 0; k < Tn; k++) { den += wgt; wgt *= ed; }
    syn[idx] = __float2half(Nn * rsqrtf(den));
}

// ======================= host =======================
static void* symv(const void* s) { void* p = nullptr; cudaGetSymbolAddress(&p, s); return p; }

template<int EPI, int BM, int OMODE, int NPASS>
static void rung(const hf* A, const hf* Bh, const hf* Bl,
                 const float* bias, float* C, hf* Ch,
                 int M, int N, int K, long ldcm, long ldcn, long ldh) {
    constexpr int SM = 3*(BM*80 + NPASS*128*80);
    cudaFuncSetAttribute(hg<EPI,BM,OMODE,NPASS>, cudaFuncAttributeMaxDynamicSharedMemorySize, SM);
    dim3 g(N/128, M/BM);
    hg<EPI,BM,OMODE,NPASS><<<g, 256, SM>>>(A, Bh, Bl, bias, C, Ch, M, N, K, ldcm, ldcn, ldh);
}

extern "C" void kernel_launch(void* const* d_in, const int* in_sizes, int n_in,
                              void* d_out, int out_size) {
    (void)in_sizes; (void)n_in; (void)out_size;
    const int*   x      = (const int*)  d_in[0];
    const float* emb    = (const float*)d_in[2];
    const float* w_kv   = (const float*)d_in[3];
    const float* w_qs   = (const float*)d_in[4];
    const float* wq     = (const float*)d_in[5];
    const float* wk     = (const float*)d_in[6];
    const float* wv     = (const float*)d_in[7];
    const float* wo     = (const float*)d_in[8];
    const float* ws1    = (const float*)d_in[9];
    const float* bs1    = (const float*)d_in[10];
    const float* ws2    = (const float*)d_in[11];
    const float* bs2    = (const float*)d_in[12];
    const float* nw1    = (const float*)d_in[13];
    const float* nb1    = (const float*)d_in[14];
    const float* nw2    = (const float*)d_in[15];
    const float* nb2    = (const float*)d_in[16];
    const float* out_w  = (const float*)d_in[17];
    const float* out_b  = (const float*)d_in[18];
    const float* z_init = (const float*)d_in[19];
    const float* p_init = (const float*)d_in[20];
    const float* dec_a  = (const float*)d_in[21];
    const float* dec_o  = (const float*)d_in[22];
    const int*   idx_la = (const int*)  d_in[23];
    const int*   idx_ra = (const int*)  d_in[24];
    const int*   idx_lo = (const int*)  d_in[25];
    const int*   idx_ro = (const int*)  d_in[26];
    float* out = (float*)d_out;

    float *tmp = (float*)symv(g_tmp);
    float *z = (float*)symv(g_z), *pah = (float*)symv(g_pah);
    float *Na = (float*)symv(g_Na), *No = (float*)symv(g_No);

    hf *emb16=(hf*)symv(g_emb16), *kv16=(hf*)symv(g_kv16);
    hf *qh16=(hf*)symv(g_qh16), *kh16=(hf*)symv(g_kh16), *vT16=(hf*)symv(g_vT16);
    hf *cat16=(hf*)symv(g_cat16), *h116=(hf*)symv(g_h116);
    hf *sa16=(hf*)symv(g_sa16), *so16=(hf*)symv(g_so16);

    hf *wkvTh=(hf*)symv(g_wkvTh), *wkvTl=(hf*)symv(g_wkvTl);
    hf *wkTh =(hf*)symv(g_wkTh),  *wkTl =(hf*)symv(g_wkTl);
    hf *wvTh =(hf*)symv(g_wvTh),  *wvTl =(hf*)symv(g_wvTl);
    hf *ws1Th=(hf*)symv(g_ws1Th), *ws1Tl=(hf*)symv(g_ws1Tl);
    hf *wsFh =(hf*)symv(g_wsFh),  *wsFl =(hf*)symv(g_wsFl);
    hf *ws2Th=(hf*)symv(g_ws2Th), *ws2Tl=(hf*)symv(g_ws2Tl);
    hf *owTh =(hf*)symv(g_owTh),  *owTl =(hf*)symv(g_owTl);
    hf *wqTh =(hf*)symv(g_wqTh),  *wqTl =(hf*)symv(g_wqTl);
    hf *wqs16h=(hf*)symv(g_wqs16h), *wqs16l=(hf*)symv(g_wqs16l);
    hf *wo16h=(hf*)symv(g_wo16h), *wo16l=(hf*)symv(g_wo16l);
    hf *Wch  =(hf*)symv(g_Wch),   *Wcl  =(hf*)symv(g_Wcl);

    const int TPB = 256;
    dim3 wb(32, 8);

    // ---- weight prep ----
    k_wsplit16<<<dim3(Ee/32,  Ee/32),  wb>>>(w_kv,  wkvTh, wkvTl, Ee,  Ee);
    k_wsplit16<<<dim3(Ee/32,  Ee/32),  wb>>>(wk,    wkTh,  wkTl,  Ee,  Ee);
    k_wsplit16<<<dim3(Ee/32,  Ee/32),  wb>>>(wv,    wvTh,  wvTl,  Ee,  Ee);
    k_wsplit16<<<dim3(SHh/32, (Ee+Ww)/32), wb>>>(ws1, ws1Th, ws1Tl, Ee+Ww, SHh);
    k_wsplit16<<<dim3(SHh/32, (Ee+Ww)/32), wb>>>(ws1, wsFh,  wsFl,  Ee+Ww, SHh);
    k_wsplit16<<<dim3(Ww/32,  SHh/32), wb>>>(ws2,   ws2Th, ws2Tl, SHh, Ww);
    k_wsplit16<<<dim3(Vv/32,  SOo/32), wb>>>(out_w, owTh,  owTl,  SOo, Vv);
    k_wsplit16<<<dim3(Ee/32,  Ee/32),  wb>>>(wq,    wqTh,  wqTl,  Ee,  Ee);
    k_split16<<<(SAa*Ee + TPB-1)/TPB, TPB>>>(w_qs, wqs16h, wqs16l, SAa*Ee);
    k_split16<<<(Ee*Ee + TPB-1)/TPB, TPB>>>(wo, wo16h, wo16l, Ee*Ee);
    {
        constexpr int SM3 = 2*4*128*80;
        cudaFuncSetAttribute(hg3, cudaFuncAttributeMaxDynamicSharedMemorySize, SM3);
        hg3<<<dim3(SAa/128, Ee/128), 256, SM3>>>(wqTh, wqTl, wqs16h, wqs16l,
                                                 Wch, Wcl, Ee, SAa, Ee, Ee, SAa);
        hg3<<<dim3(Ee/128, SHh/128), 256, SM3>>>(ws1Th, ws1Tl, wo16h, wo16l,
                                                 wsFh, wsFl, SHh, Ee, Ee, Ee+Ww, Ee+Ww);
    }

    // ---- prologue: kv, kh16, vT16 ----
    k_gather<<<(BL*Ee + TPB-1)/TPB, TPB>>>(x, emb, emb16);
    rung<0,64,1,2>(emb16, wkvTh, wkvTl, nullptr, nullptr, kv16, BL, Ee, Ee, 0, 0, Ee);
    rung<0,64,0,2>(kv16, wkTh, wkTl, nullptr, tmp, nullptr, BL, Ee, Ee, Ee, 1, 0);
    k_ropeK<<<(Bb*Ll*Ee + TPB-1)/TPB, TPB>>>(tmp, kh16);
    rung<0,64,0,2>(kv16, wvTh, wvTl, nullptr, tmp, nullptr, BL, Ee, Ee, Ee, 1, 0);
    k_vtrans<<<dim3(Ll/32, 2*Bb*NHh), wb>>>(tmp, vT16);

    k_init<<<(Dd*BQ*Ww + TPB-1)/TPB, TPB>>>(z_init, p_init, z, pah, Na, No, cat16);
    k_sync2<<<(BQ*(SAa+SOo) + TPB-1)/TPB, TPB>>>(z, Na, No, sa16, so16,
        idx_la, idx_ra, idx_lo, idx_ro, dec_a, dec_o, 1);

    // ---- T iterations ----
    for (int t = 0; t < Tt; t++) {
        // q = sa @ Wc, rope+scale fused -> qh16
        rung<0,128,3,2>(sa16, Wch, Wcl, nullptr, nullptr, qh16, BQ, Ee, SAa, 0, 0, 0);
        // tensor-core flash attention -> cat cols [0, Ee)
        k_fattn2<<<dim3(Qq/64, NHh, Bb), 128>>>(qh16, kh16, vT16, cat16, Ee+Ww);
        // fused synapse layer 1 (wo folded): h1 = gelu(cat @ wsF^T + bs1)
        rung<2,64,1,2>(cat16, wsFh, wsFl, bs1, nullptr, h116, BQ, SHh, Ee+Ww, 0, 0, SHh);
        rung<1,64,0,2>(h116, ws2Th, ws2Tl, bs2, pah + (long)t*BQ*Ww, nullptr,
                       BQ, Ww, SHh, Ww, 1, 0);
        // neuron-level models + fused sync
        k_nlm<<<dim3(Ww/32, BQ/128), 256>>>(pah, nw1, nb1, nw2, nb2, z, cat16, t + 1);
        k_sync2<<<(BQ*(SAa+SOo) + TPB-1)/TPB, TPB>>>(z, Na, No, sa16, so16,
            idx_la, idx_ra, idx_lo, idx_ro, dec_a, dec_o, t + 2);
        // logits: 1-pass fp16
        rung<1,128,0,1>(so16, owTh, owTl, out_b, out + (long)t*BQ*Vv, nullptr,
                        BQ, Vv, SOo, Vv, 1, 0);
    }
}

// round 17
// speedup vs baseline: 5.5837x; 1.1482x over previous
#include <cuda_runtime.h>
#include <cuda_bf16.h>
#include <cuda_fp16.h>
#include <math.h>
#include <stdint.h>
#include <string.h>

// ---- problem constants ----
#define Bb   2
#define Ll   512
#define Qq   512
#define Ee   1024
#define Ww   1024
#define Dd   8
#define Hn   32
#define NHh  16
#define HDd  64
#define SAa  512
#define SOo  1024
#define Vv   8192
#define Tt   6
#define SHh  2048
#define BQ   (Bb*Qq)
#define BL   (Bb*Ll)

typedef __half hf;

// ---- fp32 scratch ----
__device__ float g_z   [BQ*Ww];
__device__ float g_pah [Dd*BQ*Ww];          // ring planes of [BQ][Ww] (written lazily)
__device__ float g_Na  [BQ*SAa];
__device__ float g_No  [BQ*SOo];

// ---- fp16 activations ----
__device__ hf g_emb16[BL*Ee];
__device__ hf g_kv16 [BL*Ee];
__device__ hf g_qh16 [Bb*NHh*Qq*HDd];
__device__ hf g_kh16 [Bb*NHh*Ll*HDd];
__device__ hf g_vT16 [Bb*NHh*HDd*Ll];       // V transposed per head: [d][k]
__device__ hf g_cat16[BQ*(Ee+Ww)];          // [ctx | z]
__device__ hf g_h116 [BQ*SHh];
__device__ hf g_sa16 [BQ*SAa];
__device__ hf g_so16 [BQ*SOo];

// ---- fp16 hi/scaled-lo weights ----
__device__ hf g_wkvTh[Ee*Ee],       g_wkvTl[Ee*Ee];
__device__ hf g_wkTh [Ee*Ee],       g_wkTl [Ee*Ee];
__device__ hf g_wvTh [Ee*Ee],       g_wvTl [Ee*Ee];
__device__ hf g_ws1Th[SHh*(Ee+Ww)], g_ws1Tl[SHh*(Ee+Ww)];   // ws1^T source
__device__ hf g_wsFh [SHh*(Ee+Ww)], g_wsFl [SHh*(Ee+Ww)];   // fused [Wos^T | ws1_botT]
__device__ hf g_ws2Th[Ww*SHh],      g_ws2Tl[Ww*SHh];
__device__ hf g_owTh [Vv*SOo],      g_owTl [Vv*SOo];
__device__ hf g_wqTh [Ee*Ee],       g_wqTl [Ee*Ee];
__device__ hf g_wqs16h[SAa*Ee],     g_wqs16l[SAa*Ee];
__device__ hf g_wo16h[Ee*Ee],       g_wo16l[Ee*Ee];
__device__ hf g_Wch  [Ee*SAa],      g_Wcl  [Ee*SAa];

__device__ __forceinline__ float gelu_f(float x) {
    float y = 1.5957691216057308f*(x + 0.044715f*x*x*x);
    return x / (1.0f + __expf(-y));
}

__device__ __forceinline__ uint32_t h2u(__half2 h){
    uint32_t u;
    memcpy(&u, &h, 4);
    return u;
}

// ====================== mma primitives ======================
__device__ __forceinline__ void cpa16(uint32_t s, const void* g){
    asm volatile("cp.async.cg.shared.global [%0], [%1], 16;" :: "r"(s), "l"(g));
}
__device__ __forceinline__ void cpcommit(){ asm volatile("cp.async.commit_group;" ::: "memory"); }
template<int N> __device__ __forceinline__ void cpwait(){ asm volatile("cp.async.wait_group %0;" :: "n"(N) : "memory"); }
__device__ __forceinline__ void ldmx4(uint32_t* r, uint32_t a){
    asm volatile("ldmatrix.sync.aligned.m8n8.x4.shared.b16 {%0,%1,%2,%3}, [%4];"
        : "=r"(r[0]),"=r"(r[1]),"=r"(r[2]),"=r"(r[3]) : "r"(a));
}
__device__ __forceinline__ void mma_fp16(float* c, const uint32_t* a, uint32_t b0, uint32_t b1){
    asm volatile("mma.sync.aligned.m16n8k16.row.col.f32.f16.f16.f32 "
        "{%0,%1,%2,%3}, {%4,%5,%6,%7}, {%8,%9}, {%0,%1,%2,%3};"
        : "+f"(c[0]),"+f"(c[1]),"+f"(c[2]),"+f"(c[3])
        : "r"(a[0]),"r"(a[1]),"r"(a[2]),"r"(a[3]), "r"(b0),"r"(b1));
}

// ============ fp16 GEMM, NS-stage cp.async ============
// C(M,N) = epi(A @ B^T [+bias]); A fp16 [M,K]; Bh=fp16(B), Bl=fp16((B-Bh)*1024), [N,K].
// NPASS=2: result = acc1 + acc2/1024. NPASS=1: hi-only.
// EPI: 0 none, 1 +bias, 2 gelu(+bias)
// OMODE: 0 fp32 C, 1 fp16 single out (ldh),
//        3 rope(*oscale) -> Ch[(b*NH+h)*512 + s][64]  (needs BM=128)
//        5 transpose -> Ch[(b*NH+h)*64 + d][512] (V^T layout)
template<int EPI, int BM, int OMODE, int NPASS, int NS>
__global__ void __launch_bounds__(256, (BM==64)?2:1) hg(
    const hf* __restrict__ A,
    const hf* __restrict__ Bh, const hf* __restrict__ Bl,
    const float* __restrict__ bias,
    float* __restrict__ C, hf* __restrict__ Ch,
    int M, int N, int K, long ldcm, long ldcn, long ldh, float oscale)
{
    constexpr int WMW = BM/32;
    constexpr int WNW = 8/WMW;
    constexpr int WARP_N = 128/WNW;
    constexpr int NJ = WARP_N/8;
    constexpr int TILE_A = BM*80;
    constexpr int TILE_B = 128*80;
    constexpr int STAGE = TILE_A + NPASS*TILE_B;

    extern __shared__ __align__(16) char dyn[];
    const int tid  = threadIdx.x;
    const int wid  = tid >> 5, lane = tid & 31;
    const int bm = blockIdx.y*BM, bn = blockIdx.x*128;
    const int wm = wid % WMW, wn = wid / WMW;

    uint32_t sbase = (uint32_t)__cvta_generic_to_shared(dyn);

    const hf* gA  = A  + (long)bm*K;
    const hf* gBh = Bh + (long)bn*K;
    const hf* gBl = Bl + (long)bn*K;

    auto load_stage = [&](int st, int k0){
        uint32_t s0 = sbase + st*STAGE;
        #pragma unroll
        for (int c = 0; c < BM/64; ++c) {
            int ch = tid + c*256;
            int row = ch >> 2, seg = ch & 3;
            cpa16(s0 + row*80 + seg*16, gA + (long)row*K + k0 + seg*8);
        }
        #pragma unroll
        for (int c = 0; c < 2; ++c) {
            int ch = tid + c*256;
            int row = ch >> 2, seg = ch & 3;
            cpa16(s0 + TILE_A + row*80 + seg*16, gBh + (long)row*K + k0 + seg*8);
            if (NPASS == 2)
                cpa16(s0 + TILE_A + TILE_B + row*80 + seg*16, gBl + (long)row*K + k0 + seg*8);
        }
    };

    float acc1[2][NJ][4], acc2[2][NJ][4];
    #pragma unroll
    for (int i = 0; i < 2; i++)
        #pragma unroll
        for (int j = 0; j < NJ; j++)
            #pragma unroll
            for (int q = 0; q < 4; q++) { acc1[i][j][q] = 0.f; acc2[i][j][q] = 0.f; }

    const int NC = K >> 5;
    #pragma unroll
    for (int s = 0; s < NS-1; ++s)
        if (s < NC) { load_stage(s, s*32); cpcommit(); }

    const int l = lane & 7, sel = lane >> 3;
    const int rofs = l + ((sel & 1) << 3);
    const int cofs = (sel >> 1) << 3;

    for (int c = 0; c < NC; ++c) {
        if (c + NS-1 < NC) { load_stage((c+NS-1)%NS, (c+NS-1)*32); cpcommit(); cpwait<NS-2>(); }
        else cpwait<0>();
        __syncthreads();

        uint32_t s0  = sbase + (c%NS)*STAGE;
        uint32_t sA = s0, sBh = s0 + TILE_A, sBl = sBh + TILE_B;

        #pragma unroll
        for (int k16 = 0; k16 < 2; ++k16) {
            int colo = k16*16 + cofs;
            uint32_t a[2][4];
            #pragma unroll
            for (int mi = 0; mi < 2; ++mi) {
                uint32_t off = (uint32_t)((wm*32 + mi*16 + rofs)*40 + colo)*2;
                ldmx4(a[mi], sA + off);
            }
            uint32_t bhf[NJ/2][4], blf[NJ/2][4];
            #pragma unroll
            for (int ni = 0; ni < NJ/2; ++ni) {
                uint32_t off = (uint32_t)((wn*WARP_N + ni*16 + rofs)*40 + colo)*2;
                ldmx4(bhf[ni], sBh + off);
                if (NPASS == 2) ldmx4(blf[ni], sBl + off);
            }
            #pragma unroll
            for (int mi = 0; mi < 2; ++mi)
                #pragma unroll
                for (int nj = 0; nj < NJ; ++nj) {
                    int g = nj >> 1, h8 = nj & 1;
                    mma_fp16(acc1[mi][nj], a[mi], bhf[g][h8], bhf[g][h8+2]);
                    if (NPASS == 2) mma_fp16(acc2[mi][nj], a[mi], blf[g][h8], blf[g][h8+2]);
                }
        }
        __syncthreads();
    }

    const float SC = 1.f/1024.f;
    const int tr = lane >> 2, tc = (lane & 3)*2;

    if (OMODE == 3) {
        // rope epilogue *oscale -> Ch[(b*NH+h)*512 + s][64]; BM=128 (WARP_N=64)
        #pragma unroll
        for (int mi = 0; mi < 2; ++mi)
            #pragma unroll
            for (int njl = 0; njl < NJ/2; ++njl) {
                float vlo[4], vhi[4];
                #pragma unroll
                for (int q = 0; q < 4; ++q) {
                    vlo[q] = acc1[mi][njl][q]      + acc2[mi][njl][q]*SC;
                    vhi[q] = acc1[mi][njl+NJ/2][q] + acc2[mi][njl+NJ/2][q]*SC;
                }
                #pragma unroll
                for (int r = 0; r < 2; ++r)
                    #pragma unroll
                    for (int cc = 0; cc < 2; ++cc) {
                        int m = bm + wm*32 + mi*16 + tr + r*8;
                        int s = m & 511, bb = m >> 9;
                        int hh = (bn + wn*WARP_N) >> 6;
                        int j = njl*8 + tc + cc;
                        float inv = expf(-(float)j * (9.210340371976184f/32.f));
                        float ang = (float)s * inv;
                        float sn, cs;
                        sincosf(ang, &sn, &cs);
                        float x1 = vlo[r*2+cc], x2 = vhi[r*2+cc];
                        long base = (((long)(bb*NHh + hh))*512 + s)*64;
                        Ch[base + j]      = __float2half((x1*cs - x2*sn)*oscale);
                        Ch[base + j + 32] = __float2half((x2*cs + x1*sn)*oscale);
                    }
            }
        return;
    }

    #pragma unroll
    for (int mi = 0; mi < 2; ++mi) {
        #pragma unroll
        for (int nj = 0; nj < NJ; ++nj) {
            int m0 = bm + wm*32 + mi*16 + tr;
            int n0 = bn + wn*WARP_N + nj*8 + tc;
            float v[4];
            #pragma unroll
            for (int q = 0; q < 4; ++q)
                v[q] = (NPASS == 2) ? (acc1[mi][nj][q] + acc2[mi][nj][q]*SC) : acc1[mi][nj][q];
            if (EPI >= 1) {
                float b0 = __ldg(bias + n0), b1 = __ldg(bias + n0 + 1);
                v[0] += b0; v[1] += b1; v[2] += b0; v[3] += b1;
            }
            if (EPI == 2) {
                v[0] = gelu_f(v[0]); v[1] = gelu_f(v[1]);
                v[2] = gelu_f(v[2]); v[3] = gelu_f(v[3]);
            }
            if (OMODE == 5) {
                // V^T scatter: Ch[((b*NH+h)*64 + d)*512 + s]
                int bbv = m0 >> 9, sv = m0 & 511;
                int hv = n0 >> 6, dv = n0 & 63;
                long bhd = ((long)(bbv*NHh + hv))*HDd;
                Ch[(bhd + dv)*Ll + sv]         = __float2half(v[0]);
                Ch[(bhd + dv + 1)*Ll + sv]     = __float2half(v[1]);
                Ch[(bhd + dv)*Ll + sv + 8]     = __float2half(v[2]);
                Ch[(bhd + dv + 1)*Ll + sv + 8] = __float2half(v[3]);
            } else if (OMODE == 1) {
                #pragma unroll
                for (int rr = 0; rr < 2; ++rr) {
                    long base = (long)(m0 + rr*8)*ldh + n0;
                    __half2 hh;
                    hh.x = __float2half(v[rr*2+0]);
                    hh.y = __float2half(v[rr*2+1]);
                    *reinterpret_cast<__half2*>(Ch + base) = hh;
                }
            } else if (ldcn == 1) {
                *(float2*)(C + (long)m0*ldcm + n0)     = make_float2(v[0], v[1]);
                *(float2*)(C + (long)(m0+8)*ldcm + n0) = make_float2(v[2], v[3]);
            } else {
                C[(long)m0*ldcm     + (long)n0*ldcn]     = v[0];
                C[(long)m0*ldcm     + (long)(n0+1)*ldcn] = v[1];
                C[(long)(m0+8)*ldcm + (long)n0*ldcn]     = v[2];
                C[(long)(m0+8)*ldcm + (long)(n0+1)*ldcn] = v[3];
            }
        }
    }
}

// ===== prep 3-pass GEMM: A hi/lo, B hi/lo -> fp16 hi/scaled-lo out (ldh) =====
__global__ void __launch_bounds__(256, 1) hg3(
    const hf* __restrict__ Ah, const hf* __restrict__ Al,
    const hf* __restrict__ Bh, const hf* __restrict__ Bl,
    hf* __restrict__ Ch, hf* __restrict__ Cl,
    int M, int N, int K, long lda, long ldh)
{
    constexpr int TILE = 128*80;
    constexpr int STAGE = 4*TILE;
    extern __shared__ __align__(16) char dyn[];
    const int tid  = threadIdx.x;
    const int wid  = tid >> 5, lane = tid & 31;
    const int bm = blockIdx.y*128, bn = blockIdx.x*128;
    const int wm = wid & 3, wn = wid >> 2;

    uint32_t sbase = (uint32_t)__cvta_generic_to_shared(dyn);
    const hf* gAh = Ah + (long)bm*lda;
    const hf* gAl = Al + (long)bm*lda;
    const hf* gBh = Bh + (long)bn*K;
    const hf* gBl = Bl + (long)bn*K;

    auto load_stage = [&](int st, int k0){
        uint32_t s0 = sbase + st*STAGE;
        #pragma unroll
        for (int c = 0; c < 2; ++c) {
            int ch = tid + c*256;
            int row = ch >> 2, seg = ch & 3;
            cpa16(s0 + row*80 + seg*16,          gAh + (long)row*lda + k0 + seg*8);
            cpa16(s0 + TILE   + row*80 + seg*16, gAl + (long)row*lda + k0 + seg*8);
            cpa16(s0 + 2*TILE + row*80 + seg*16, gBh + (long)row*K + k0 + seg*8);
            cpa16(s0 + 3*TILE + row*80 + seg*16, gBl + (long)row*K + k0 + seg*8);
        }
    };

    float acc1[2][8][4], acc2[2][8][4];
    #pragma unroll
    for (int i = 0; i < 2; i++)
        #pragma unroll
        for (int j = 0; j < 8; j++)
            #pragma unroll
            for (int q = 0; q < 4; q++) { acc1[i][j][q] = 0.f; acc2[i][j][q] = 0.f; }

    const int NC = K >> 5;
    load_stage(0, 0); cpcommit();

    const int l = lane & 7, sel = lane >> 3;
    const int rofs = l + ((sel & 1) << 3);
    const int cofs = (sel >> 1) << 3;

    for (int c = 0; c < NC; ++c) {
        if (c + 1 < NC) { load_stage((c+1)&1, (c+1)*32); cpcommit(); cpwait<1>(); }
        else cpwait<0>();
        __syncthreads();
        uint32_t s0 = sbase + (c&1)*STAGE;
        uint32_t sAh = s0, sAl = s0 + TILE, sBh = s0 + 2*TILE, sBl = s0 + 3*TILE;
        #pragma unroll
        for (int k16 = 0; k16 < 2; ++k16) {
            int colo = k16*16 + cofs;
            uint32_t ah[2][4], al[2][4];
            #pragma unroll
            for (int mi = 0; mi < 2; ++mi) {
                uint32_t off = (uint32_t)((wm*32 + mi*16 + rofs)*40 + colo)*2;
                ldmx4(ah[mi], sAh + off);
                ldmx4(al[mi], sAl + off);
            }
            uint32_t bh[4][4], bl[4][4];
            #pragma unroll
            for (int ni = 0; ni < 4; ++ni) {
                uint32_t off = (uint32_t)((wn*64 + ni*16 + rofs)*40 + colo)*2;
                ldmx4(bh[ni], sBh + off);
                ldmx4(bl[ni], sBl + off);
            }
            #pragma unroll
            for (int mi = 0; mi < 2; ++mi)
                #pragma unroll
                for (int nj = 0; nj < 8; ++nj) {
                    int g = nj >> 1, h8 = nj & 1;
                    mma_fp16(acc1[mi][nj], ah[mi], bh[g][h8], bh[g][h8+2]);
                    mma_fp16(acc2[mi][nj], ah[mi], bl[g][h8], bl[g][h8+2]);
                    mma_fp16(acc2[mi][nj], al[mi], bh[g][h8], bh[g][h8+2]);
                }
        }
        __syncthreads();
    }

    const float SC = 1.f/1024.f;
    const int tr = lane >> 2, tc = (lane & 3)*2;
    #pragma unroll
    for (int mi = 0; mi < 2; ++mi)
        #pragma unroll
        for (int nj = 0; nj < 8; ++nj) {
            int m0 = bm + wm*32 + mi*16 + tr;
            int n0 = bn + wn*64 + nj*8 + tc;
            float v[4];
            #pragma unroll
            for (int q = 0; q < 4; ++q) v[q] = acc1[mi][nj][q] + acc2[mi][nj][q]*SC;
            #pragma unroll
            for (int rr = 0; rr < 2; ++rr) {
                long base = (long)(m0 + rr*8)*ldh + n0;
                hf h0 = __float2half(v[rr*2+0]);
                hf h1 = __float2half(v[rr*2+1]);
                hf l0 = __float2half((v[rr*2+0] - __half2float(h0))*1024.f);
                hf l1 = __float2half((v[rr*2+1] - __half2float(h1))*1024.f);
                __half2 hh; hh.x = h0; hh.y = h1;
                __half2 llv; llv.x = l0; llv.y = l1;
                *reinterpret_cast<__half2*>(Ch + base) = hh;
                *reinterpret_cast<__half2*>(Cl + base) = llv;
            }
        }
}

// ============== tensor-core flash attention ==============
#define AT_STR 72

__global__ void __launch_bounds__(128) k_fattn2(
    const hf* __restrict__ qh, const hf* __restrict__ kh,
    const hf* __restrict__ vt, hf* __restrict__ dst, int ldd)
{
    __shared__ hf sQ[64*AT_STR];
    __shared__ hf sK[2][64*AT_STR];
    __shared__ hf sV[2][64*AT_STR];

    const int tid = threadIdx.x;
    const int wid = tid >> 5, lane = tid & 31;
    const int q0 = blockIdx.x*64, h = blockIdx.y, b = blockIdx.z;
    const long bh = b*NHh + h;

    const hf* gQ = qh + (bh*Qq + q0)*HDd;
    const hf* gK = kh + bh*Ll*HDd;
    const hf* gV = vt + bh*HDd*Ll;

    uint32_t sQa = (uint32_t)__cvta_generic_to_shared(sQ);
    uint32_t sKa = (uint32_t)__cvta_generic_to_shared(sK);
    uint32_t sVa = (uint32_t)__cvta_generic_to_shared(sV);

    for (int i = tid; i < 512; i += 128) {
        int row = i >> 3, seg = i & 7;
        cpa16(sQa + (row*AT_STR + seg*8)*2, gQ + row*HDd + seg*8);
    }
    auto loadKV = [&](int st, int c){
        uint32_t k0 = sKa + st*64*AT_STR*2;
        uint32_t v0 = sVa + st*64*AT_STR*2;
        for (int i = tid; i < 512; i += 128) {
            int row = i >> 3, seg = i & 7;
            cpa16(k0 + (row*AT_STR + seg*8)*2, gK + (long)(c*64 + row)*HDd + seg*8);
            cpa16(v0 + (row*AT_STR + seg*8)*2, gV + (long)row*Ll + c*64 + seg*8);
        }
    };

    const int NC = blockIdx.x + 1;
    loadKV(0, 0); cpcommit();
    if (NC > 1) { loadKV(1, 1); cpcommit(); }

    const int l = lane & 7, sel = lane >> 3;
    const int rofs = l + ((sel & 1) << 3);
    const int cofs = (sel >> 1) << 3;
    const int tr = lane >> 2, tc = (lane & 3)*2;

    float O[8][4];
    #pragma unroll
    for (int i = 0; i < 8; i++)
        #pragma unroll
        for (int q = 0; q < 4; q++) O[i][q] = 0.f;
    float mrun0 = -1e30f, mrun1 = -1e30f, sum0 = 0.f, sum1 = 0.f;
    uint32_t aq[4][4];

    const int rowg0 = q0 + wid*16 + tr, rowg1 = rowg0 + 8;

    for (int c = 0; c < NC; ++c) {
        if (c + 1 < NC) cpwait<1>(); else cpwait<0>();
        __syncthreads();
        if (c == 0) {
            #pragma unroll
            for (int g = 0; g < 4; ++g)
                ldmx4(aq[g], sQa + ((wid*16 + rofs)*AT_STR + g*16 + cofs)*2);
        }
        uint32_t kb = sKa + (c&1)*64*AT_STR*2;
        uint32_t vb = sVa + (c&1)*64*AT_STR*2;

        float S[8][4];
        #pragma unroll
        for (int i = 0; i < 8; i++)
            #pragma unroll
            for (int q = 0; q < 4; q++) S[i][q] = 0.f;

        #pragma unroll
        for (int g = 0; g < 4; ++g) {
            #pragma unroll
            for (int nt = 0; nt < 4; ++nt) {
                uint32_t bk[4];
                ldmx4(bk, kb + ((nt*16 + rofs)*AT_STR + g*16 + cofs)*2);
                mma_fp16(S[2*nt],   aq[g], bk[0], bk[2]);
                mma_fp16(S[2*nt+1], aq[g], bk[1], bk[3]);
            }
        }

        if (c == NC - 1) {
            #pragma unroll
            for (int nj = 0; nj < 8; ++nj) {
                int colg = c*64 + nj*8 + tc;
                if (colg     > rowg0) S[nj][0] = -1e30f;
                if (colg + 1 > rowg0) S[nj][1] = -1e30f;
                if (colg     > rowg1) S[nj][2] = -1e30f;
                if (colg + 1 > rowg1) S[nj][3] = -1e30f;
            }
        }

        float mx0 = -1e30f, mx1 = -1e30f;
        #pragma unroll
        for (int nj = 0; nj < 8; ++nj) {
            mx0 = fmaxf(mx0, fmaxf(S[nj][0], S[nj][1]));
            mx1 = fmaxf(mx1, fmaxf(S[nj][2], S[nj][3]));
        }
        mx0 = fmaxf(mx0, __shfl_xor_sync(0xffffffffu, mx0, 1));
        mx0 = fmaxf(mx0, __shfl_xor_sync(0xffffffffu, mx0, 2));
        mx1 = fmaxf(mx1, __shfl_xor_sync(0xffffffffu, mx1, 1));
        mx1 = fmaxf(mx1, __shfl_xor_sync(0xffffffffu, mx1, 2));
        float mn0 = fmaxf(mrun0, mx0), mn1 = fmaxf(mrun1, mx1);
        float sc0 = __expf(mrun0 - mn0), sc1 = __expf(mrun1 - mn1);
        mrun0 = mn0; mrun1 = mn1;

        float ps0 = 0.f, ps1 = 0.f;
        uint32_t Ph[8][2];
        #pragma unroll
        for (int nj = 0; nj < 8; ++nj) {
            float p0 = __expf(S[nj][0] - mn0), p1 = __expf(S[nj][1] - mn0);
            float p2 = __expf(S[nj][2] - mn1), p3 = __expf(S[nj][3] - mn1);
            ps0 += p0 + p1; ps1 += p2 + p3;
            Ph[nj][0] = h2u(__floats2half2_rn(p0, p1));
            Ph[nj][1] = h2u(__floats2half2_rn(p2, p3));
        }
        sum0 = sum0*sc0 + ps0;
        sum1 = sum1*sc1 + ps1;
        #pragma unroll
        for (int nt = 0; nt < 8; ++nt) {
            O[nt][0] *= sc0; O[nt][1] *= sc0;
            O[nt][2] *= sc1; O[nt][3] *= sc1;
        }

        #pragma unroll
        for (int g = 0; g < 4; ++g) {
            uint32_t aP[4] = { Ph[2*g][0], Ph[2*g][1], Ph[2*g+1][0], Ph[2*g+1][1] };
            #pragma unroll
            for (int nt = 0; nt < 4; ++nt) {
                uint32_t bv[4];
                ldmx4(bv, vb + ((nt*16 + rofs)*AT_STR + g*16 + cofs)*2);
                mma_fp16(O[2*nt],   aP, bv[0], bv[2]);
                mma_fp16(O[2*nt+1], aP, bv[1], bv[3]);
            }
        }
        __syncthreads();
        if (c + 2 < NC) { loadKV(c & 1, c + 2); cpcommit(); }
    }

    sum0 += __shfl_xor_sync(0xffffffffu, sum0, 1);
    sum0 += __shfl_xor_sync(0xffffffffu, sum0, 2);
    sum1 += __shfl_xor_sync(0xffffffffu, sum1, 1);
    sum1 += __shfl_xor_sync(0xffffffffu, sum1, 2);
    const float i0 = 1.f/sum0, i1 = 1.f/sum1;

    long r0 = (long)(b*Qq + rowg0)*ldd + h*HDd;
    long r1 = r0 + 8*ldd;
    #pragma unroll
    for (int nt = 0; nt < 8; ++nt) {
        int col = nt*8 + tc;
        *reinterpret_cast<__half2*>(dst + r0 + col) = __floats2half2_rn(O[nt][0]*i0, O[nt][1]*i0);
        *reinterpret_cast<__half2*>(dst + r1 + col) = __floats2half2_rn(O[nt][2]*i1, O[nt][3]*i1);
    }
}

// ======================= small kernels =======================
__global__ void k_wsplit16(const float* __restrict__ w, hf* __restrict__ hi,
                           hf* __restrict__ lo, int K, int N) {
    __shared__ float t[32][33];
    int k0 = blockIdx.y*32, n0 = blockIdx.x*32;
    for (int r = threadIdx.y; r < 32; r += 8)
        t[r][threadIdx.x] = w[(long)(k0+r)*N + n0 + threadIdx.x];
    __syncthreads();
    for (int r = threadIdx.y; r < 32; r += 8) {
        float v = t[threadIdx.x][r];
        hf h = __float2half(v);
        long o = (long)(n0+r)*K + k0 + threadIdx.x;
        hi[o] = h;
        lo[o] = __float2half((v - __half2float(h))*1024.f);
    }
}

__global__ void k_split16(const float* __restrict__ in, hf* __restrict__ hi,
                          hf* __restrict__ lo, int n) {
    int i = blockIdx.x*blockDim.x + threadIdx.x;
    if (i >= n) return;
    float v = in[i];
    hf h = __float2half(v);
    hi[i] = h;
    lo[i] = __float2half((v - __half2float(h))*1024.f);
}

// copy ws1T cols [Ee, Ee+Ww) into wsF (both hi and lo)
__global__ void k_copycols(const hf* __restrict__ sh, const hf* __restrict__ sl,
                           hf* __restrict__ dh, hf* __restrict__ dl) {
    int i = blockIdx.x*blockDim.x + threadIdx.x;
    if (i >= SHh*Ww) return;
    int row = i / Ww, col = i % Ww;
    long idx = (long)row*(Ee+Ww) + Ee + col;
    dh[idx] = sh[idx];
    dl[idx] = sl[idx];
}

__global__ void k_gather(const int* __restrict__ x, const float* __restrict__ emb,
                         hf* __restrict__ o16) {
    int i = blockIdx.x*blockDim.x + threadIdx.x;
    if (i >= BL*Ee) return;
    int e = i % Ee, bl = i / Ee;
    o16[i] = __float2half(emb[(long)x[bl]*Ee + e]);
}

__global__ void k_init(const float* __restrict__ z0,
                       float* __restrict__ z,
                       float* __restrict__ Na, float* __restrict__ No,
                       hf* __restrict__ cat16) {
    int i = blockIdx.x*blockDim.x + threadIdx.x;
    if (i < BQ*Ww) {
        int w = i % Ww, bq = i / Ww;
        float v = z0[w];
        z[i] = v;
        cat16[(long)bq*(Ee+Ww) + Ee + w] = __float2half(v);
    }
    if (i < BQ*SAa) Na[i] = 0.f;
    if (i < BQ*SOo) No[i] = 0.f;
}

// NLM with virtual pah: unwritten physical planes read p_init
__global__ void __launch_bounds__(256) k_nlm(
    const float* __restrict__ pah, const float* __restrict__ p0,
    const float* __restrict__ w1,
    const float* __restrict__ b1, const float* __restrict__ w2,
    const float* __restrict__ b2, float* __restrict__ z,
    hf* __restrict__ cat16, int t)
{
    __shared__ float w1s[32*257];
    __shared__ float b1s[32*33];
    __shared__ float w2s[32*33];
    __shared__ float b2s[32];
    const int tid = threadIdx.x;
    const int w0 = blockIdx.x*32, bq0 = blockIdx.y*128;
    const int start = t + 1;

    for (int j = tid; j < 32*256; j += 256) w1s[(j>>8)*257 + (j&255)] = w1[(long)w0*256 + j];
    for (int j = tid; j < 32*32;  j += 256) {
        b1s[(j>>5)*33 + (j&31)] = b1[(long)w0*32 + j];
        w2s[(j>>5)*33 + (j&31)] = w2[(long)w0*32 + j];
    }
    if (tid < 32) b2s[tid] = b2[w0 + tid];
    __syncthreads();

    const int wl = tid & 31, bql = tid >> 5;
    const int w = w0 + wl;
    for (int bq = bq0 + bql; bq < bq0 + 128; bq += 8) {
        float pv[Dd];
        #pragma unroll
        for (int d = 0; d < Dd; d++) {
            int phys = (start + d) & 7;
            pv[d] = (phys <= t) ? pah[(long)phys*BQ*Ww + (long)bq*Ww + w]
                                : p0[w*Dd + phys];
        }
        float zacc = b2s[wl];
        #pragma unroll
        for (int hh = 0; hh < Hn; hh++) {
            float a = b1s[wl*33 + hh];
            #pragma unroll
            for (int d = 0; d < Dd; d++) a += pv[d]*w1s[wl*257 + d*32 + hh];
            zacc += gelu_f(a)*w2s[wl*33 + hh];
        }
        z[(long)bq*Ww + w] = zacc;
        cat16[(long)bq*(Ee+Ww) + Ee + w] = __float2half(zacc);
    }
}

__global__ void k_sync2(const float* __restrict__ z,
                        float* __restrict__ Na, float* __restrict__ No,
                        hf* __restrict__ sa, hf* __restrict__ so,
                        const int* __restrict__ ila, const int* __restrict__ ira,
                        const int* __restrict__ ilo, const int* __restrict__ iro,
                        const float* __restrict__ dec_a, const float* __restrict__ dec_o,
                        int Tn) {
    int i = blockIdx.x*blockDim.x + threadIdx.x;
    if (i >= BQ*(SAa+SOo)) return;
    int s = i % (SAa+SOo), bq = i / (SAa+SOo);
    const float* zr = z + (long)bq*Ww;
    float d, p;
    float* Nbuf; hf* syn; long idx;
    if (s < SAa) {
        d = dec_a[s];
        p = zr[ila[s]]*zr[ira[s]];
        Nbuf = Na; syn = sa; idx = (long)bq*SAa + s;
    } else {
        int so_s = s - SAa;
        d = dec_o[so_s];
        p = zr[ilo[so_s]]*zr[iro[so_s]];
        Nbuf = No; syn = so; idx = (long)bq*SOo + so_s;
    }
    float ed = __expf(-d);
    float Nn = Nbuf[idx]*ed + p;
    Nbuf[idx] = Nn;
    float den = 0.f, wgt = 1.f;
    for (int k = 0; k < Tn; k++) { den += wgt; wgt *= ed; }
    syn[idx] = __float2half(Nn * rsqrtf(den));
}

// ======================= host =======================
static void* symv(const void* s) { void* p = nullptr; cudaGetSymbolAddress(&p, s); return p; }

template<int EPI, int BM, int OMODE, int NPASS, int NS>
static void rung(const hf* A, const hf* Bh, const hf* Bl,
                 const float* bias, float* C, hf* Ch,
                 int M, int N, int K, long ldcm, long ldcn, long ldh, float oscale = 1.f) {
    constexpr int SM = NS*(BM*80 + NPASS*128*80);
    cudaFuncSetAttribute(hg<EPI,BM,OMODE,NPASS,NS>, cudaFuncAttributeMaxDynamicSharedMemorySize, SM);
    dim3 g(N/128, M/BM);
    hg<EPI,BM,OMODE,NPASS,NS><<<g, 256, SM>>>(A, Bh, Bl, bias, C, Ch, M, N, K, ldcm, ldcn, ldh, oscale);
}

extern "C" void kernel_launch(void* const* d_in, const int* in_sizes, int n_in,
                              void* d_out, int out_size) {
    (void)in_sizes; (void)n_in; (void)out_size;
    const int*   x      = (const int*)  d_in[0];
    const float* emb    = (const float*)d_in[2];
    const float* w_kv   = (const float*)d_in[3];
    const float* w_qs   = (const float*)d_in[4];
    const float* wq     = (const float*)d_in[5];
    const float* wk     = (const float*)d_in[6];
    const float* wv     = (const float*)d_in[7];
    const float* wo     = (const float*)d_in[8];
    const float* ws1    = (const float*)d_in[9];
    const float* bs1    = (const float*)d_in[10];
    const float* ws2    = (const float*)d_in[11];
    const float* bs2    = (const float*)d_in[12];
    const float* nw1    = (const float*)d_in[13];
    const float* nb1    = (const float*)d_in[14];
    const float* nw2    = (const float*)d_in[15];
    const float* nb2    = (const float*)d_in[16];
    const float* out_w  = (const float*)d_in[17];
    const float* out_b  = (const float*)d_in[18];
    const float* z_init = (const float*)d_in[19];
    const float* p_init = (const float*)d_in[20];
    const float* dec_a  = (const float*)d_in[21];
    const float* dec_o  = (const float*)d_in[22];
    const int*   idx_la = (const int*)  d_in[23];
    const int*   idx_ra = (const int*)  d_in[24];
    const int*   idx_lo = (const int*)  d_in[25];
    const int*   idx_ro = (const int*)  d_in[26];
    float* out = (float*)d_out;

    float *z = (float*)symv(g_z), *pah = (float*)symv(g_pah);
    float *Na = (float*)symv(g_Na), *No = (float*)symv(g_No);

    hf *emb16=(hf*)symv(g_emb16), *kv16=(hf*)symv(g_kv16);
    hf *qh16=(hf*)symv(g_qh16), *kh16=(hf*)symv(g_kh16), *vT16=(hf*)symv(g_vT16);
    hf *cat16=(hf*)symv(g_cat16), *h116=(hf*)symv(g_h116);
    hf *sa16=(hf*)symv(g_sa16), *so16=(hf*)symv(g_so16);

    hf *wkvTh=(hf*)symv(g_wkvTh), *wkvTl=(hf*)symv(g_wkvTl);
    hf *wkTh =(hf*)symv(g_wkTh),  *wkTl =(hf*)symv(g_wkTl);
    hf *wvTh =(hf*)symv(g_wvTh),  *wvTl =(hf*)symv(g_wvTl);
    hf *ws1Th=(hf*)symv(g_ws1Th), *ws1Tl=(hf*)symv(g_ws1Tl);
    hf *wsFh =(hf*)symv(g_wsFh),  *wsFl =(hf*)symv(g_wsFl);
    hf *ws2Th=(hf*)symv(g_ws2Th), *ws2Tl=(hf*)symv(g_ws2Tl);
    hf *owTh =(hf*)symv(g_owTh),  *owTl =(hf*)symv(g_owTl);
    hf *wqTh =(hf*)symv(g_wqTh),  *wqTl =(hf*)symv(g_wqTl);
    hf *wqs16h=(hf*)symv(g_wqs16h), *wqs16l=(hf*)symv(g_wqs16l);
    hf *wo16h=(hf*)symv(g_wo16h), *wo16l=(hf*)symv(g_wo16l);
    hf *Wch  =(hf*)symv(g_Wch),   *Wcl  =(hf*)symv(g_Wcl);

    const int TPB = 256;
    dim3 wb(32, 8);

    // ---- weight prep ----
    k_wsplit16<<<dim3(Ee/32,  Ee/32),  wb>>>(w_kv,  wkvTh, wkvTl, Ee,  Ee);
    k_wsplit16<<<dim3(Ee/32,  Ee/32),  wb>>>(wk,    wkTh,  wkTl,  Ee,  Ee);
    k_wsplit16<<<dim3(Ee/32,  Ee/32),  wb>>>(wv,    wvTh,  wvTl,  Ee,  Ee);
    k_wsplit16<<<dim3(SHh/32, (Ee+Ww)/32), wb>>>(ws1, ws1Th, ws1Tl, Ee+Ww, SHh);
    k_wsplit16<<<dim3(Ww/32,  SHh/32), wb>>>(ws2,   ws2Th, ws2Tl, SHh, Ww);
    k_wsplit16<<<dim3(Vv/32,  SOo/32), wb>>>(out_w, owTh,  owTl,  SOo, Vv);
    k_wsplit16<<<dim3(Ee/32,  Ee/32),  wb>>>(wq,    wqTh,  wqTl,  Ee,  Ee);
    k_split16<<<(SAa*Ee + TPB-1)/TPB, TPB>>>(w_qs, wqs16h, wqs16l, SAa*Ee);
    k_split16<<<(Ee*Ee + TPB-1)/TPB, TPB>>>(wo, wo16h, wo16l, Ee*Ee);
    k_copycols<<<(SHh*Ww + TPB-1)/TPB, TPB>>>(ws1Th, ws1Tl, wsFh, wsFl);
    {
        constexpr int SM3 = 2*4*128*80;
        cudaFuncSetAttribute(hg3, cudaFuncAttributeMaxDynamicSharedMemorySize, SM3);
        hg3<<<dim3(SAa/128, Ee/128), 256, SM3>>>(wqTh, wqTl, wqs16h, wqs16l,
                                                 Wch, Wcl, Ee, SAa, Ee, Ee, SAa);
        hg3<<<dim3(Ee/128, SHh/128), 256, SM3>>>(ws1Th, ws1Tl, wo16h, wo16l,
                                                 wsFh, wsFl, SHh, Ee, Ee, Ee+Ww, Ee+Ww);
    }

    // ---- prologue: kv, kh16 (rope fused), vT16 (transpose fused) ----
    k_gather<<<(BL*Ee + TPB-1)/TPB, TPB>>>(x, emb, emb16);
    rung<0,64,1,2,4>(emb16, wkvTh, wkvTl, nullptr, nullptr, kv16, BL, Ee, Ee, 0, 0, Ee);
    rung<0,128,3,2,4>(kv16, wkTh, wkTl, nullptr, nullptr, kh16, BL, Ee, Ee, 0, 0, 0, 1.0f);
    rung<0,64,5,2,4>(kv16, wvTh, wvTl, nullptr, nullptr, vT16, BL, Ee, Ee, 0, 0, 0);

    k_init<<<(BQ*SOo + TPB-1)/TPB, TPB>>>(z_init, z, Na, No, cat16);
    k_sync2<<<(BQ*(SAa+SOo) + TPB-1)/TPB, TPB>>>(z, Na, No, sa16, so16,
        idx_la, idx_ra, idx_lo, idx_ro, dec_a, dec_o, 1);

    // ---- T iterations ----
    for (int t = 0; t < Tt; t++) {
        // q = sa @ Wc (1-pass), rope+scale fused -> qh16
        rung<0,128,3,1,4>(sa16, Wch, Wcl, nullptr, nullptr, qh16, BQ, Ee, SAa, 0, 0, 0, 0.125f);
        // tensor-core flash attention -> cat cols [0, Ee)
        k_fattn2<<<dim3(Qq/64, NHh, Bb), 128>>>(qh16, kh16, vT16, cat16, Ee+Ww);
        // fused synapse layer 1 (wo folded): h1 = gelu(cat @ wsF^T + bs1)
        rung<2,64,1,2,4>(cat16, wsFh, wsFl, bs1, nullptr, h116, BQ, SHh, Ee+Ww, 0, 0, SHh);
        rung<1,64,0,2,4>(h116, ws2Th, ws2Tl, bs2, pah + (long)t*BQ*Ww, nullptr,
                         BQ, Ww, SHh, Ww, 1, 0);
        // neuron-level models (virtual pah) + fused sync
        k_nlm<<<dim3(Ww/32, BQ/128), 256>>>(pah, p_init, nw1, nb1, nw2, nb2, z, cat16, t);
        k_sync2<<<(BQ*(SAa+SOo) + TPB-1)/TPB, TPB>>>(z, Na, No, sa16, so16,
            idx_la, idx_ra, idx_lo, idx_ro, dec_a, dec_o, t + 2);
        // logits: 1-pass fp16
        rung<1,128,0,1,4>(so16, owTh, owTl, out_b, out + (long)t*BQ*Vv, nullptr,
                          BQ, Vv, SOo, Vv, 1, 0);
    }
}